// round 3
// baseline (speedup 1.0000x reference)
#include <cuda_runtime.h>
#include <math.h>

#define NB 2
#define L 196
#define D 768
#define LD (L*D)
#define MW 7
#define NLTOT (NB*L)   // 392
#define STRH 448       // padded half-spectrum stride (385 -> 448)
#define NF 832         // fwd table cols (770 -> 13*64)
#define KI 784         // idft K (770 -> 49*16)

// ---------------- scratch ---------------------------------------------------
__device__ float    g_V  [NB*LD];
__device__ float    g_Tf [D*NF];        // fwd twiddles  [d][2k]=cos, [2k+1]=-sin
__device__ float    g_Ti [KI*D];        // idft twiddles [k][d]=cos ; [385+k][d]=-sin ; pad 0
__device__ float    g_YA [NLTOT*KI];    // idft A matrix [row][Yr'(385) | Yi'(385) | 0 pad]
__device__ float    g_Xr [NLTOT*STRH];
__device__ float    g_Xi [NLTOT*STRH];
__device__ float    g_sty[NLTOT*STRH];
__device__ float    g_B1 [NLTOT*STRH];
__device__ float    g_B2 [NLTOT*STRH];
__device__ float    g_B3 [NLTOT*STRH];
__device__ unsigned g_M  [NB*L*MW];

// ---------------- f32x2 helpers ---------------------------------------------
typedef unsigned long long u64;
__device__ __forceinline__ void fma2(u64 &acc, u64 a, u64 b) {
    asm("fma.rn.f32x2 %0, %1, %2, %0;" : "+l"(acc) : "l"(a), "l"(b));
}
__device__ __forceinline__ u64 pack2(float x, float y) {
    u64 r; asm("mov.b64 %0, {%1, %2};" : "=l"(r) : "f"(x), "f"(y)); return r;
}
__device__ __forceinline__ float2 unpack2(u64 v) {
    float2 f; asm("mov.b64 {%0, %1}, %2;" : "=f"(f.x), "=f"(f.y) : "l"(v)); return f;
}

__device__ __forceinline__ float blockSum256(float v, float* red) {
    #pragma unroll
    for (int o = 16; o; o >>= 1) v += __shfl_xor_sync(0xffffffffu, v, o);
    if ((threadIdx.x & 31) == 0) red[threadIdx.x >> 5] = v;
    __syncthreads();
    if (threadIdx.x < 32) {
        float x = (threadIdx.x < 8) ? red[threadIdx.x] : 0.f;
        #pragma unroll
        for (int o = 4; o; o >>= 1) x += __shfl_xor_sync(0xffffffffu, x, o);
        if (threadIdx.x == 0) red[0] = x;
    }
    __syncthreads();
    float r = red[0];
    __syncthreads();
    return r;
}

// ---------------- K0: twiddle tables ----------------------------------------
__global__ void k_twiddle() {
    __shared__ float2 tw[D];
    int tid = threadIdx.x;
    for (int i = tid; i < D; i += 256) {
        float s, c; sincospif((float)i * (1.f / 384.f), &s, &c);
        tw[i] = make_float2(c, s);
    }
    __syncthreads();
    int r0 = blockIdx.x * 8;
    #pragma unroll
    for (int rr = 0; rr < 8; rr++) {
        int r = r0 + rr;
        if (r >= D + KI) break;
        if (r < D) {                   // Tf row d
            int d = r;
            for (int k = tid; k < NF / 2; k += 256) {
                int idx = (d * k) % D;
                float2 t = tw[idx];
                *reinterpret_cast<float2*>(&g_Tf[(size_t)d * NF + 2 * k]) =
                    make_float2(t.x, -t.y);
            }
        } else {                       // Ti row q
            int q = r - D;
            for (int d = tid; d < D; d += 256) {
                float v;
                if (q < 385)      v =  tw[(q * d) % D].x;
                else if (q < 770) v = -tw[((q - 385) * d) % D].y;
                else              v = 0.f;
                g_Ti[(size_t)q * D + d] = v;
            }
        }
    }
}

// ---------------- K_misc: zero g_M, zero YA pad, copy cls rows --------------
__global__ void k_misc(const float* __restrict__ x, float* __restrict__ out) {
    int t = blockIdx.x * 256 + threadIdx.x;
    if (t < NB * L * MW) g_M[t] = 0u;
    if (t < NLTOT * (KI - 770)) {                 // YA pad cols [770, KI)
        int row = t / (KI - 770), c = 770 + t % (KI - 770);
        g_YA[(size_t)row * KI + c] = 0.f;
    }
    if (t < NB * D) {
        int a = t / D, d = t % D;
        out[(size_t)a * 197 * D + d] = x[(size_t)a * 197 * D + d];
    }
}

// ---------------- K1: patchify + center + L2-normalize ----------------------
__global__ void k_patch(const float* __restrict__ imgs) {
    __shared__ float red[8];
    __shared__ float buf[D];
    int blk = blockIdx.x, a = blk / L, l = blk % L;
    int hh = l / 14, ww = l % 14;
    int tid = threadIdx.x;
    int p = tid >> 4, q = tid & 15;
    const float* base = imgs + ((size_t)a * 3 * 224 + (size_t)(hh * 16 + p)) * 224
                             + (ww * 16 + q);
    float v[3];
    #pragma unroll
    for (int c = 0; c < 3; c++) v[c] = base[(size_t)c * 224 * 224];
    float mean = blockSum256(v[0] + v[1] + v[2], red) * (1.f / 768.f);
    float u[3]; float ss = 0.f;
    #pragma unroll
    for (int c = 0; c < 3; c++) { u[c] = v[c] - mean; ss += u[c] * u[c]; }
    float tot = blockSum256(ss, red);
    float inv = 1.f / sqrtf(tot);
    #pragma unroll
    for (int c = 0; c < 3; c++) buf[tid * 3 + c] = u[c] * inv;
    __syncthreads();
    if (tid < 192) {
        reinterpret_cast<float4*>(g_V + (size_t)blk * D)[tid] =
            reinterpret_cast<float4*>(buf)[tid];
    }
}

// ---------------- K2: Sim = V V^T upper-tri, 32x32 reg-tiled FFMA2 ----------
__global__ void k_sim() {
    __shared__ float As[16][32], Bs[16][32];
    int a = blockIdx.z;
    int t = blockIdx.x, bi = 0;
    while (t >= 7 - bi) { t -= 7 - bi; bi++; }
    int bj = bi + t;
    int i0 = bi * 32, j0 = bj * 32;
    int tid = threadIdx.x;
    int tx = tid & 15, ty = tid >> 4;
    int m = tid >> 3, kk2 = (tid & 7) << 1;
    const float* Vb = g_V + (size_t)a * LD;
    u64 acc[2] = {0ULL, 0ULL};
    for (int k0 = 0; k0 < D; k0 += 16) {
        float2 av = make_float2(0.f, 0.f), bv = av;
        if (i0 + m < L) av = *reinterpret_cast<const float2*>(Vb + (size_t)(i0 + m) * D + k0 + kk2);
        if (j0 + m < L) bv = *reinterpret_cast<const float2*>(Vb + (size_t)(j0 + m) * D + k0 + kk2);
        As[kk2][m] = av.x; As[kk2 + 1][m] = av.y;
        Bs[kk2][m] = bv.x; Bs[kk2 + 1][m] = bv.y;
        __syncthreads();
        #pragma unroll
        for (int kk = 0; kk < 16; kk++) {
            float2 a2 = *reinterpret_cast<float2*>(&As[kk][ty << 1]);
            u64 b = *reinterpret_cast<u64*>(&Bs[kk][tx << 1]);
            fma2(acc[0], pack2(a2.x, a2.x), b);
            fma2(acc[1], pack2(a2.y, a2.y), b);
        }
        __syncthreads();
    }
    #pragma unroll
    for (int r = 0; r < 2; r++) {
        int i = i0 + (ty << 1) + r;
        if (i >= L) continue;
        float2 c = unpack2(acc[r]);
        int j = j0 + (tx << 1);
        if (j < L && j >= i && c.x > 0.3f)
            atomicOr(&g_M[(a * L + i) * MW + (j >> 5)], 1u << (j & 31));
        j++;
        if (j < L && j >= i && c.y > 0.3f)
            atomicOr(&g_M[(a * L + i) * MW + (j >> 5)], 1u << (j & 31));
    }
}

// ---------------- K3: sequential propagation (skip-store fast path) ---------
__global__ void k_prop() {
    __shared__ unsigned m[NB * L * MW];
    __shared__ int sS, sRem, ired[8];
    int tid = threadIdx.x;
    int local = 0;
    for (int t = tid; t < NB * L * MW; t += 256) {
        unsigned w = g_M[t]; m[t] = w; local += __popc(w);
    }
    #pragma unroll
    for (int o = 16; o; o >>= 1) local += __shfl_xor_sync(0xffffffffu, local, o);
    if ((tid & 31) == 0) ired[tid >> 5] = local;
    __syncthreads();
    if (tid == 0) {
        int s = 0;
        #pragma unroll
        for (int w = 0; w < 8; w++) s += ired[w];
        sS = s;
    }
    __syncthreads();
    int s0 = sS;
    for (int i = 0; i < L - 1; i++) {
        if (sS == NB * L) break;
        if (tid == 0) sRem = 0;
        __syncthreads();
        int rem = 0;
        int nj = L - 1 - i;
        int cnt = NB * nj * MW;
        for (int t = tid; t < cnt; t += 256) {
            int w = t % MW; int r = t / MW;
            int j = i + 1 + (r % nj); int a = r / nj;
            unsigned rw  = m[(a * L + i) * MW + w];
            unsigned old = m[(a * L + j) * MW + w];
            unsigned drop = old & rw;
            if (drop) { m[(a * L + j) * MW + w] = old & ~rw; rem += __popc(drop); }
        }
        #pragma unroll
        for (int o = 16; o; o >>= 1) rem += __shfl_xor_sync(0xffffffffu, rem, o);
        if ((tid & 31) == 0 && rem) atomicAdd(&sRem, rem);
        __syncthreads();
        if (tid == 0) sS -= sRem;
        __syncthreads();
    }
    if (sS != s0) {                    // only write back if something changed
        for (int t = tid; t < NB * L * MW; t += 256) g_M[t] = m[t];
    }
}

// ---------------- K4: forward DFT as GEMM  C[392,770] = x @ Tf --------------
__global__ void k_fwd(const float* __restrict__ x) {
    __shared__ float As[16][64];
    __shared__ float Bs[16][64];
    int tid = threadIdx.x;
    int tx = tid & 15, ty = tid >> 4;
    int n0 = blockIdx.x * 64, m0 = blockIdx.y * 64;
    u64 acc[4][2];
    #pragma unroll
    for (int i = 0; i < 4; i++) { acc[i][0] = 0ULL; acc[i][1] = 0ULL; }

    int lm = tid >> 2, lk = (tid & 3) << 2;     // A loader
    int bk = tid >> 4, bn4 = (tid & 15) << 2;   // B loader
    int arow = m0 + lm;
    const float* Abase = nullptr;
    bool avalid = arow < NLTOT;
    if (avalid) {
        int a = arow / L, i = arow % L;
        Abase = x + ((size_t)(a * 197 + 1 + i)) * D;
    }
    for (int k0 = 0; k0 < D; k0 += 16) {
        float4 av = make_float4(0.f, 0.f, 0.f, 0.f);
        if (avalid) av = *reinterpret_cast<const float4*>(Abase + k0 + lk);
        As[lk + 0][lm] = av.x; As[lk + 1][lm] = av.y;
        As[lk + 2][lm] = av.z; As[lk + 3][lm] = av.w;
        *reinterpret_cast<float4*>(&Bs[bk][bn4]) =
            *reinterpret_cast<const float4*>(&g_Tf[(size_t)(k0 + bk) * NF + n0 + bn4]);
        __syncthreads();
        #pragma unroll
        for (int kk = 0; kk < 16; kk++) {
            float4 a4 = *reinterpret_cast<float4*>(&As[kk][ty << 2]);
            u64 b01 = *reinterpret_cast<u64*>(&Bs[kk][tx << 2]);
            u64 b23 = *reinterpret_cast<u64*>(&Bs[kk][(tx << 2) + 2]);
            const float* ap = reinterpret_cast<const float*>(&a4);
            #pragma unroll
            for (int im = 0; im < 4; im++) {
                u64 aa = pack2(ap[im], ap[im]);
                fma2(acc[im][0], aa, b01);
                fma2(acc[im][1], aa, b23);
            }
        }
        __syncthreads();
    }
    int n = n0 + (tx << 2);
    int k = n >> 1;
    #pragma unroll
    for (int im = 0; im < 4; im++) {
        int row = m0 + (ty << 2) + im;
        if (row >= NLTOT) continue;
        size_t b = (size_t)row * STRH;
        float2 c01 = unpack2(acc[im][0]);
        float2 c23 = unpack2(acc[im][1]);
        if (k <= 384) {
            g_Xr[b + k] = c01.x; g_Xi[b + k] = c01.y;
            g_sty[b + k] = sqrtf(c01.x * c01.x + c01.y * c01.y);
        }
        if (k + 1 <= 384) {
            g_Xr[b + k + 1] = c23.x; g_Xi[b + k + 1] = c23.y;
            g_sty[b + k + 1] = sqrtf(c23.x * c23.x + c23.y * c23.y);
        }
    }
}

// ---------------- K5: cluster stats (half spectrum) -------------------------
__global__ void k_stats() {
    __shared__ unsigned mw[MW];
    int blk = blockIdx.x, a = blk / L, i = blk % L;
    int tid = threadIdx.x;
    if (tid < MW) mw[tid] = g_M[(a * L + i) * MW + tid];
    __syncthreads();
    int num = 0;
    #pragma unroll
    for (int w = 0; w < MW; w++) num += __popc(mw[w]);
    float numc = (num > 0) ? (float)num : 1e-7f;
    bool has2 = tid < 129;           // col2 = tid+256 < 385
    int c1 = tid, c2 = tid + 256;

    float S1a = 0.f, S1b = 0.f;
    for (int w = 0; w < MW; w++) {
        unsigned bits = mw[w];
        while (bits) {
            int j = (w << 5) + __ffs((int)bits) - 1; bits &= bits - 1;
            const float* sp = g_sty + (size_t)(a * L + j) * STRH;
            S1a += sp[c1];
            if (has2) S1b += sp[c2];
        }
    }
    float avga = S1a / numc, avgb = S1b / numc;
    float S2a = 0.f, S2b = 0.f;
    for (int w = 0; w < MW; w++) {
        unsigned bits = mw[w];
        while (bits) {
            int j = (w << 5) + __ffs((int)bits) - 1; bits &= bits - 1;
            const float* sp = g_sty + (size_t)(a * L + j) * STRH;
            float xa = sp[c1] - avga; S2a += xa * xa;
            if (has2) { float xb = sp[c2] - avgb; S2b += xb * xb; }
        }
    }
    size_t off = (size_t)blk * STRH;
    float sta = sqrtf(S2a / numc);
    float ma = (S1a > 0.f) ? 1.f : 0.f;
    g_B1[off + c1] = ma * sta; g_B2[off + c1] = ma * avga; g_B3[off + c1] = ma;
    if (has2) {
        float stb = sqrtf(S2b / numc);
        float mb = (S1b > 0.f) ? 1.f : 0.f;
        g_B1[off + c2] = mb * stb; g_B2[off + c2] = mb * avgb; g_B3[off + c2] = mb;
    } else if (tid < 192) {          // zero pad cols [385,448)
        g_B1[off + c2] = 0.f; g_B2[off + c2] = 0.f; g_B3[off + c2] = 0.f;
    }
}

// ---------------- K6: fused triple GEMM + Y build ----------------------------
// s = (A1@B1 + A2@B2) / max(A2@B3,1e-7); then Y = X*s/|X| weighted -> g_YA
__global__ void k_gemm3(const float* __restrict__ ls, const float* __restrict__ noise) {
    __shared__ float A1s[16][64], A2s[16][64];
    __shared__ float B1s[16][64], B2s[16][64], B3s[16][64];
    int tid = threadIdx.x;
    int tx = tid & 15, ty = tid >> 4;
    int n0 = blockIdx.x * 64, m0 = blockIdx.y * 64;
    int a = blockIdx.z;
    u64 ac1[4][2], ac2[4][2], ac3[4][2];
    #pragma unroll
    for (int i = 0; i < 4; i++) {
        ac1[i][0] = ac1[i][1] = 0ULL;
        ac2[i][0] = ac2[i][1] = 0ULL;
        ac3[i][0] = ac3[i][1] = 0ULL;
    }
    int lm = tid >> 2, lk = (tid & 3) << 2;
    int bk = tid >> 4, bn4 = (tid & 15) << 2;
    const float* lsb = ls    + (size_t)a * L * L;
    const float* nsb = noise + (size_t)a * L * L;

    for (int k0 = 0; k0 < 208; k0 += 16) {
        int ia = m0 + lm, ja = k0 + lk;
        float4 lv = make_float4(0.f, 0.f, 0.f, 0.f), nv = lv;
        if (ia < L && ja < L) {
            lv = *reinterpret_cast<const float4*>(lsb + (size_t)ia * L + ja);
            nv = *reinterpret_cast<const float4*>(nsb + (size_t)ia * L + ja);
        }
        A1s[lk + 0][lm] = lv.x * nv.x; A2s[lk + 0][lm] = lv.x;
        A1s[lk + 1][lm] = lv.y * nv.y; A2s[lk + 1][lm] = lv.y;
        A1s[lk + 2][lm] = lv.z * nv.z; A2s[lk + 2][lm] = lv.z;
        A1s[lk + 3][lm] = lv.w * nv.w; A2s[lk + 3][lm] = lv.w;
        int jb = k0 + bk;
        float4 b1 = make_float4(0.f, 0.f, 0.f, 0.f), b2 = b1, b3 = b1;
        if (jb < L) {
            size_t o = (size_t)(a * L + jb) * STRH + n0 + bn4;
            b1 = *reinterpret_cast<const float4*>(&g_B1[o]);
            b2 = *reinterpret_cast<const float4*>(&g_B2[o]);
            b3 = *reinterpret_cast<const float4*>(&g_B3[o]);
        }
        *reinterpret_cast<float4*>(&B1s[bk][bn4]) = b1;
        *reinterpret_cast<float4*>(&B2s[bk][bn4]) = b2;
        *reinterpret_cast<float4*>(&B3s[bk][bn4]) = b3;
        __syncthreads();
        #pragma unroll
        for (int kk = 0; kk < 16; kk++) {
            float4 a1 = *reinterpret_cast<float4*>(&A1s[kk][ty << 2]);
            float4 a2 = *reinterpret_cast<float4*>(&A2s[kk][ty << 2]);
            u64 b1a = *reinterpret_cast<u64*>(&B1s[kk][tx << 2]);
            u64 b1b = *reinterpret_cast<u64*>(&B1s[kk][(tx << 2) + 2]);
            u64 b2a = *reinterpret_cast<u64*>(&B2s[kk][tx << 2]);
            u64 b2b = *reinterpret_cast<u64*>(&B2s[kk][(tx << 2) + 2]);
            u64 b3a = *reinterpret_cast<u64*>(&B3s[kk][tx << 2]);
            u64 b3b = *reinterpret_cast<u64*>(&B3s[kk][(tx << 2) + 2]);
            const float* a1p = reinterpret_cast<const float*>(&a1);
            const float* a2p = reinterpret_cast<const float*>(&a2);
            #pragma unroll
            for (int im = 0; im < 4; im++) {
                u64 aa1 = pack2(a1p[im], a1p[im]);
                u64 aa2 = pack2(a2p[im], a2p[im]);
                fma2(ac1[im][0], aa1, b1a); fma2(ac1[im][1], aa1, b1b);
                fma2(ac2[im][0], aa2, b2a); fma2(ac2[im][1], aa2, b2b);
                fma2(ac3[im][0], aa2, b3a); fma2(ac3[im][1], aa2, b3b);
            }
        }
        __syncthreads();
    }
    #pragma unroll
    for (int im = 0; im < 4; im++) {
        int i = m0 + (ty << 2) + im;
        if (i >= L) continue;
        int row = a * L + i;
        size_t ob = (size_t)row * STRH;
        size_t by = (size_t)row * KI;
        int n = n0 + (tx << 2);
        float2 p1a = unpack2(ac1[im][0]), p1b = unpack2(ac1[im][1]);
        float2 p2a = unpack2(ac2[im][0]), p2b = unpack2(ac2[im][1]);
        float2 p3a = unpack2(ac3[im][0]), p3b = unpack2(ac3[im][1]);
        float num[4] = {p1a.x + p2a.x, p1a.y + p2a.y, p1b.x + p2b.x, p1b.y + p2b.y};
        float den[4] = {p3a.x, p3a.y, p3b.x, p3b.y};
        #pragma unroll
        for (int c = 0; c < 4; c++) {
            int col = n + c;
            if (col >= 385) continue;
            float s = num[c] / fmaxf(den[c], 1e-7f);
            float xr = g_Xr[ob + col], xi = g_Xi[ob + col];
            float m2 = xr * xr + xi * xi;
            float yr, yi;
            if (m2 > 0.f) { float r = s / sqrtf(m2); yr = xr * r; yi = xi * r; }
            else          { yr = s; yi = 0.f; }
            float w = (col == 0 || col == 384) ? 1.f : 2.f;
            g_YA[by + col] = w * yr;
            g_YA[by + 385 + col] = w * yi;
        }
    }
}

// ---------------- K8: inverse DFT as GEMM  out = YA @ Ti / 768 --------------
__global__ void k_idft(float* __restrict__ out) {
    __shared__ float As[16][64];
    __shared__ float Bs[16][64];
    int tid = threadIdx.x;
    int tx = tid & 15, ty = tid >> 4;
    int n0 = blockIdx.x * 64, m0 = blockIdx.y * 64;
    u64 acc[4][2];
    #pragma unroll
    for (int i = 0; i < 4; i++) { acc[i][0] = 0ULL; acc[i][1] = 0ULL; }
    int lm = tid >> 2, lk = (tid & 3) << 2;
    int bk = tid >> 4, bn4 = (tid & 15) << 2;
    int arow = m0 + lm;
    bool avalid = arow < NLTOT;
    const float* Abase = g_YA + (size_t)arow * KI;
    for (int k0 = 0; k0 < KI; k0 += 16) {
        float4 av = make_float4(0.f, 0.f, 0.f, 0.f);
        if (avalid) av = *reinterpret_cast<const float4*>(Abase + k0 + lk);
        As[lk + 0][lm] = av.x; As[lk + 1][lm] = av.y;
        As[lk + 2][lm] = av.z; As[lk + 3][lm] = av.w;
        *reinterpret_cast<float4*>(&Bs[bk][bn4]) =
            *reinterpret_cast<const float4*>(&g_Ti[(size_t)(k0 + bk) * D + n0 + bn4]);
        __syncthreads();
        #pragma unroll
        for (int kk = 0; kk < 16; kk++) {
            float4 a4 = *reinterpret_cast<float4*>(&As[kk][ty << 2]);
            u64 b01 = *reinterpret_cast<u64*>(&Bs[kk][tx << 2]);
            u64 b23 = *reinterpret_cast<u64*>(&Bs[kk][(tx << 2) + 2]);
            const float* ap = reinterpret_cast<const float*>(&a4);
            #pragma unroll
            for (int im = 0; im < 4; im++) {
                u64 aa = pack2(ap[im], ap[im]);
                fma2(acc[im][0], aa, b01);
                fma2(acc[im][1], aa, b23);
            }
        }
        __syncthreads();
    }
    #pragma unroll
    for (int im = 0; im < 4; im++) {
        int row = m0 + (ty << 2) + im;
        if (row >= NLTOT) continue;
        int a = row / L, i = row % L;
        float2 c01 = unpack2(acc[im][0]);
        float2 c23 = unpack2(acc[im][1]);
        float4 o = make_float4(c01.x * (1.f / 768.f), c01.y * (1.f / 768.f),
                               c23.x * (1.f / 768.f), c23.y * (1.f / 768.f));
        *reinterpret_cast<float4*>(
            &out[((size_t)(a * 197 + 1 + i)) * D + n0 + (tx << 2)]) = o;
    }
}

// ---------------- launch ------------------------------------------------------
extern "C" void kernel_launch(void* const* d_in, const int* in_sizes, int n_in,
                              void* d_out, int out_size) {
    const float* x     = (const float*)d_in[0];
    const float* imgs  = (const float*)d_in[1];
    const float* ls    = (const float*)d_in[2];
    const float* noise = (const float*)d_in[3];
    float* out = (float*)d_out;

    k_twiddle<<<(D + KI + 7) / 8, 256>>>();
    k_misc<<<(NLTOT * (KI - 770) + 255) / 256, 256>>>(x, out);
    k_patch<<<NLTOT, 256>>>(imgs);
    k_sim<<<dim3(28, 1, NB), 256>>>();
    k_prop<<<1, 256>>>();
    k_fwd<<<dim3(13, 7), 256>>>(x);
    k_stats<<<NLTOT, 256>>>();
    k_gemm3<<<dim3(7, 4, NB), 256>>>(ls, noise);
    k_idft<<<dim3(12, 7), 256>>>(out);
}

// round 4
// speedup vs baseline: 1.2958x; 1.2958x over previous
#include <cuda_runtime.h>
#include <math.h>

#define NB 2
#define L 196
#define D 768
#define LD (L*D)
#define MW 7
#define NLTOT (NB*L)   // 392
#define STRH 448       // padded half-spectrum stride (385 -> 448)
#define NF 832         // fwd table cols (770 -> 13*64)
#define KI 784         // idft K (770 -> 49*16)

// ---------------- scratch ---------------------------------------------------
__device__ float    g_V  [NB*LD];
__device__ float    g_Tf [D*NF];
__device__ float    g_Ti [KI*D];
__device__ float    g_YA [NLTOT*KI];
__device__ float    g_Xr [NLTOT*STRH];
__device__ float    g_Xi [NLTOT*STRH];
__device__ float    g_sty[NLTOT*STRH];
__device__ float    g_B1 [NLTOT*STRH];
__device__ float    g_B2 [NLTOT*STRH];
__device__ float    g_B3 [NLTOT*STRH];
__device__ unsigned g_M  [NB*L*MW];

// ---------------- f32x2 helpers ---------------------------------------------
typedef unsigned long long u64;
__device__ __forceinline__ void fma2(u64 &acc, u64 a, u64 b) {
    asm("fma.rn.f32x2 %0, %1, %2, %0;" : "+l"(acc) : "l"(a), "l"(b));
}
__device__ __forceinline__ u64 pack2(float x, float y) {
    u64 r; asm("mov.b64 %0, {%1, %2};" : "=l"(r) : "f"(x), "f"(y)); return r;
}
__device__ __forceinline__ float2 unpack2(u64 v) {
    float2 f; asm("mov.b64 {%0, %1}, %2;" : "=f"(f.x), "=f"(f.y) : "l"(v)); return f;
}

__device__ __forceinline__ float blockSum256(float v, float* red) {
    #pragma unroll
    for (int o = 16; o; o >>= 1) v += __shfl_xor_sync(0xffffffffu, v, o);
    if ((threadIdx.x & 31) == 0) red[threadIdx.x >> 5] = v;
    __syncthreads();
    if (threadIdx.x < 32) {
        float x = (threadIdx.x < 8) ? red[threadIdx.x] : 0.f;
        #pragma unroll
        for (int o = 4; o; o >>= 1) x += __shfl_xor_sync(0xffffffffu, x, o);
        if (threadIdx.x == 0) red[0] = x;
    }
    __syncthreads();
    float r = red[0];
    __syncthreads();
    return r;
}

// ============ Kernel A: misc | twiddle | patch (grid-partitioned) ============
#define A_MISC 22
#define A_TW   194
#define A_GRID (A_MISC + A_TW + NLTOT)   // 608

__global__ void k_A(const float* __restrict__ imgs, const float* __restrict__ x,
                    float* __restrict__ out) {
    int b = blockIdx.x, tid = threadIdx.x;
    if (b < A_MISC) {
        int t = b * 256 + tid;
        if (t < NB * L * MW) g_M[t] = 0u;
        if (t < NLTOT * (KI - 770)) {
            int row = t / (KI - 770), c = 770 + t % (KI - 770);
            g_YA[(size_t)row * KI + c] = 0.f;
        }
        if (t < NB * D) {
            int a = t / D, d = t % D;
            out[(size_t)a * 197 * D + d] = x[(size_t)a * 197 * D + d];
        }
        return;
    }
    if (b < A_MISC + A_TW) {
        __shared__ float2 tw[D];
        for (int i = tid; i < D; i += 256) {
            float s, c; sincospif((float)i * (1.f / 384.f), &s, &c);
            tw[i] = make_float2(c, s);
        }
        __syncthreads();
        int r0 = (b - A_MISC) * 8;
        #pragma unroll
        for (int rr = 0; rr < 8; rr++) {
            int r = r0 + rr;
            if (r >= D + KI) break;
            if (r < D) {
                int d = r;
                for (int k = tid; k < NF / 2; k += 256) {
                    int idx = (d * k) % D;
                    float2 t2 = tw[idx];
                    *reinterpret_cast<float2*>(&g_Tf[(size_t)d * NF + 2 * k]) =
                        make_float2(t2.x, -t2.y);
                }
            } else {
                int q = r - D;
                for (int d = tid; d < D; d += 256) {
                    float v;
                    if (q < 385)      v =  tw[(q * d) % D].x;
                    else if (q < 770) v = -tw[((q - 385) * d) % D].y;
                    else              v = 0.f;
                    g_Ti[(size_t)q * D + d] = v;
                }
            }
        }
        return;
    }
    { // patch
        __shared__ float red[8];
        __shared__ float buf[D];
        int blk = b - A_MISC - A_TW, a = blk / L, l = blk % L;
        int hh = l / 14, ww = l % 14;
        int p = tid >> 4, q = tid & 15;
        const float* base = imgs + ((size_t)a * 3 * 224 + (size_t)(hh * 16 + p)) * 224
                                 + (ww * 16 + q);
        float v[3];
        #pragma unroll
        for (int c = 0; c < 3; c++) v[c] = base[(size_t)c * 224 * 224];
        float mean = blockSum256(v[0] + v[1] + v[2], red) * (1.f / 768.f);
        float u[3]; float ss = 0.f;
        #pragma unroll
        for (int c = 0; c < 3; c++) { u[c] = v[c] - mean; ss += u[c] * u[c]; }
        float tot = blockSum256(ss, red);
        float inv = 1.f / sqrtf(tot);
        #pragma unroll
        for (int c = 0; c < 3; c++) buf[tid * 3 + c] = u[c] * inv;
        __syncthreads();
        if (tid < 192)
            reinterpret_cast<float4*>(g_V + (size_t)blk * D)[tid] =
                reinterpret_cast<float4*>(buf)[tid];
    }
}

// ============ Kernel B: sim (56 blocks) | fwd (91 blocks) = 147 = 1 wave =====
__global__ void k_B(const float* __restrict__ x) {
    __shared__ __align__(16) float S[2304];   // sim needs 2176, fwd 2048
    int b = blockIdx.x, tid = threadIdx.x;
    if (b < 56) {
        // -------- sim: 32x32 upper-tri tile, 32-deep ktile, prefetch --------
        int a = b / 28;
        int t = b % 28, bi = 0;
        while (t >= 7 - bi) { t -= 7 - bi; bi++; }
        int bj = bi + t;
        int i0 = bi * 32, j0 = bj * 32;
        float (*As)[34] = (float(*)[34])S;
        float (*Bs)[34] = (float(*)[34])(S + 1088);
        int tx = tid & 15, ty = tid >> 4;
        int m = tid >> 3, k4 = (tid & 7) << 2;
        const float* Vb = g_V + (size_t)a * LD;
        const float* Arow = (i0 + m < L) ? Vb + (size_t)(i0 + m) * D : nullptr;
        const float* Brow = (j0 + m < L) ? Vb + (size_t)(j0 + m) * D : nullptr;
        float4 z4 = make_float4(0.f, 0.f, 0.f, 0.f);
        float4 avP = Arow ? *reinterpret_cast<const float4*>(Arow + k4) : z4;
        float4 bvP = Brow ? *reinterpret_cast<const float4*>(Brow + k4) : z4;
        u64 acc[2] = {0ULL, 0ULL};
        for (int k0 = 0; k0 < D; k0 += 32) {
            As[k4 + 0][m] = avP.x; As[k4 + 1][m] = avP.y;
            As[k4 + 2][m] = avP.z; As[k4 + 3][m] = avP.w;
            Bs[k4 + 0][m] = bvP.x; Bs[k4 + 1][m] = bvP.y;
            Bs[k4 + 2][m] = bvP.z; Bs[k4 + 3][m] = bvP.w;
            __syncthreads();
            int kn = k0 + 32;
            if (kn < D) {
                avP = Arow ? *reinterpret_cast<const float4*>(Arow + kn + k4) : z4;
                bvP = Brow ? *reinterpret_cast<const float4*>(Brow + kn + k4) : z4;
            }
            #pragma unroll
            for (int kk = 0; kk < 32; kk++) {
                float2 a2 = *reinterpret_cast<float2*>(&As[kk][ty << 1]);
                u64 bb = *reinterpret_cast<u64*>(&Bs[kk][tx << 1]);
                fma2(acc[0], pack2(a2.x, a2.x), bb);
                fma2(acc[1], pack2(a2.y, a2.y), bb);
            }
            __syncthreads();
        }
        #pragma unroll
        for (int r = 0; r < 2; r++) {
            int i = i0 + (ty << 1) + r;
            if (i >= L) continue;
            float2 c = unpack2(acc[r]);
            int j = j0 + (tx << 1);
            if (j < L && j >= i && c.x > 0.3f)
                atomicOr(&g_M[(a * L + i) * MW + (j >> 5)], 1u << (j & 31));
            j++;
            if (j < L && j >= i && c.y > 0.3f)
                atomicOr(&g_M[(a * L + i) * MW + (j >> 5)], 1u << (j & 31));
        }
    } else {
        // -------- fwd: C[392,770] = x @ Tf, 64x64 tile, prefetch ------------
        int bb = b - 56;
        int n0 = (bb % 13) * 64, m0 = (bb / 13) * 64;
        float (*As)[64] = (float(*)[64])S;
        float (*Bs)[64] = (float(*)[64])(S + 1024);
        int tx = tid & 15, ty = tid >> 4;
        u64 acc[4][2];
        #pragma unroll
        for (int i = 0; i < 4; i++) { acc[i][0] = 0ULL; acc[i][1] = 0ULL; }
        int lm = tid >> 2, lk = (tid & 3) << 2;
        int bk = tid >> 4, bn4 = (tid & 15) << 2;
        int arow = m0 + lm;
        bool avalid = arow < NLTOT;
        const float* Abase = nullptr;
        if (avalid) {
            int a = arow / L, i = arow % L;
            Abase = x + ((size_t)(a * 197 + 1 + i)) * D;
        }
        float4 z4 = make_float4(0.f, 0.f, 0.f, 0.f);
        float4 avP = avalid ? *reinterpret_cast<const float4*>(Abase + lk) : z4;
        float4 bvP = *reinterpret_cast<const float4*>(&g_Tf[(size_t)bk * NF + n0 + bn4]);
        for (int k0 = 0; k0 < D; k0 += 16) {
            As[lk + 0][lm] = avP.x; As[lk + 1][lm] = avP.y;
            As[lk + 2][lm] = avP.z; As[lk + 3][lm] = avP.w;
            *reinterpret_cast<float4*>(&Bs[bk][bn4]) = bvP;
            __syncthreads();
            int kn = k0 + 16;
            if (kn < D) {
                avP = avalid ? *reinterpret_cast<const float4*>(Abase + kn + lk) : z4;
                bvP = *reinterpret_cast<const float4*>(&g_Tf[(size_t)(kn + bk) * NF + n0 + bn4]);
            }
            #pragma unroll
            for (int kk = 0; kk < 16; kk++) {
                float4 a4 = *reinterpret_cast<float4*>(&As[kk][ty << 2]);
                u64 b01 = *reinterpret_cast<u64*>(&Bs[kk][tx << 2]);
                u64 b23 = *reinterpret_cast<u64*>(&Bs[kk][(tx << 2) + 2]);
                const float* ap = reinterpret_cast<const float*>(&a4);
                #pragma unroll
                for (int im = 0; im < 4; im++) {
                    u64 aa = pack2(ap[im], ap[im]);
                    fma2(acc[im][0], aa, b01);
                    fma2(acc[im][1], aa, b23);
                }
            }
            __syncthreads();
        }
        int n = n0 + (tx << 2);
        int k = n >> 1;
        #pragma unroll
        for (int im = 0; im < 4; im++) {
            int row = m0 + (ty << 2) + im;
            if (row >= NLTOT) continue;
            size_t bo = (size_t)row * STRH;
            float2 c01 = unpack2(acc[im][0]);
            float2 c23 = unpack2(acc[im][1]);
            if (k <= 384) {
                g_Xr[bo + k] = c01.x; g_Xi[bo + k] = c01.y;
                g_sty[bo + k] = sqrtf(c01.x * c01.x + c01.y * c01.y);
            }
            if (k + 1 <= 384) {
                g_Xr[bo + k + 1] = c23.x; g_Xi[bo + k + 1] = c23.y;
                g_sty[bo + k + 1] = sqrtf(c23.x * c23.x + c23.y * c23.y);
            }
        }
    }
}

// ============ Kernel C: per-row local prop replay + stats ====================
__global__ void k_C() {
    __shared__ unsigned m[NB * L * MW];
    __shared__ int sS, sRem, ired[8];
    int blk = blockIdx.x, a = blk / L, i = blk % L;
    int tid = threadIdx.x;
    int local = 0;
    for (int t = tid; t < NB * L * MW; t += 256) {
        unsigned w = g_M[t]; m[t] = w; local += __popc(w);
    }
    #pragma unroll
    for (int o = 16; o; o >>= 1) local += __shfl_xor_sync(0xffffffffu, local, o);
    if ((tid & 31) == 0) ired[tid >> 5] = local;
    __syncthreads();
    if (tid == 0) {
        int s = 0;
        #pragma unroll
        for (int w = 0; w < 8; w++) s += ired[w];
        sS = s;
    }
    __syncthreads();
    // replay prop only up to iteration i-1 (row i final after that)
    for (int ii = 0; ii < i; ii++) {
        if (sS == NB * L) break;
        if (tid == 0) sRem = 0;
        __syncthreads();
        int rem = 0;
        int nj = L - 1 - ii;
        int cnt = NB * nj * MW;
        for (int t = tid; t < cnt; t += 256) {
            int w = t % MW; int r = t / MW;
            int j = ii + 1 + (r % nj); int aa = r / nj;
            unsigned rw  = m[(aa * L + ii) * MW + w];
            unsigned old = m[(aa * L + j) * MW + w];
            unsigned drop = old & rw;
            if (drop) { m[(aa * L + j) * MW + w] = old & ~rw; rem += __popc(drop); }
        }
        #pragma unroll
        for (int o = 16; o; o >>= 1) rem += __shfl_xor_sync(0xffffffffu, rem, o);
        if ((tid & 31) == 0 && rem) atomicAdd(&sRem, rem);
        __syncthreads();
        if (tid == 0) sS -= sRem;
        __syncthreads();
    }
    // stats for row (a, i) from final local row bits
    const unsigned* mw = &m[(a * L + i) * MW];
    int num = 0;
    #pragma unroll
    for (int w = 0; w < MW; w++) num += __popc(mw[w]);
    float numc = (num > 0) ? (float)num : 1e-7f;
    bool has2 = tid < 129;
    int c1 = tid, c2 = tid + 256;
    float S1a = 0.f, S1b = 0.f;
    for (int w = 0; w < MW; w++) {
        unsigned bits = mw[w];
        while (bits) {
            int j = (w << 5) + __ffs((int)bits) - 1; bits &= bits - 1;
            const float* sp = g_sty + (size_t)(a * L + j) * STRH;
            S1a += sp[c1];
            if (has2) S1b += sp[c2];
        }
    }
    float avga = S1a / numc, avgb = S1b / numc;
    float S2a = 0.f, S2b = 0.f;
    for (int w = 0; w < MW; w++) {
        unsigned bits = mw[w];
        while (bits) {
            int j = (w << 5) + __ffs((int)bits) - 1; bits &= bits - 1;
            const float* sp = g_sty + (size_t)(a * L + j) * STRH;
            float xa = sp[c1] - avga; S2a += xa * xa;
            if (has2) { float xb = sp[c2] - avgb; S2b += xb * xb; }
        }
    }
    size_t off = (size_t)blk * STRH;
    float sta = sqrtf(S2a / numc);
    float ma = (S1a > 0.f) ? 1.f : 0.f;
    g_B1[off + c1] = ma * sta; g_B2[off + c1] = ma * avga; g_B3[off + c1] = ma;
    if (has2) {
        float stb = sqrtf(S2b / numc);
        float mb = (S1b > 0.f) ? 1.f : 0.f;
        g_B1[off + c2] = mb * stb; g_B2[off + c2] = mb * avgb; g_B3[off + c2] = mb;
    } else if (tid < 192) {
        g_B1[off + c2] = 0.f; g_B2[off + c2] = 0.f; g_B3[off + c2] = 0.f;
    }
}

// ============ Kernel D: fused triple GEMM + Y build (prefetched) =============
__global__ void k_D(const float* __restrict__ ls, const float* __restrict__ noise) {
    __shared__ float A1s[16][64], A2s[16][64];
    __shared__ float B1s[16][64], B2s[16][64], B3s[16][64];
    int tid = threadIdx.x;
    int tx = tid & 15, ty = tid >> 4;
    int n0 = blockIdx.x * 64, m0 = blockIdx.y * 64;
    int a = blockIdx.z;
    u64 ac1[4][2], ac2[4][2], ac3[4][2];
    #pragma unroll
    for (int i = 0; i < 4; i++) {
        ac1[i][0] = ac1[i][1] = 0ULL;
        ac2[i][0] = ac2[i][1] = 0ULL;
        ac3[i][0] = ac3[i][1] = 0ULL;
    }
    int lm = tid >> 2, lk = (tid & 3) << 2;
    int bk = tid >> 4, bn4 = (tid & 15) << 2;
    const float* lsb = ls    + (size_t)a * L * L;
    const float* nsb = noise + (size_t)a * L * L;
    float4 z4 = make_float4(0.f, 0.f, 0.f, 0.f);
    int ia = m0 + lm;
    float4 lvP = z4, nvP = z4, b1P = z4, b2P = z4, b3P = z4;
    if (ia < L && lk < L) {
        lvP = *reinterpret_cast<const float4*>(lsb + (size_t)ia * L + lk);
        nvP = *reinterpret_cast<const float4*>(nsb + (size_t)ia * L + lk);
    }
    {
        size_t o = (size_t)(a * L + bk) * STRH + n0 + bn4;
        b1P = *reinterpret_cast<const float4*>(&g_B1[o]);
        b2P = *reinterpret_cast<const float4*>(&g_B2[o]);
        b3P = *reinterpret_cast<const float4*>(&g_B3[o]);
    }
    for (int k0 = 0; k0 < 208; k0 += 16) {
        A1s[lk + 0][lm] = lvP.x * nvP.x; A2s[lk + 0][lm] = lvP.x;
        A1s[lk + 1][lm] = lvP.y * nvP.y; A2s[lk + 1][lm] = lvP.y;
        A1s[lk + 2][lm] = lvP.z * nvP.z; A2s[lk + 2][lm] = lvP.z;
        A1s[lk + 3][lm] = lvP.w * nvP.w; A2s[lk + 3][lm] = lvP.w;
        *reinterpret_cast<float4*>(&B1s[bk][bn4]) = b1P;
        *reinterpret_cast<float4*>(&B2s[bk][bn4]) = b2P;
        *reinterpret_cast<float4*>(&B3s[bk][bn4]) = b3P;
        __syncthreads();
        int kn = k0 + 16;
        if (kn < 208) {
            int ja = kn + lk;
            lvP = z4; nvP = z4;
            if (ia < L && ja < L) {
                lvP = *reinterpret_cast<const float4*>(lsb + (size_t)ia * L + ja);
                nvP = *reinterpret_cast<const float4*>(nsb + (size_t)ia * L + ja);
            }
            int jb = kn + bk;
            b1P = z4; b2P = z4; b3P = z4;
            if (jb < L) {
                size_t o = (size_t)(a * L + jb) * STRH + n0 + bn4;
                b1P = *reinterpret_cast<const float4*>(&g_B1[o]);
                b2P = *reinterpret_cast<const float4*>(&g_B2[o]);
                b3P = *reinterpret_cast<const float4*>(&g_B3[o]);
            }
        }
        #pragma unroll
        for (int kk = 0; kk < 16; kk++) {
            float4 a1 = *reinterpret_cast<float4*>(&A1s[kk][ty << 2]);
            float4 a2 = *reinterpret_cast<float4*>(&A2s[kk][ty << 2]);
            u64 b1a = *reinterpret_cast<u64*>(&B1s[kk][tx << 2]);
            u64 b1b = *reinterpret_cast<u64*>(&B1s[kk][(tx << 2) + 2]);
            u64 b2a = *reinterpret_cast<u64*>(&B2s[kk][tx << 2]);
            u64 b2b = *reinterpret_cast<u64*>(&B2s[kk][(tx << 2) + 2]);
            u64 b3a = *reinterpret_cast<u64*>(&B3s[kk][tx << 2]);
            u64 b3b = *reinterpret_cast<u64*>(&B3s[kk][(tx << 2) + 2]);
            const float* a1p = reinterpret_cast<const float*>(&a1);
            const float* a2p = reinterpret_cast<const float*>(&a2);
            #pragma unroll
            for (int im = 0; im < 4; im++) {
                u64 aa1 = pack2(a1p[im], a1p[im]);
                u64 aa2 = pack2(a2p[im], a2p[im]);
                fma2(ac1[im][0], aa1, b1a); fma2(ac1[im][1], aa1, b1b);
                fma2(ac2[im][0], aa2, b2a); fma2(ac2[im][1], aa2, b2b);
                fma2(ac3[im][0], aa2, b3a); fma2(ac3[im][1], aa2, b3b);
            }
        }
        __syncthreads();
    }
    #pragma unroll
    for (int im = 0; im < 4; im++) {
        int i = m0 + (ty << 2) + im;
        if (i >= L) continue;
        int row = a * L + i;
        size_t ob = (size_t)row * STRH;
        size_t by = (size_t)row * KI;
        int n = n0 + (tx << 2);
        float2 p1a = unpack2(ac1[im][0]), p1b = unpack2(ac1[im][1]);
        float2 p2a = unpack2(ac2[im][0]), p2b = unpack2(ac2[im][1]);
        float2 p3a = unpack2(ac3[im][0]), p3b = unpack2(ac3[im][1]);
        float num[4] = {p1a.x + p2a.x, p1a.y + p2a.y, p1b.x + p2b.x, p1b.y + p2b.y};
        float den[4] = {p3a.x, p3a.y, p3b.x, p3b.y};
        #pragma unroll
        for (int c = 0; c < 4; c++) {
            int col = n + c;
            if (col >= 385) continue;
            float s = num[c] / fmaxf(den[c], 1e-7f);
            float xr = g_Xr[ob + col], xi = g_Xi[ob + col];
            float m2 = xr * xr + xi * xi;
            float yr, yi;
            if (m2 > 0.f) { float r = s / sqrtf(m2); yr = xr * r; yi = xi * r; }
            else          { yr = s; yi = 0.f; }
            float w = (col == 0 || col == 384) ? 1.f : 2.f;
            g_YA[by + col] = w * yr;
            g_YA[by + 385 + col] = w * yi;
        }
    }
}

// ============ Kernel E: inverse DFT GEMM (prefetched) ========================
__global__ void k_E(float* __restrict__ out) {
    __shared__ float As[16][64];
    __shared__ float Bs[16][64];
    int tid = threadIdx.x;
    int tx = tid & 15, ty = tid >> 4;
    int n0 = blockIdx.x * 64, m0 = blockIdx.y * 64;
    u64 acc[4][2];
    #pragma unroll
    for (int i = 0; i < 4; i++) { acc[i][0] = 0ULL; acc[i][1] = 0ULL; }
    int lm = tid >> 2, lk = (tid & 3) << 2;
    int bk = tid >> 4, bn4 = (tid & 15) << 2;
    int arow = m0 + lm;
    bool avalid = arow < NLTOT;
    const float* Abase = g_YA + (size_t)arow * KI;
    float4 z4 = make_float4(0.f, 0.f, 0.f, 0.f);
    float4 avP = avalid ? *reinterpret_cast<const float4*>(Abase + lk) : z4;
    float4 bvP = *reinterpret_cast<const float4*>(&g_Ti[(size_t)bk * D + n0 + bn4]);
    for (int k0 = 0; k0 < KI; k0 += 16) {
        As[lk + 0][lm] = avP.x; As[lk + 1][lm] = avP.y;
        As[lk + 2][lm] = avP.z; As[lk + 3][lm] = avP.w;
        *reinterpret_cast<float4*>(&Bs[bk][bn4]) = bvP;
        __syncthreads();
        int kn = k0 + 16;
        if (kn < KI) {
            avP = avalid ? *reinterpret_cast<const float4*>(Abase + kn + lk) : z4;
            bvP = *reinterpret_cast<const float4*>(&g_Ti[(size_t)(kn + bk) * D + n0 + bn4]);
        }
        #pragma unroll
        for (int kk = 0; kk < 16; kk++) {
            float4 a4 = *reinterpret_cast<float4*>(&As[kk][ty << 2]);
            u64 b01 = *reinterpret_cast<u64*>(&Bs[kk][tx << 2]);
            u64 b23 = *reinterpret_cast<u64*>(&Bs[kk][(tx << 2) + 2]);
            const float* ap = reinterpret_cast<const float*>(&a4);
            #pragma unroll
            for (int im = 0; im < 4; im++) {
                u64 aa = pack2(ap[im], ap[im]);
                fma2(acc[im][0], aa, b01);
                fma2(acc[im][1], aa, b23);
            }
        }
        __syncthreads();
    }
    #pragma unroll
    for (int im = 0; im < 4; im++) {
        int row = m0 + (ty << 2) + im;
        if (row >= NLTOT) continue;
        int a = row / L, i = row % L;
        float2 c01 = unpack2(acc[im][0]);
        float2 c23 = unpack2(acc[im][1]);
        float4 o = make_float4(c01.x * (1.f / 768.f), c01.y * (1.f / 768.f),
                               c23.x * (1.f / 768.f), c23.y * (1.f / 768.f));
        *reinterpret_cast<float4*>(
            &out[((size_t)(a * 197 + 1 + i)) * D + n0 + (tx << 2)]) = o;
    }
}

// ---------------- launch ------------------------------------------------------
extern "C" void kernel_launch(void* const* d_in, const int* in_sizes, int n_in,
                              void* d_out, int out_size) {
    const float* x     = (const float*)d_in[0];
    const float* imgs  = (const float*)d_in[1];
    const float* ls    = (const float*)d_in[2];
    const float* noise = (const float*)d_in[3];
    float* out = (float*)d_out;

    k_A<<<A_GRID, 256>>>(imgs, x, out);
    k_B<<<147, 256>>>(x);
    k_C<<<NLTOT, 256>>>();
    k_D<<<dim3(7, 4, NB), 256>>>(ls, noise);
    k_E<<<dim3(12, 7), 256>>>(out);
}

// round 5
// speedup vs baseline: 1.2988x; 1.0023x over previous
#include <cuda_runtime.h>
#include <math.h>

#define NB 2
#define L 196
#define D 768
#define LD (L*D)
#define MW 7
#define NLTOT (NB*L)   // 392
#define STRH 448
#define NF 832
#define KI 784

// ---------------- scratch ---------------------------------------------------
__device__ float    g_V  [NB*LD];
__device__ float    g_Tf [D*NF];
__device__ float    g_Ti [KI*D];
__device__ float    g_YA [NLTOT*KI];
__device__ float    g_Xr [NLTOT*STRH];
__device__ float    g_Xi [NLTOT*STRH];
__device__ float    g_sty[NLTOT*STRH];
__device__ float    g_B1 [NLTOT*STRH];
__device__ float    g_B2 [NLTOT*STRH];
__device__ float    g_B3 [NLTOT*STRH];
__device__ unsigned g_M  [NB*L*MW];

// ---------------- f32x2 helpers ---------------------------------------------
typedef unsigned long long u64;
__device__ __forceinline__ void fma2(u64 &acc, u64 a, u64 b) {
    asm("fma.rn.f32x2 %0, %1, %2, %0;" : "+l"(acc) : "l"(a), "l"(b));
}
__device__ __forceinline__ u64 pack2(float x, float y) {
    u64 r; asm("mov.b64 %0, {%1, %2};" : "=l"(r) : "f"(x), "f"(y)); return r;
}
__device__ __forceinline__ float2 unpack2(u64 v) {
    float2 f; asm("mov.b64 {%0, %1}, %2;" : "=f"(f.x), "=f"(f.y) : "l"(v)); return f;
}

__device__ __forceinline__ float blockSum256(float v, float* red) {
    #pragma unroll
    for (int o = 16; o; o >>= 1) v += __shfl_xor_sync(0xffffffffu, v, o);
    if ((threadIdx.x & 31) == 0) red[threadIdx.x >> 5] = v;
    __syncthreads();
    if (threadIdx.x < 32) {
        float x = (threadIdx.x < 8) ? red[threadIdx.x] : 0.f;
        #pragma unroll
        for (int o = 4; o; o >>= 1) x += __shfl_xor_sync(0xffffffffu, x, o);
        if (threadIdx.x == 0) red[0] = x;
    }
    __syncthreads();
    float r = red[0];
    __syncthreads();
    return r;
}

// ============ Kernel A: misc | twiddle | patch ================================
#define A_MISC 22
#define A_TW   194
#define A_GRID (A_MISC + A_TW + NLTOT)

__global__ void k_A(const float* __restrict__ imgs, const float* __restrict__ x,
                    float* __restrict__ out) {
    int b = blockIdx.x, tid = threadIdx.x;
    if (b < A_MISC) {
        int t = b * 256 + tid;
        if (t < NB * L * MW) g_M[t] = 0u;
        if (t < NLTOT * (KI - 770)) {
            int row = t / (KI - 770), c = 770 + t % (KI - 770);
            g_YA[(size_t)row * KI + c] = 0.f;
        }
        if (t < NB * D) {
            int a = t / D, d = t % D;
            out[(size_t)a * 197 * D + d] = x[(size_t)a * 197 * D + d];
        }
        return;
    }
    if (b < A_MISC + A_TW) {
        __shared__ float2 tw[D];
        for (int i = tid; i < D; i += 256) {
            float s, c; sincospif((float)i * (1.f / 384.f), &s, &c);
            tw[i] = make_float2(c, s);
        }
        __syncthreads();
        int r0 = (b - A_MISC) * 8;
        #pragma unroll
        for (int rr = 0; rr < 8; rr++) {
            int r = r0 + rr;
            if (r >= D + KI) break;
            if (r < D) {
                int d = r;
                for (int k = tid; k < NF / 2; k += 256) {
                    int idx = (d * k) % D;
                    float2 t2 = tw[idx];
                    *reinterpret_cast<float2*>(&g_Tf[(size_t)d * NF + 2 * k]) =
                        make_float2(t2.x, -t2.y);
                }
            } else {
                int q = r - D;
                for (int d = tid; d < D; d += 256) {
                    float v;
                    if (q < 385)      v =  tw[(q * d) % D].x;
                    else if (q < 770) v = -tw[((q - 385) * d) % D].y;
                    else              v = 0.f;
                    g_Ti[(size_t)q * D + d] = v;
                }
            }
        }
        return;
    }
    {
        __shared__ float red[8];
        __shared__ float buf[D];
        int blk = b - A_MISC - A_TW, a = blk / L, l = blk % L;
        int hh = l / 14, ww = l % 14;
        int p = tid >> 4, q = tid & 15;
        const float* base = imgs + ((size_t)a * 3 * 224 + (size_t)(hh * 16 + p)) * 224
                                 + (ww * 16 + q);
        float v[3];
        #pragma unroll
        for (int c = 0; c < 3; c++) v[c] = base[(size_t)c * 224 * 224];
        float mean = blockSum256(v[0] + v[1] + v[2], red) * (1.f / 768.f);
        float u[3]; float ss = 0.f;
        #pragma unroll
        for (int c = 0; c < 3; c++) { u[c] = v[c] - mean; ss += u[c] * u[c]; }
        float tot = blockSum256(ss, red);
        float inv = 1.f / sqrtf(tot);
        #pragma unroll
        for (int c = 0; c < 3; c++) buf[tid * 3 + c] = u[c] * inv;
        __syncthreads();
        if (tid < 192)
            reinterpret_cast<float4*>(g_V + (size_t)blk * D)[tid] =
                reinterpret_cast<float4*>(buf)[tid];
    }
}

// ============ Kernel B: sim (56) | fwd (91) = 147 blocks, double-buffered =====
__global__ void k_B(const float* __restrict__ x) {
    __shared__ __align__(16) float S[4608];
    int b = blockIdx.x, tid = threadIdx.x;
    if (b < 56) {
        // ---- sim: 32x32 tile, ktile 32, double-buffered ----
        int a = b / 28;
        int t = b % 28, bi = 0;
        while (t >= 7 - bi) { t -= 7 - bi; bi++; }
        int bj = bi + t;
        int i0 = bi * 32, j0 = bj * 32;
        float (*As)[34] = (float(*)[34])S;            // [2*32][34]
        float (*Bs)[34] = (float(*)[34])(S + 2176);
        int tx = tid & 15, ty = tid >> 4;
        int m = tid >> 3, k4 = (tid & 7) << 2;
        const float* Vb = g_V + (size_t)a * LD;
        const float* Arow = (i0 + m < L) ? Vb + (size_t)(i0 + m) * D : nullptr;
        const float* Brow = (j0 + m < L) ? Vb + (size_t)(j0 + m) * D : nullptr;
        float4 z4 = make_float4(0.f, 0.f, 0.f, 0.f);
        float4 avP = Arow ? *reinterpret_cast<const float4*>(Arow + k4) : z4;
        float4 bvP = Brow ? *reinterpret_cast<const float4*>(Brow + k4) : z4;
        u64 acc[2] = {0ULL, 0ULL};
        int p = 0;
        // prime buf0
        As[k4 + 0][m] = avP.x; As[k4 + 1][m] = avP.y;
        As[k4 + 2][m] = avP.z; As[k4 + 3][m] = avP.w;
        Bs[k4 + 0][m] = bvP.x; Bs[k4 + 1][m] = bvP.y;
        Bs[k4 + 2][m] = bvP.z; Bs[k4 + 3][m] = bvP.w;
        __syncthreads();
        for (int k0 = 0; k0 < D; k0 += 32) {
            int kn = k0 + 32;
            if (kn < D) {
                avP = Arow ? *reinterpret_cast<const float4*>(Arow + kn + k4) : z4;
                bvP = Brow ? *reinterpret_cast<const float4*>(Brow + kn + k4) : z4;
            }
            int pb = p * 32;
            #pragma unroll
            for (int kk = 0; kk < 32; kk++) {
                float2 a2 = *reinterpret_cast<float2*>(&As[pb + kk][ty << 1]);
                u64 bb = *reinterpret_cast<u64*>(&Bs[pb + kk][tx << 1]);
                fma2(acc[0], pack2(a2.x, a2.x), bb);
                fma2(acc[1], pack2(a2.y, a2.y), bb);
            }
            if (kn < D) {
                int qb = (1 - p) * 32;
                As[qb + k4 + 0][m] = avP.x; As[qb + k4 + 1][m] = avP.y;
                As[qb + k4 + 2][m] = avP.z; As[qb + k4 + 3][m] = avP.w;
                Bs[qb + k4 + 0][m] = bvP.x; Bs[qb + k4 + 1][m] = bvP.y;
                Bs[qb + k4 + 2][m] = bvP.z; Bs[qb + k4 + 3][m] = bvP.w;
                __syncthreads();
                p ^= 1;
            }
        }
        #pragma unroll
        for (int r = 0; r < 2; r++) {
            int i = i0 + (ty << 1) + r;
            if (i >= L) continue;
            float2 c = unpack2(acc[r]);
            int j = j0 + (tx << 1);
            if (j < L && j >= i && c.x > 0.3f)
                atomicOr(&g_M[(a * L + i) * MW + (j >> 5)], 1u << (j & 31));
            j++;
            if (j < L && j >= i && c.y > 0.3f)
                atomicOr(&g_M[(a * L + i) * MW + (j >> 5)], 1u << (j & 31));
        }
    } else {
        // ---- fwd: 64x64 tile, ktile 16, double-buffered ----
        int bb = b - 56;
        int n0 = (bb % 13) * 64, m0 = (bb / 13) * 64;
        float (*As)[64] = (float(*)[64])S;            // [2*16][64]
        float (*Bs)[64] = (float(*)[64])(S + 2048);
        int tx = tid & 15, ty = tid >> 4;
        u64 acc[4][2];
        #pragma unroll
        for (int i = 0; i < 4; i++) { acc[i][0] = 0ULL; acc[i][1] = 0ULL; }
        int lm = tid >> 2, lk = (tid & 3) << 2;
        int bk = tid >> 4, bn4 = (tid & 15) << 2;
        int arow = m0 + lm;
        bool avalid = arow < NLTOT;
        const float* Abase = nullptr;
        if (avalid) {
            int a = arow / L, i = arow % L;
            Abase = x + ((size_t)(a * 197 + 1 + i)) * D;
        }
        float4 z4 = make_float4(0.f, 0.f, 0.f, 0.f);
        float4 avP = avalid ? *reinterpret_cast<const float4*>(Abase + lk) : z4;
        float4 bvP = *reinterpret_cast<const float4*>(&g_Tf[(size_t)bk * NF + n0 + bn4]);
        int p = 0;
        As[lk + 0][lm] = avP.x; As[lk + 1][lm] = avP.y;
        As[lk + 2][lm] = avP.z; As[lk + 3][lm] = avP.w;
        *reinterpret_cast<float4*>(&Bs[bk][bn4]) = bvP;
        __syncthreads();
        for (int k0 = 0; k0 < D; k0 += 16) {
            int kn = k0 + 16;
            if (kn < D) {
                avP = avalid ? *reinterpret_cast<const float4*>(Abase + kn + lk) : z4;
                bvP = *reinterpret_cast<const float4*>(&g_Tf[(size_t)(kn + bk) * NF + n0 + bn4]);
            }
            int pb = p * 16;
            #pragma unroll
            for (int kk = 0; kk < 16; kk++) {
                float4 a4 = *reinterpret_cast<float4*>(&As[pb + kk][ty << 2]);
                u64 b01 = *reinterpret_cast<u64*>(&Bs[pb + kk][tx << 2]);
                u64 b23 = *reinterpret_cast<u64*>(&Bs[pb + kk][(tx << 2) + 2]);
                const float* ap = reinterpret_cast<const float*>(&a4);
                #pragma unroll
                for (int im = 0; im < 4; im++) {
                    u64 aa = pack2(ap[im], ap[im]);
                    fma2(acc[im][0], aa, b01);
                    fma2(acc[im][1], aa, b23);
                }
            }
            if (kn < D) {
                int qb = (1 - p) * 16;
                As[qb + lk + 0][lm] = avP.x; As[qb + lk + 1][lm] = avP.y;
                As[qb + lk + 2][lm] = avP.z; As[qb + lk + 3][lm] = avP.w;
                *reinterpret_cast<float4*>(&Bs[qb + bk][bn4]) = bvP;
                __syncthreads();
                p ^= 1;
            }
        }
        int n = n0 + (tx << 2);
        int k = n >> 1;
        #pragma unroll
        for (int im = 0; im < 4; im++) {
            int row = m0 + (ty << 2) + im;
            if (row >= NLTOT) continue;
            size_t bo = (size_t)row * STRH;
            float2 c01 = unpack2(acc[im][0]);
            float2 c23 = unpack2(acc[im][1]);
            if (k <= 384) {
                g_Xr[bo + k] = c01.x; g_Xi[bo + k] = c01.y;
                g_sty[bo + k] = sqrtf(c01.x * c01.x + c01.y * c01.y);
            }
            if (k + 1 <= 384) {
                g_Xr[bo + k + 1] = c23.x; g_Xi[bo + k + 1] = c23.y;
                g_sty[bo + k + 1] = sqrtf(c23.x * c23.x + c23.y * c23.y);
            }
        }
    }
}

// ============ Kernel C: per-row local prop replay + stats ====================
__global__ void k_C() {
    __shared__ unsigned m[NB * L * MW];
    __shared__ int sS, sRem, ired[8];
    int blk = blockIdx.x, a = blk / L, i = blk % L;
    int tid = threadIdx.x;
    int local = 0;
    for (int t = tid; t < NB * L * MW; t += 256) {
        unsigned w = g_M[t]; m[t] = w; local += __popc(w);
    }
    #pragma unroll
    for (int o = 16; o; o >>= 1) local += __shfl_xor_sync(0xffffffffu, local, o);
    if ((tid & 31) == 0) ired[tid >> 5] = local;
    __syncthreads();
    if (tid == 0) {
        int s = 0;
        #pragma unroll
        for (int w = 0; w < 8; w++) s += ired[w];
        sS = s;
    }
    __syncthreads();
    for (int ii = 0; ii < i; ii++) {
        if (sS == NB * L) break;
        if (tid == 0) sRem = 0;
        __syncthreads();
        int rem = 0;
        int nj = L - 1 - ii;
        int cnt = NB * nj * MW;
        for (int t = tid; t < cnt; t += 256) {
            int w = t % MW; int r = t / MW;
            int j = ii + 1 + (r % nj); int aa = r / nj;
            unsigned rw  = m[(aa * L + ii) * MW + w];
            unsigned old = m[(aa * L + j) * MW + w];
            unsigned drop = old & rw;
            if (drop) { m[(aa * L + j) * MW + w] = old & ~rw; rem += __popc(drop); }
        }
        #pragma unroll
        for (int o = 16; o; o >>= 1) rem += __shfl_xor_sync(0xffffffffu, rem, o);
        if ((tid & 31) == 0 && rem) atomicAdd(&sRem, rem);
        __syncthreads();
        if (tid == 0) sS -= sRem;
        __syncthreads();
    }
    const unsigned* mw = &m[(a * L + i) * MW];
    int num = 0;
    #pragma unroll
    for (int w = 0; w < MW; w++) num += __popc(mw[w]);
    float numc = (num > 0) ? (float)num : 1e-7f;
    bool has2 = tid < 129;
    int c1 = tid, c2 = tid + 256;
    float S1a = 0.f, S1b = 0.f;
    for (int w = 0; w < MW; w++) {
        unsigned bits = mw[w];
        while (bits) {
            int j = (w << 5) + __ffs((int)bits) - 1; bits &= bits - 1;
            const float* sp = g_sty + (size_t)(a * L + j) * STRH;
            S1a += sp[c1];
            if (has2) S1b += sp[c2];
        }
    }
    float avga = S1a / numc, avgb = S1b / numc;
    float S2a = 0.f, S2b = 0.f;
    for (int w = 0; w < MW; w++) {
        unsigned bits = mw[w];
        while (bits) {
            int j = (w << 5) + __ffs((int)bits) - 1; bits &= bits - 1;
            const float* sp = g_sty + (size_t)(a * L + j) * STRH;
            float xa = sp[c1] - avga; S2a += xa * xa;
            if (has2) { float xb = sp[c2] - avgb; S2b += xb * xb; }
        }
    }
    size_t off = (size_t)blk * STRH;
    float sta = sqrtf(S2a / numc);
    float ma = (S1a > 0.f) ? 1.f : 0.f;
    g_B1[off + c1] = ma * sta; g_B2[off + c1] = ma * avga; g_B3[off + c1] = ma;
    if (has2) {
        float stb = sqrtf(S2b / numc);
        float mb = (S1b > 0.f) ? 1.f : 0.f;
        g_B1[off + c2] = mb * stb; g_B2[off + c2] = mb * avgb; g_B3[off + c2] = mb;
    } else if (tid < 192) {
        g_B1[off + c2] = 0.f; g_B2[off + c2] = 0.f; g_B3[off + c2] = 0.f;
    }
}

// ============ Kernel D: triple GEMM + Y build; 32x64 tiles, double-buffered ==
__global__ void k_D(const float* __restrict__ ls, const float* __restrict__ noise) {
    __shared__ __align__(16) float SD[8192];
    float (*A1s)[32] = (float(*)[32])SD;           // [2*16][32]
    float (*A2s)[32] = (float(*)[32])(SD + 1024);
    float (*B1s)[64] = (float(*)[64])(SD + 2048);  // [2*16][64]
    float (*B2s)[64] = (float(*)[64])(SD + 4096);
    float (*B3s)[64] = (float(*)[64])(SD + 6144);
    int tid = threadIdx.x;
    int tx = tid & 15, ty = tid >> 4;
    int n0 = blockIdx.x * 64, m0 = blockIdx.y * 32;
    int a = blockIdx.z;
    u64 ac1[2][2], ac2[2][2], ac3[2][2];
    #pragma unroll
    for (int i = 0; i < 2; i++) {
        ac1[i][0] = ac1[i][1] = 0ULL;
        ac2[i][0] = ac2[i][1] = 0ULL;
        ac3[i][0] = ac3[i][1] = 0ULL;
    }
    int lm = tid >> 3, lk2 = (tid & 7) << 1;       // A: 32 rows x 16 k
    int bk = tid >> 4, bn4 = (tid & 15) << 2;      // B: 16 k x 64 n
    const float* lsb = ls    + (size_t)a * L * L;
    const float* nsb = noise + (size_t)a * L * L;
    float4 z4 = make_float4(0.f, 0.f, 0.f, 0.f);
    int ia = m0 + lm;
    bool iav = ia < L;
    // prefetch tile 0
    float lv0 = 0.f, lv1 = 0.f, nv0 = 0.f, nv1 = 0.f;
    if (iav) {
        int ja = lk2;
        if (ja < L)     { lv0 = lsb[(size_t)ia * L + ja];     nv0 = nsb[(size_t)ia * L + ja]; }
        if (ja + 1 < L) { lv1 = lsb[(size_t)ia * L + ja + 1]; nv1 = nsb[(size_t)ia * L + ja + 1]; }
    }
    float4 b1P = z4, b2P = z4, b3P = z4;
    {
        size_t o = (size_t)(a * L + bk) * STRH + n0 + bn4;
        b1P = *reinterpret_cast<const float4*>(&g_B1[o]);
        b2P = *reinterpret_cast<const float4*>(&g_B2[o]);
        b3P = *reinterpret_cast<const float4*>(&g_B3[o]);
    }
    int p = 0;
    A1s[lk2 + 0][lm] = lv0 * nv0; A2s[lk2 + 0][lm] = lv0;
    A1s[lk2 + 1][lm] = lv1 * nv1; A2s[lk2 + 1][lm] = lv1;
    *reinterpret_cast<float4*>(&B1s[bk][bn4]) = b1P;
    *reinterpret_cast<float4*>(&B2s[bk][bn4]) = b2P;
    *reinterpret_cast<float4*>(&B3s[bk][bn4]) = b3P;
    __syncthreads();
    for (int k0 = 0; k0 < 208; k0 += 16) {
        int kn = k0 + 16;
        if (kn < 208) {
            lv0 = lv1 = nv0 = nv1 = 0.f;
            if (iav) {
                int ja = kn + lk2;
                if (ja < L)     { lv0 = lsb[(size_t)ia * L + ja];     nv0 = nsb[(size_t)ia * L + ja]; }
                if (ja + 1 < L) { lv1 = lsb[(size_t)ia * L + ja + 1]; nv1 = nsb[(size_t)ia * L + ja + 1]; }
            }
            int jb = kn + bk;
            b1P = z4; b2P = z4; b3P = z4;
            if (jb < L) {
                size_t o = (size_t)(a * L + jb) * STRH + n0 + bn4;
                b1P = *reinterpret_cast<const float4*>(&g_B1[o]);
                b2P = *reinterpret_cast<const float4*>(&g_B2[o]);
                b3P = *reinterpret_cast<const float4*>(&g_B3[o]);
            }
        }
        int pb = p * 16;
        #pragma unroll
        for (int kk = 0; kk < 16; kk++) {
            float2 a1 = *reinterpret_cast<float2*>(&A1s[pb + kk][ty << 1]);
            float2 a2 = *reinterpret_cast<float2*>(&A2s[pb + kk][ty << 1]);
            u64 b1a = *reinterpret_cast<u64*>(&B1s[pb + kk][tx << 2]);
            u64 b1b = *reinterpret_cast<u64*>(&B1s[pb + kk][(tx << 2) + 2]);
            u64 b2a = *reinterpret_cast<u64*>(&B2s[pb + kk][tx << 2]);
            u64 b2b = *reinterpret_cast<u64*>(&B2s[pb + kk][(tx << 2) + 2]);
            u64 b3a = *reinterpret_cast<u64*>(&B3s[pb + kk][tx << 2]);
            u64 b3b = *reinterpret_cast<u64*>(&B3s[pb + kk][(tx << 2) + 2]);
            const float* a1p = reinterpret_cast<const float*>(&a1);
            const float* a2p = reinterpret_cast<const float*>(&a2);
            #pragma unroll
            for (int im = 0; im < 2; im++) {
                u64 aa1 = pack2(a1p[im], a1p[im]);
                u64 aa2 = pack2(a2p[im], a2p[im]);
                fma2(ac1[im][0], aa1, b1a); fma2(ac1[im][1], aa1, b1b);
                fma2(ac2[im][0], aa2, b2a); fma2(ac2[im][1], aa2, b2b);
                fma2(ac3[im][0], aa2, b3a); fma2(ac3[im][1], aa2, b3b);
            }
        }
        if (kn < 208) {
            int qb = (1 - p) * 16;
            A1s[qb + lk2 + 0][lm] = lv0 * nv0; A2s[qb + lk2 + 0][lm] = lv0;
            A1s[qb + lk2 + 1][lm] = lv1 * nv1; A2s[qb + lk2 + 1][lm] = lv1;
            *reinterpret_cast<float4*>(&B1s[qb + bk][bn4]) = b1P;
            *reinterpret_cast<float4*>(&B2s[qb + bk][bn4]) = b2P;
            *reinterpret_cast<float4*>(&B3s[qb + bk][bn4]) = b3P;
            __syncthreads();
            p ^= 1;
        }
    }
    #pragma unroll
    for (int im = 0; im < 2; im++) {
        int i = m0 + (ty << 1) + im;
        if (i >= L) continue;
        int row = a * L + i;
        size_t ob = (size_t)row * STRH;
        size_t by = (size_t)row * KI;
        int n = n0 + (tx << 2);
        float2 p1a = unpack2(ac1[im][0]), p1b = unpack2(ac1[im][1]);
        float2 p2a = unpack2(ac2[im][0]), p2b = unpack2(ac2[im][1]);
        float2 p3a = unpack2(ac3[im][0]), p3b = unpack2(ac3[im][1]);
        float num[4] = {p1a.x + p2a.x, p1a.y + p2a.y, p1b.x + p2b.x, p1b.y + p2b.y};
        float den[4] = {p3a.x, p3a.y, p3b.x, p3b.y};
        #pragma unroll
        for (int c = 0; c < 4; c++) {
            int col = n + c;
            if (col >= 385) continue;
            float s = num[c] / fmaxf(den[c], 1e-7f);
            float xr = g_Xr[ob + col], xi = g_Xi[ob + col];
            float m2 = xr * xr + xi * xi;
            float yr, yi;
            if (m2 > 0.f) { float r = s / sqrtf(m2); yr = xr * r; yi = xi * r; }
            else          { yr = s; yi = 0.f; }
            float w = (col == 0 || col == 384) ? 1.f : 2.f;
            g_YA[by + col] = w * yr;
            g_YA[by + 385 + col] = w * yi;
        }
    }
}

// ============ Kernel E: inverse DFT GEMM, double-buffered ====================
__global__ void k_E(float* __restrict__ out) {
    __shared__ __align__(16) float S[4096];
    float (*As)[64] = (float(*)[64])S;
    float (*Bs)[64] = (float(*)[64])(S + 2048);
    int tid = threadIdx.x;
    int tx = tid & 15, ty = tid >> 4;
    int n0 = blockIdx.x * 64, m0 = blockIdx.y * 64;
    u64 acc[4][2];
    #pragma unroll
    for (int i = 0; i < 4; i++) { acc[i][0] = 0ULL; acc[i][1] = 0ULL; }
    int lm = tid >> 2, lk = (tid & 3) << 2;
    int bk = tid >> 4, bn4 = (tid & 15) << 2;
    int arow = m0 + lm;
    bool avalid = arow < NLTOT;
    const float* Abase = g_YA + (size_t)arow * KI;
    float4 z4 = make_float4(0.f, 0.f, 0.f, 0.f);
    float4 avP = avalid ? *reinterpret_cast<const float4*>(Abase + lk) : z4;
    float4 bvP = *reinterpret_cast<const float4*>(&g_Ti[(size_t)bk * D + n0 + bn4]);
    int p = 0;
    As[lk + 0][lm] = avP.x; As[lk + 1][lm] = avP.y;
    As[lk + 2][lm] = avP.z; As[lk + 3][lm] = avP.w;
    *reinterpret_cast<float4*>(&Bs[bk][bn4]) = bvP;
    __syncthreads();
    for (int k0 = 0; k0 < KI; k0 += 16) {
        int kn = k0 + 16;
        if (kn < KI) {
            avP = avalid ? *reinterpret_cast<const float4*>(Abase + kn + lk) : z4;
            bvP = *reinterpret_cast<const float4*>(&g_Ti[(size_t)(kn + bk) * D + n0 + bn4]);
        }
        int pb = p * 16;
        #pragma unroll
        for (int kk = 0; kk < 16; kk++) {
            float4 a4 = *reinterpret_cast<float4*>(&As[pb + kk][ty << 2]);
            u64 b01 = *reinterpret_cast<u64*>(&Bs[pb + kk][tx << 2]);
            u64 b23 = *reinterpret_cast<u64*>(&Bs[pb + kk][(tx << 2) + 2]);
            const float* ap = reinterpret_cast<const float*>(&a4);
            #pragma unroll
            for (int im = 0; im < 4; im++) {
                u64 aa = pack2(ap[im], ap[im]);
                fma2(acc[im][0], aa, b01);
                fma2(acc[im][1], aa, b23);
            }
        }
        if (kn < KI) {
            int qb = (1 - p) * 16;
            As[qb + lk + 0][lm] = avP.x; As[qb + lk + 1][lm] = avP.y;
            As[qb + lk + 2][lm] = avP.z; As[qb + lk + 3][lm] = avP.w;
            *reinterpret_cast<float4*>(&Bs[qb + bk][bn4]) = bvP;
            __syncthreads();
            p ^= 1;
        }
    }
    #pragma unroll
    for (int im = 0; im < 4; im++) {
        int row = m0 + (ty << 2) + im;
        if (row >= NLTOT) continue;
        int a = row / L, i = row % L;
        float2 c01 = unpack2(acc[im][0]);
        float2 c23 = unpack2(acc[im][1]);
        float4 o = make_float4(c01.x * (1.f / 768.f), c01.y * (1.f / 768.f),
                               c23.x * (1.f / 768.f), c23.y * (1.f / 768.f));
        *reinterpret_cast<float4*>(
            &out[((size_t)(a * 197 + 1 + i)) * D + n0 + (tx << 2)]) = o;
    }
}

// ---------------- launch ------------------------------------------------------
extern "C" void kernel_launch(void* const* d_in, const int* in_sizes, int n_in,
                              void* d_out, int out_size) {
    const float* x     = (const float*)d_in[0];
    const float* imgs  = (const float*)d_in[1];
    const float* ls    = (const float*)d_in[2];
    const float* noise = (const float*)d_in[3];
    float* out = (float*)d_out;

    k_A<<<A_GRID, 256>>>(imgs, x, out);
    k_B<<<147, 256>>>(x);
    k_C<<<NLTOT, 256>>>();
    k_D<<<dim3(7, 7, NB), 256>>>(ls, noise);
    k_E<<<dim3(12, 7), 256>>>(out);
}

// round 6
// speedup vs baseline: 2.7709x; 2.1334x over previous
#include <cuda_runtime.h>
#include <math.h>

#define NB 2
#define L 196
#define D 768
#define LD (L*D)
#define MW 7
#define NLTOT (NB*L)   // 392
#define STRH 448       // padded half-spectrum stride

// ---------------- scratch ---------------------------------------------------
__device__ float    g_V   [NB*LD];
__device__ float    g_Xr  [NLTOT*STRH];
__device__ float    g_Xi  [NLTOT*STRH];
__device__ float    g_sty [NLTOT*STRH];
__device__ float    g_S   [NLTOT*STRH];
__device__ float    g_B1  [NLTOT*STRH];
__device__ float    g_B2  [NLTOT*STRH];
__device__ float    g_B3  [NLTOT*STRH];
__device__ float    g_rsum[NLTOT];
__device__ unsigned g_M   [NB*L*MW];
__device__ int      g_nzero;

// ---------------- f32x2 helpers ---------------------------------------------
typedef unsigned long long u64;
__device__ __forceinline__ void fma2(u64 &acc, u64 a, u64 b) {
    asm("fma.rn.f32x2 %0, %1, %2, %0;" : "+l"(acc) : "l"(a), "l"(b));
}
__device__ __forceinline__ u64 pack2(float x, float y) {
    u64 r; asm("mov.b64 %0, {%1, %2};" : "=l"(r) : "f"(x), "f"(y)); return r;
}
__device__ __forceinline__ float2 unpack2(u64 v) {
    float2 f; asm("mov.b64 {%0, %1}, %2;" : "=f"(f.x), "=f"(f.y) : "l"(v)); return f;
}

__device__ __forceinline__ float blockSum256(float v, float* red) {
    #pragma unroll
    for (int o = 16; o; o >>= 1) v += __shfl_xor_sync(0xffffffffu, v, o);
    if ((threadIdx.x & 31) == 0) red[threadIdx.x >> 5] = v;
    __syncthreads();
    if (threadIdx.x < 32) {
        float x = (threadIdx.x < 8) ? red[threadIdx.x] : 0.f;
        #pragma unroll
        for (int o = 4; o; o >>= 1) x += __shfl_xor_sync(0xffffffffu, x, o);
        if (threadIdx.x == 0) red[0] = x;
    }
    __syncthreads();
    float r = red[0];
    __syncthreads();
    return r;
}

// ---------------- Stockham mixed-radix FFT, N=768 = 3 * 2^8 ------------------
// 256 threads. sgn = -1 forward DFT, +1 inverse (unscaled). Result in returned ptr.
__device__ __forceinline__ float2* fft768(float2* a, float2* b, int tid, float sgn) {
    // radix-3 stage, l=1: 256 butterflies, one per thread
    {
        const float c3 = 0.8660254037844386f * sgn;   // w3 = -1/2 + i*c3
        float2 x0 = a[tid], x1 = a[tid + 256], x2 = a[tid + 512];
        float2 s = make_float2(x1.x + x2.x, x1.y + x2.y);
        float2 d = make_float2(x1.x - x2.x, x1.y - x2.y);
        float mr = x0.x - 0.5f * s.x, mi = x0.y - 0.5f * s.y;
        b[3 * tid]     = make_float2(x0.x + s.x, x0.y + s.y);
        b[3 * tid + 1] = make_float2(mr - c3 * d.y, mi + c3 * d.x);
        b[3 * tid + 2] = make_float2(mr + c3 * d.y, mi - c3 * d.x);
    }
    __syncthreads();
    // 8 radix-2 stages: l = 3,6,...,384
    float2* src = b; float2* dst = a;
    #pragma unroll
    for (int st = 0; st < 8; st++) {
        const int l = 3 << st;
        const float invl = 1.0f / (float)(3 << st);
        #pragma unroll
        for (int rep = 0; rep < 2; rep++) {
            int j = tid + rep * 256;
            if (j < 384) {
                int k = j % l;
                float2 u = src[j], v = src[j + 384];
                float sn, cs;
                sincospif(sgn * (float)k * invl, &sn, &cs);  // cis(sgn*pi*k/l)
                float2 vw = make_float2(v.x * cs - v.y * sn, v.x * sn + v.y * cs);
                dst[2 * j - k]     = make_float2(u.x + vw.x, u.y + vw.y);
                dst[2 * j - k + l] = make_float2(u.x - vw.x, u.y - vw.y);
            }
        }
        __syncthreads();
        float2* t = src; src = dst; dst = t;
    }
    return src;
}

// ============ Kernel A: fwdFFT(392) | patch(392) | rowsum(49) | misc(11) =====
#define A_FFT   392
#define A_PATCH 392
#define A_RS    49
#define A_MISC  11
#define A_GRID  (A_FFT + A_PATCH + A_RS + A_MISC)

__global__ void k_A(const float* __restrict__ imgs, const float* __restrict__ x,
                    float* __restrict__ out, const float* __restrict__ ls) {
    __shared__ __align__(16) char sm[12352];
    int b = blockIdx.x, tid = threadIdx.x;
    if (b < A_FFT) {
        // ---- forward FFT of x row ----
        float2* fa = (float2*)sm;
        float2* fb = fa + 768;
        int row = b, a = row / L, i = row % L;
        const float* xp = x + ((size_t)(a * 197 + 1 + i)) * D;
        for (int d = tid; d < D; d += 256) fa[d] = make_float2(xp[d], 0.f);
        __syncthreads();
        float2* res = fft768(fa, fb, tid, -1.0f);
        size_t bh = (size_t)row * STRH;
        for (int k = tid; k <= 384; k += 256) {
            float2 X = res[k];
            g_Xr[bh + k] = X.x; g_Xi[bh + k] = X.y;
            g_sty[bh + k] = sqrtf(X.x * X.x + X.y * X.y);
        }
        return;
    }
    b -= A_FFT;
    if (b < A_PATCH) {
        // ---- patchify + center + L2 normalize ----
        float* red = (float*)sm;
        float* buf = (float*)(sm + 64);
        int blk = b, a = blk / L, l = blk % L;
        int hh = l / 14, ww = l % 14;
        int p = tid >> 4, q = tid & 15;
        const float* base = imgs + ((size_t)a * 3 * 224 + (size_t)(hh * 16 + p)) * 224
                                 + (ww * 16 + q);
        float v[3];
        #pragma unroll
        for (int c = 0; c < 3; c++) v[c] = base[(size_t)c * 224 * 224];
        float mean = blockSum256(v[0] + v[1] + v[2], red) * (1.f / 768.f);
        float u[3]; float ss = 0.f;
        #pragma unroll
        for (int c = 0; c < 3; c++) { u[c] = v[c] - mean; ss += u[c] * u[c]; }
        float tot = blockSum256(ss, red);
        float inv = 1.f / sqrtf(tot);
        #pragma unroll
        for (int c = 0; c < 3; c++) buf[tid * 3 + c] = u[c] * inv;
        __syncthreads();
        if (tid < 192)
            reinterpret_cast<float4*>(g_V + (size_t)blk * D)[tid] =
                reinterpret_cast<float4*>(buf)[tid];
        return;
    }
    b -= A_PATCH;
    if (b < A_RS) {
        // ---- rowsum of ls: warp per row ----
        int w = tid >> 5, lane = tid & 31;
        int row = b * 8 + w;
        if (row < NLTOT) {
            int a = row / L, i = row % L;
            const float* lp = ls + ((size_t)a * L + i) * L;
            float s = 0.f;
            for (int j = lane; j < L; j += 32) s += lp[j];
            #pragma unroll
            for (int o = 16; o; o >>= 1) s += __shfl_xor_sync(0xffffffffu, s, o);
            if (lane == 0) g_rsum[row] = s;
        }
        return;
    }
    b -= A_RS;
    {
        int t = b * 256 + tid;
        if (t < NB * L * MW) g_M[t] = 0u;
        if (t < NB * D) {
            int a = t / D, d = t % D;
            out[(size_t)a * 197 * D + d] = x[(size_t)a * 197 * D + d];
        }
        if (t == 0) g_nzero = 0;
    }
}

// ============ Kernel B: sim 32x32 upper-tri, double-buffered =================
__global__ void k_B() {
    __shared__ __align__(16) float S[4352];
    int b = blockIdx.x, tid = threadIdx.x;
    int a = b / 28;
    int t = b % 28, bi = 0;
    while (t >= 7 - bi) { t -= 7 - bi; bi++; }
    int bj = bi + t;
    int i0 = bi * 32, j0 = bj * 32;
    float (*As)[34] = (float(*)[34])S;            // [2*32][34]
    float (*Bs)[34] = (float(*)[34])(S + 2176);
    int tx = tid & 15, ty = tid >> 4;
    int m = tid >> 3, k4 = (tid & 7) << 2;
    const float* Vb = g_V + (size_t)a * LD;
    const float* Arow = (i0 + m < L) ? Vb + (size_t)(i0 + m) * D : nullptr;
    const float* Brow = (j0 + m < L) ? Vb + (size_t)(j0 + m) * D : nullptr;
    float4 z4 = make_float4(0.f, 0.f, 0.f, 0.f);
    float4 avP = Arow ? *reinterpret_cast<const float4*>(Arow + k4) : z4;
    float4 bvP = Brow ? *reinterpret_cast<const float4*>(Brow + k4) : z4;
    u64 acc[2] = {0ULL, 0ULL};
    int p = 0;
    As[k4 + 0][m] = avP.x; As[k4 + 1][m] = avP.y;
    As[k4 + 2][m] = avP.z; As[k4 + 3][m] = avP.w;
    Bs[k4 + 0][m] = bvP.x; Bs[k4 + 1][m] = bvP.y;
    Bs[k4 + 2][m] = bvP.z; Bs[k4 + 3][m] = bvP.w;
    __syncthreads();
    for (int k0 = 0; k0 < D; k0 += 32) {
        int kn = k0 + 32;
        if (kn < D) {
            avP = Arow ? *reinterpret_cast<const float4*>(Arow + kn + k4) : z4;
            bvP = Brow ? *reinterpret_cast<const float4*>(Brow + kn + k4) : z4;
        }
        int pb = p * 32;
        #pragma unroll
        for (int kk = 0; kk < 32; kk++) {
            float2 a2 = *reinterpret_cast<float2*>(&As[pb + kk][ty << 1]);
            u64 bb = *reinterpret_cast<u64*>(&Bs[pb + kk][tx << 1]);
            fma2(acc[0], pack2(a2.x, a2.x), bb);
            fma2(acc[1], pack2(a2.y, a2.y), bb);
        }
        if (kn < D) {
            int qb = (1 - p) * 32;
            As[qb + k4 + 0][m] = avP.x; As[qb + k4 + 1][m] = avP.y;
            As[qb + k4 + 2][m] = avP.z; As[qb + k4 + 3][m] = avP.w;
            Bs[qb + k4 + 0][m] = bvP.x; Bs[qb + k4 + 1][m] = bvP.y;
            Bs[qb + k4 + 2][m] = bvP.z; Bs[qb + k4 + 3][m] = bvP.w;
            __syncthreads();
            p ^= 1;
        }
    }
    #pragma unroll
    for (int r = 0; r < 2; r++) {
        int i = i0 + (ty << 1) + r;
        if (i >= L) continue;
        float2 c = unpack2(acc[r]);
        int j = j0 + (tx << 1);
        if (j < L && j >= i && c.x > 0.3f)
            atomicOr(&g_M[(a * L + i) * MW + (j >> 5)], 1u << (j & 31));
        j++;
        if (j < L && j >= i && c.y > 0.3f)
            atomicOr(&g_M[(a * L + i) * MW + (j >> 5)], 1u << (j & 31));
    }
}

// ============ Kernel C: per-row prop replay + stats + nzero ==================
__global__ void k_C() {
    __shared__ unsigned m[NB * L * MW];
    __shared__ int sS, sRem, ired[8];
    int blk = blockIdx.x, a = blk / L, i = blk % L;
    int tid = threadIdx.x;
    int local = 0;
    for (int t = tid; t < NB * L * MW; t += 256) {
        unsigned w = g_M[t]; m[t] = w; local += __popc(w);
    }
    #pragma unroll
    for (int o = 16; o; o >>= 1) local += __shfl_xor_sync(0xffffffffu, local, o);
    if ((tid & 31) == 0) ired[tid >> 5] = local;
    __syncthreads();
    if (tid == 0) {
        int s = 0;
        #pragma unroll
        for (int w = 0; w < 8; w++) s += ired[w];
        sS = s;
    }
    __syncthreads();
    for (int ii = 0; ii < i; ii++) {
        if (sS == NB * L) break;
        if (tid == 0) sRem = 0;
        __syncthreads();
        int rem = 0;
        int nj = L - 1 - ii;
        int cnt = NB * nj * MW;
        for (int t = tid; t < cnt; t += 256) {
            int w = t % MW; int r = t / MW;
            int j = ii + 1 + (r % nj); int aa = r / nj;
            unsigned rw  = m[(aa * L + ii) * MW + w];
            unsigned old = m[(aa * L + j) * MW + w];
            unsigned drop = old & rw;
            if (drop) { m[(aa * L + j) * MW + w] = old & ~rw; rem += __popc(drop); }
        }
        #pragma unroll
        for (int o = 16; o; o >>= 1) rem += __shfl_xor_sync(0xffffffffu, rem, o);
        if ((tid & 31) == 0 && rem) atomicAdd(&sRem, rem);
        __syncthreads();
        if (tid == 0) sS -= sRem;
        __syncthreads();
    }
    const unsigned* mw = &m[(a * L + i) * MW];
    int num = 0;
    #pragma unroll
    for (int w = 0; w < MW; w++) num += __popc(mw[w]);
    float numc = (num > 0) ? (float)num : 1e-7f;
    bool has2 = tid < 129;
    int c1 = tid, c2 = tid + 256;
    float S1a = 0.f, S1b = 0.f;
    for (int w = 0; w < MW; w++) {
        unsigned bits = mw[w];
        while (bits) {
            int j = (w << 5) + __ffs((int)bits) - 1; bits &= bits - 1;
            const float* sp = g_sty + (size_t)(a * L + j) * STRH;
            S1a += sp[c1];
            if (has2) S1b += sp[c2];
        }
    }
    float avga = S1a / numc, avgb = S1b / numc;
    float S2a = 0.f, S2b = 0.f;
    for (int w = 0; w < MW; w++) {
        unsigned bits = mw[w];
        while (bits) {
            int j = (w << 5) + __ffs((int)bits) - 1; bits &= bits - 1;
            const float* sp = g_sty + (size_t)(a * L + j) * STRH;
            float xa = sp[c1] - avga; S2a += xa * xa;
            if (has2) { float xb = sp[c2] - avgb; S2b += xb * xb; }
        }
    }
    size_t off = (size_t)blk * STRH;
    float sta = sqrtf(S2a / numc);
    float ma = (S1a > 0.f) ? 1.f : 0.f;
    if (!(S1a > 0.f)) atomicAdd(&g_nzero, 1);
    g_B1[off + c1] = ma * sta; g_B2[off + c1] = ma * avga; g_B3[off + c1] = ma;
    if (has2) {
        float stb = sqrtf(S2b / numc);
        float mb = (S1b > 0.f) ? 1.f : 0.f;
        if (!(S1b > 0.f)) atomicAdd(&g_nzero, 1);
        g_B1[off + c2] = mb * stb; g_B2[off + c2] = mb * avgb; g_B3[off + c2] = mb;
    } else if (tid < 192) {
        g_B1[off + c2] = 0.f; g_B2[off + c2] = 0.f; g_B3[off + c2] = 0.f;
    }
}

// ============ Kernel D: triple GEMM -> g_S; fast path drops B3 ===============
__global__ void k_D(const float* __restrict__ ls, const float* __restrict__ noise) {
    __shared__ __align__(16) float SD[8192];
    __shared__ int s_nz;
    float (*A1s)[32] = (float(*)[32])SD;           // [2*16][32]
    float (*A2s)[32] = (float(*)[32])(SD + 1024);
    float (*B1s)[64] = (float(*)[64])(SD + 2048);  // [2*16][64]
    float (*B2s)[64] = (float(*)[64])(SD + 4096);
    float (*B3s)[64] = (float(*)[64])(SD + 6144);
    int tid = threadIdx.x;
    if (tid == 0) s_nz = g_nzero;
    int tx = tid & 15, ty = tid >> 4;
    int n0 = blockIdx.x * 64, m0 = blockIdx.y * 32;
    int a = blockIdx.z;
    u64 ac1[2][2], ac2[2][2], ac3[2][2];
    #pragma unroll
    for (int i = 0; i < 2; i++) {
        ac1[i][0] = ac1[i][1] = 0ULL;
        ac2[i][0] = ac2[i][1] = 0ULL;
        ac3[i][0] = ac3[i][1] = 0ULL;
    }
    int lm = tid >> 3, lk2 = (tid & 7) << 1;
    int bk = tid >> 4, bn4 = (tid & 15) << 2;
    const float* lsb = ls    + (size_t)a * L * L;
    const float* nsb = noise + (size_t)a * L * L;
    float4 z4 = make_float4(0.f, 0.f, 0.f, 0.f);
    float2 z2 = make_float2(0.f, 0.f);
    int ia = m0 + lm;
    bool iav = ia < L;
    float2 lvP = z2, nvP = z2;
    if (iav) {   // lk2 < 196 always for tile 0
        lvP = *reinterpret_cast<const float2*>(lsb + (size_t)ia * L + lk2);
        nvP = *reinterpret_cast<const float2*>(nsb + (size_t)ia * L + lk2);
    }
    float4 b1P, b2P, b3P = z4;
    {
        size_t o = (size_t)(a * L + bk) * STRH + n0 + bn4;
        b1P = *reinterpret_cast<const float4*>(&g_B1[o]);
        b2P = *reinterpret_cast<const float4*>(&g_B2[o]);
        b3P = *reinterpret_cast<const float4*>(&g_B3[o]);
    }
    int p = 0;
    A1s[lk2 + 0][lm] = lvP.x * nvP.x; A2s[lk2 + 0][lm] = lvP.x;
    A1s[lk2 + 1][lm] = lvP.y * nvP.y; A2s[lk2 + 1][lm] = lvP.y;
    *reinterpret_cast<float4*>(&B1s[bk][bn4]) = b1P;
    *reinterpret_cast<float4*>(&B2s[bk][bn4]) = b2P;
    *reinterpret_cast<float4*>(&B3s[bk][bn4]) = b3P;
    __syncthreads();
    bool fast = (s_nz == 0);
    for (int k0 = 0; k0 < 208; k0 += 16) {
        int kn = k0 + 16;
        if (kn < 208) {
            lvP = z2; nvP = z2;
            if (iav) {
                int ja = kn + lk2;
                if (ja + 1 < L) {
                    lvP = *reinterpret_cast<const float2*>(lsb + (size_t)ia * L + ja);
                    nvP = *reinterpret_cast<const float2*>(nsb + (size_t)ia * L + ja);
                } else if (ja < L) {
                    lvP.x = lsb[(size_t)ia * L + ja]; nvP.x = nsb[(size_t)ia * L + ja];
                }
            }
            int jb = kn + bk;
            b1P = z4; b2P = z4; b3P = z4;
            if (jb < L) {
                size_t o = (size_t)(a * L + jb) * STRH + n0 + bn4;
                b1P = *reinterpret_cast<const float4*>(&g_B1[o]);
                b2P = *reinterpret_cast<const float4*>(&g_B2[o]);
                if (!fast) b3P = *reinterpret_cast<const float4*>(&g_B3[o]);
            }
        }
        int pb = p * 16;
        if (fast) {
            #pragma unroll
            for (int kk = 0; kk < 16; kk++) {
                float2 a1 = *reinterpret_cast<float2*>(&A1s[pb + kk][ty << 1]);
                float2 a2 = *reinterpret_cast<float2*>(&A2s[pb + kk][ty << 1]);
                u64 b1a = *reinterpret_cast<u64*>(&B1s[pb + kk][tx << 2]);
                u64 b1b = *reinterpret_cast<u64*>(&B1s[pb + kk][(tx << 2) + 2]);
                u64 b2a = *reinterpret_cast<u64*>(&B2s[pb + kk][tx << 2]);
                u64 b2b = *reinterpret_cast<u64*>(&B2s[pb + kk][(tx << 2) + 2]);
                #pragma unroll
                for (int im = 0; im < 2; im++) {
                    float a1v = im ? a1.y : a1.x;
                    float a2v = im ? a2.y : a2.x;
                    u64 aa1 = pack2(a1v, a1v);
                    u64 aa2 = pack2(a2v, a2v);
                    fma2(ac1[im][0], aa1, b1a); fma2(ac1[im][1], aa1, b1b);
                    fma2(ac2[im][0], aa2, b2a); fma2(ac2[im][1], aa2, b2b);
                }
            }
        } else {
            #pragma unroll
            for (int kk = 0; kk < 16; kk++) {
                float2 a1 = *reinterpret_cast<float2*>(&A1s[pb + kk][ty << 1]);
                float2 a2 = *reinterpret_cast<float2*>(&A2s[pb + kk][ty << 1]);
                u64 b1a = *reinterpret_cast<u64*>(&B1s[pb + kk][tx << 2]);
                u64 b1b = *reinterpret_cast<u64*>(&B1s[pb + kk][(tx << 2) + 2]);
                u64 b2a = *reinterpret_cast<u64*>(&B2s[pb + kk][tx << 2]);
                u64 b2b = *reinterpret_cast<u64*>(&B2s[pb + kk][(tx << 2) + 2]);
                u64 b3a = *reinterpret_cast<u64*>(&B3s[pb + kk][tx << 2]);
                u64 b3b = *reinterpret_cast<u64*>(&B3s[pb + kk][(tx << 2) + 2]);
                #pragma unroll
                for (int im = 0; im < 2; im++) {
                    float a1v = im ? a1.y : a1.x;
                    float a2v = im ? a2.y : a2.x;
                    u64 aa1 = pack2(a1v, a1v);
                    u64 aa2 = pack2(a2v, a2v);
                    fma2(ac1[im][0], aa1, b1a); fma2(ac1[im][1], aa1, b1b);
                    fma2(ac2[im][0], aa2, b2a); fma2(ac2[im][1], aa2, b2b);
                    fma2(ac3[im][0], aa2, b3a); fma2(ac3[im][1], aa2, b3b);
                }
            }
        }
        if (kn < 208) {
            int qb = (1 - p) * 16;
            A1s[qb + lk2 + 0][lm] = lvP.x * nvP.x; A2s[qb + lk2 + 0][lm] = lvP.x;
            A1s[qb + lk2 + 1][lm] = lvP.y * nvP.y; A2s[qb + lk2 + 1][lm] = lvP.y;
            *reinterpret_cast<float4*>(&B1s[qb + bk][bn4]) = b1P;
            *reinterpret_cast<float4*>(&B2s[qb + bk][bn4]) = b2P;
            *reinterpret_cast<float4*>(&B3s[qb + bk][bn4]) = b3P;
            __syncthreads();
            p ^= 1;
        }
    }
    #pragma unroll
    for (int im = 0; im < 2; im++) {
        int i = m0 + (ty << 1) + im;
        if (i >= L) continue;
        int row = a * L + i;
        size_t ob = (size_t)row * STRH;
        int n = n0 + (tx << 2);
        float2 p1a = unpack2(ac1[im][0]), p1b = unpack2(ac1[im][1]);
        float2 p2a = unpack2(ac2[im][0]), p2b = unpack2(ac2[im][1]);
        float numv[4] = {p1a.x + p2a.x, p1a.y + p2a.y, p1b.x + p2b.x, p1b.y + p2b.y};
        float den[4];
        if (fast) {
            float rs = g_rsum[row];
            den[0] = den[1] = den[2] = den[3] = rs;
        } else {
            float2 p3a = unpack2(ac3[im][0]), p3b = unpack2(ac3[im][1]);
            den[0] = p3a.x; den[1] = p3a.y; den[2] = p3b.x; den[3] = p3b.y;
        }
        #pragma unroll
        for (int c = 0; c < 4; c++) {
            int col = n + c;
            if (col < 385)
                g_S[ob + col] = numv[c] / fmaxf(den[c], 1e-7f);
        }
    }
}

// ============ Kernel E: build Y (Hermitian) + inverse FFT + store ============
__global__ void k_E(float* __restrict__ out) {
    __shared__ __align__(16) float2 fa[768];
    __shared__ __align__(16) float2 fb[768];
    int blk = blockIdx.x, a = blk / L, i = blk % L;
    int tid = threadIdx.x;
    size_t bh = (size_t)blk * STRH;
    for (int c = tid; c <= 384; c += 256) {
        float s  = g_S[bh + c];
        float xr = g_Xr[bh + c], xi = g_Xi[bh + c];
        float m2 = xr * xr + xi * xi;
        float yr, yi;
        if (m2 > 0.f) { float r = s / sqrtf(m2); yr = xr * r; yi = xi * r; }
        else          { yr = s; yi = 0.f; }
        fa[c] = make_float2(yr, yi);
    }
    __syncthreads();
    for (int c = 385 + tid; c < 768; c += 256) {
        float2 y = fa[768 - c];
        fa[c] = make_float2(y.x, -y.y);
    }
    __syncthreads();
    float2* res = fft768(fa, fb, tid, 1.0f);
    float* op = out + ((size_t)(a * 197 + 1 + i)) * D;
    for (int d = tid; d < D; d += 256)
        op[d] = res[d].x * (1.f / 768.f);
}

// ---------------- launch ------------------------------------------------------
extern "C" void kernel_launch(void* const* d_in, const int* in_sizes, int n_in,
                              void* d_out, int out_size) {
    const float* x     = (const float*)d_in[0];
    const float* imgs  = (const float*)d_in[1];
    const float* ls    = (const float*)d_in[2];
    const float* noise = (const float*)d_in[3];
    float* out = (float*)d_out;

    k_A<<<A_GRID, 256>>>(imgs, x, out, ls);
    k_B<<<56, 256>>>();
    k_C<<<NLTOT, 256>>>();
    k_D<<<dim3(7, 7, NB), 256>>>(ls, noise);
    k_E<<<NLTOT, 256>>>(out);
}

// round 7
// speedup vs baseline: 2.8288x; 1.0209x over previous
#include <cuda_runtime.h>
#include <math.h>

#define NB 2
#define L 196
#define D 768
#define LD (L*D)
#define MW 7
#define NLTOT (NB*L)   // 392
#define STRH 448       // padded half-spectrum stride

// ---------------- scratch ---------------------------------------------------
__device__ float    g_V   [NB*LD];
__device__ float    g_Xr  [NLTOT*STRH];
__device__ float    g_Xi  [NLTOT*STRH];
__device__ float    g_sty [NLTOT*STRH];
__device__ float    g_Sn  [2][NLTOT*STRH];   // split-K numerator halves
__device__ float    g_Sd  [2][NLTOT*STRH];   // split-K denominator halves (slow path)
__device__ float    g_B1  [NLTOT*STRH];
__device__ float    g_B2  [NLTOT*STRH];
__device__ float    g_B3  [NLTOT*STRH];
__device__ float    g_rsum[NLTOT];
__device__ unsigned g_M   [NB*L*MW];
__device__ int      g_nzero;

// ---------------- f32x2 helpers ---------------------------------------------
typedef unsigned long long u64;
__device__ __forceinline__ void fma2(u64 &acc, u64 a, u64 b) {
    asm("fma.rn.f32x2 %0, %1, %2, %0;" : "+l"(acc) : "l"(a), "l"(b));
}
__device__ __forceinline__ u64 pack2(float x, float y) {
    u64 r; asm("mov.b64 %0, {%1, %2};" : "=l"(r) : "f"(x), "f"(y)); return r;
}
__device__ __forceinline__ float2 unpack2(u64 v) {
    float2 f; asm("mov.b64 {%0, %1}, %2;" : "=f"(f.x), "=f"(f.y) : "l"(v)); return f;
}

__device__ __forceinline__ float blockSum256(float v, float* red) {
    #pragma unroll
    for (int o = 16; o; o >>= 1) v += __shfl_xor_sync(0xffffffffu, v, o);
    if ((threadIdx.x & 31) == 0) red[threadIdx.x >> 5] = v;
    __syncthreads();
    if (threadIdx.x < 32) {
        float x = (threadIdx.x < 8) ? red[threadIdx.x] : 0.f;
        #pragma unroll
        for (int o = 4; o; o >>= 1) x += __shfl_xor_sync(0xffffffffu, x, o);
        if (threadIdx.x == 0) red[0] = x;
    }
    __syncthreads();
    float r = red[0];
    __syncthreads();
    return r;
}

// ---------------- Stockham FFT N=768 = 3*2^8, table-driven twiddles ----------
// tw[i] = cis(pi*i/384). sgn = -1 fwd, +1 inv (unscaled).
__device__ __forceinline__ float2* fft768t(float2* a, float2* b,
                                           const float2* tw, int tid, float sgn) {
    {
        const float c3 = 0.8660254037844386f * sgn;
        float2 x0 = a[tid], x1 = a[tid + 256], x2 = a[tid + 512];
        float2 s = make_float2(x1.x + x2.x, x1.y + x2.y);
        float2 d = make_float2(x1.x - x2.x, x1.y - x2.y);
        float mr = x0.x - 0.5f * s.x, mi = x0.y - 0.5f * s.y;
        b[3 * tid]     = make_float2(x0.x + s.x, x0.y + s.y);
        b[3 * tid + 1] = make_float2(mr - c3 * d.y, mi + c3 * d.x);
        b[3 * tid + 2] = make_float2(mr + c3 * d.y, mi - c3 * d.x);
    }
    __syncthreads();
    float2* src = b; float2* dst = a;
    #pragma unroll
    for (int st = 0; st < 8; st++) {
        const int l = 3 << st;
        const int sh = 128 >> st;
        #pragma unroll
        for (int rep = 0; rep < 2; rep++) {
            int j = tid + rep * 256;
            if (j < 384) {
                int k = j % l;
                float2 u = src[j], v = src[j + 384];
                float2 t = tw[k * sh];
                float cs = t.x, sn = sgn * t.y;
                float2 vw = make_float2(v.x * cs - v.y * sn, v.x * sn + v.y * cs);
                dst[2 * j - k]     = make_float2(u.x + vw.x, u.y + vw.y);
                dst[2 * j - k + l] = make_float2(u.x - vw.x, u.y - vw.y);
            }
        }
        __syncthreads();
        float2* t = src; src = dst; dst = t;
    }
    return src;
}

// ============ Kernel A1: patch(392) | rowsum(49) | misc(11) ==================
#define A1_PATCH 392
#define A1_RS    49
#define A1_MISC  11
#define A1_GRID  (A1_PATCH + A1_RS + A1_MISC)

__global__ void k_A1(const float* __restrict__ imgs, const float* __restrict__ x,
                     float* __restrict__ out, const float* __restrict__ ls) {
    __shared__ float red[8];
    __shared__ float buf[D];
    int b = blockIdx.x, tid = threadIdx.x;
    if (b < A1_PATCH) {
        int blk = b, a = blk / L, l = blk % L;
        int hh = l / 14, ww = l % 14;
        int p = tid >> 4, q = tid & 15;
        const float* base = imgs + ((size_t)a * 3 * 224 + (size_t)(hh * 16 + p)) * 224
                                 + (ww * 16 + q);
        float v[3];
        #pragma unroll
        for (int c = 0; c < 3; c++) v[c] = base[(size_t)c * 224 * 224];
        float mean = blockSum256(v[0] + v[1] + v[2], red) * (1.f / 768.f);
        float u[3]; float ss = 0.f;
        #pragma unroll
        for (int c = 0; c < 3; c++) { u[c] = v[c] - mean; ss += u[c] * u[c]; }
        float tot = blockSum256(ss, red);
        float inv = 1.f / sqrtf(tot);
        #pragma unroll
        for (int c = 0; c < 3; c++) buf[tid * 3 + c] = u[c] * inv;
        __syncthreads();
        if (tid < 192)
            reinterpret_cast<float4*>(g_V + (size_t)blk * D)[tid] =
                reinterpret_cast<float4*>(buf)[tid];
        return;
    }
    b -= A1_PATCH;
    if (b < A1_RS) {
        int w = tid >> 5, lane = tid & 31;
        int row = b * 8 + w;
        if (row < NLTOT) {
            int a = row / L, i = row % L;
            const float* lp = ls + ((size_t)a * L + i) * L;
            float s = 0.f;
            for (int j = lane; j < L; j += 32) s += lp[j];
            #pragma unroll
            for (int o = 16; o; o >>= 1) s += __shfl_xor_sync(0xffffffffu, s, o);
            if (lane == 0) g_rsum[row] = s;
        }
        return;
    }
    b -= A1_RS;
    {
        int t = b * 256 + tid;
        if (t < NB * L * MW) g_M[t] = 0u;
        if (t < NB * D) {
            int a = t / D, d = t % D;
            out[(size_t)a * 197 * D + d] = x[(size_t)a * 197 * D + d];
        }
        if (t == 0) g_nzero = 0;
    }
}

// ============ Kernel A2: fwd FFT(392) | sim(56) — one wave ===================
__global__ void k_A2(const float* __restrict__ x) {
    __shared__ __align__(16) float S[4352];
    int b = blockIdx.x, tid = threadIdx.x;
    if (b < NLTOT) {
        // ---- forward FFT ----
        float2* fa = (float2*)S;
        float2* fb = fa + 768;
        float2* tw = fa + 1536;
        for (int i = tid; i < 384; i += 256) {
            float s, c; sincospif((float)i * (1.f / 384.f), &s, &c);
            tw[i] = make_float2(c, s);
        }
        int row = b, a = row / L, i = row % L;
        const float* xp = x + ((size_t)(a * 197 + 1 + i)) * D;
        for (int d = tid; d < D; d += 256) fa[d] = make_float2(xp[d], 0.f);
        __syncthreads();
        float2* res = fft768t(fa, fb, tw, tid, -1.0f);
        size_t bh = (size_t)row * STRH;
        for (int k = tid; k <= 384; k += 256) {
            float2 X = res[k];
            g_Xr[bh + k] = X.x; g_Xi[bh + k] = X.y;
            g_sty[bh + k] = sqrtf(X.x * X.x + X.y * X.y);
        }
        return;
    }
    {
        // ---- sim: 32x32 upper-tri tile, double-buffered ----
        int bb = b - NLTOT;
        int a = bb / 28;
        int t = bb % 28, bi = 0;
        while (t >= 7 - bi) { t -= 7 - bi; bi++; }
        int bj = bi + t;
        int i0 = bi * 32, j0 = bj * 32;
        float (*As)[34] = (float(*)[34])S;
        float (*Bs)[34] = (float(*)[34])(S + 2176);
        int tx = tid & 15, ty = tid >> 4;
        int m = tid >> 3, k4 = (tid & 7) << 2;
        const float* Vb = g_V + (size_t)a * LD;
        const float* Arow = (i0 + m < L) ? Vb + (size_t)(i0 + m) * D : nullptr;
        const float* Brow = (j0 + m < L) ? Vb + (size_t)(j0 + m) * D : nullptr;
        float4 z4 = make_float4(0.f, 0.f, 0.f, 0.f);
        float4 avP = Arow ? *reinterpret_cast<const float4*>(Arow + k4) : z4;
        float4 bvP = Brow ? *reinterpret_cast<const float4*>(Brow + k4) : z4;
        u64 acc[2] = {0ULL, 0ULL};
        int p = 0;
        As[k4 + 0][m] = avP.x; As[k4 + 1][m] = avP.y;
        As[k4 + 2][m] = avP.z; As[k4 + 3][m] = avP.w;
        Bs[k4 + 0][m] = bvP.x; Bs[k4 + 1][m] = bvP.y;
        Bs[k4 + 2][m] = bvP.z; Bs[k4 + 3][m] = bvP.w;
        __syncthreads();
        for (int k0 = 0; k0 < D; k0 += 32) {
            int kn = k0 + 32;
            if (kn < D) {
                avP = Arow ? *reinterpret_cast<const float4*>(Arow + kn + k4) : z4;
                bvP = Brow ? *reinterpret_cast<const float4*>(Brow + kn + k4) : z4;
            }
            int pb = p * 32;
            #pragma unroll
            for (int kk = 0; kk < 32; kk++) {
                float2 a2 = *reinterpret_cast<float2*>(&As[pb + kk][ty << 1]);
                u64 bbv = *reinterpret_cast<u64*>(&Bs[pb + kk][tx << 1]);
                fma2(acc[0], pack2(a2.x, a2.x), bbv);
                fma2(acc[1], pack2(a2.y, a2.y), bbv);
            }
            if (kn < D) {
                int qb = (1 - p) * 32;
                As[qb + k4 + 0][m] = avP.x; As[qb + k4 + 1][m] = avP.y;
                As[qb + k4 + 2][m] = avP.z; As[qb + k4 + 3][m] = avP.w;
                Bs[qb + k4 + 0][m] = bvP.x; Bs[qb + k4 + 1][m] = bvP.y;
                Bs[qb + k4 + 2][m] = bvP.z; Bs[qb + k4 + 3][m] = bvP.w;
                __syncthreads();
                p ^= 1;
            }
        }
        #pragma unroll
        for (int r = 0; r < 2; r++) {
            int i = i0 + (ty << 1) + r;
            if (i >= L) continue;
            float2 c = unpack2(acc[r]);
            int j = j0 + (tx << 1);
            if (j < L && j >= i && c.x > 0.3f)
                atomicOr(&g_M[(a * L + i) * MW + (j >> 5)], 1u << (j & 31));
            j++;
            if (j < L && j >= i && c.y > 0.3f)
                atomicOr(&g_M[(a * L + i) * MW + (j >> 5)], 1u << (j & 31));
        }
    }
}

// ============ Kernel C: per-row prop replay + stats + nzero ==================
__global__ void k_C() {
    __shared__ unsigned m[NB * L * MW];
    __shared__ int sS, sRem, ired[8];
    int blk = blockIdx.x, a = blk / L, i = blk % L;
    int tid = threadIdx.x;
    int local = 0;
    for (int t = tid; t < NB * L * MW; t += 256) {
        unsigned w = g_M[t]; m[t] = w; local += __popc(w);
    }
    #pragma unroll
    for (int o = 16; o; o >>= 1) local += __shfl_xor_sync(0xffffffffu, local, o);
    if ((tid & 31) == 0) ired[tid >> 5] = local;
    __syncthreads();
    if (tid == 0) {
        int s = 0;
        #pragma unroll
        for (int w = 0; w < 8; w++) s += ired[w];
        sS = s;
    }
    __syncthreads();
    for (int ii = 0; ii < i; ii++) {
        if (sS == NB * L) break;
        if (tid == 0) sRem = 0;
        __syncthreads();
        int rem = 0;
        int nj = L - 1 - ii;
        int cnt = NB * nj * MW;
        for (int t = tid; t < cnt; t += 256) {
            int w = t % MW; int r = t / MW;
            int j = ii + 1 + (r % nj); int aa = r / nj;
            unsigned rw  = m[(aa * L + ii) * MW + w];
            unsigned old = m[(aa * L + j) * MW + w];
            unsigned drop = old & rw;
            if (drop) { m[(aa * L + j) * MW + w] = old & ~rw; rem += __popc(drop); }
        }
        #pragma unroll
        for (int o = 16; o; o >>= 1) rem += __shfl_xor_sync(0xffffffffu, rem, o);
        if ((tid & 31) == 0 && rem) atomicAdd(&sRem, rem);
        __syncthreads();
        if (tid == 0) sS -= sRem;
        __syncthreads();
    }
    const unsigned* mw = &m[(a * L + i) * MW];
    int num = 0;
    #pragma unroll
    for (int w = 0; w < MW; w++) num += __popc(mw[w]);
    float numc = (num > 0) ? (float)num : 1e-7f;
    bool has2 = tid < 129;
    int c1 = tid, c2 = tid + 256;
    float S1a = 0.f, S1b = 0.f;
    for (int w = 0; w < MW; w++) {
        unsigned bits = mw[w];
        while (bits) {
            int j = (w << 5) + __ffs((int)bits) - 1; bits &= bits - 1;
            const float* sp = g_sty + (size_t)(a * L + j) * STRH;
            S1a += sp[c1];
            if (has2) S1b += sp[c2];
        }
    }
    float avga = S1a / numc, avgb = S1b / numc;
    float S2a = 0.f, S2b = 0.f;
    for (int w = 0; w < MW; w++) {
        unsigned bits = mw[w];
        while (bits) {
            int j = (w << 5) + __ffs((int)bits) - 1; bits &= bits - 1;
            const float* sp = g_sty + (size_t)(a * L + j) * STRH;
            float xa = sp[c1] - avga; S2a += xa * xa;
            if (has2) { float xb = sp[c2] - avgb; S2b += xb * xb; }
        }
    }
    size_t off = (size_t)blk * STRH;
    float sta = sqrtf(S2a / numc);
    float ma = (S1a > 0.f) ? 1.f : 0.f;
    if (!(S1a > 0.f)) atomicAdd(&g_nzero, 1);
    g_B1[off + c1] = ma * sta; g_B2[off + c1] = ma * avga; g_B3[off + c1] = ma;
    if (has2) {
        float stb = sqrtf(S2b / numc);
        float mb = (S1b > 0.f) ? 1.f : 0.f;
        if (!(S1b > 0.f)) atomicAdd(&g_nzero, 1);
        g_B1[off + c2] = mb * stb; g_B2[off + c2] = mb * avgb; g_B3[off + c2] = mb;
    } else if (tid < 192) {
        g_B1[off + c2] = 0.f; g_B2[off + c2] = 0.f; g_B3[off + c2] = 0.f;
    }
}

// ============ Kernel D: split-K triple GEMM -> g_Sn/g_Sd halves ==============
__global__ void k_D(const float* __restrict__ ls, const float* __restrict__ noise) {
    __shared__ __align__(16) float SD[8192];
    __shared__ int s_nz;
    float (*A1s)[32] = (float(*)[32])SD;
    float (*A2s)[32] = (float(*)[32])(SD + 1024);
    float (*B1s)[64] = (float(*)[64])(SD + 2048);
    float (*B2s)[64] = (float(*)[64])(SD + 4096);
    float (*B3s)[64] = (float(*)[64])(SD + 6144);
    int tid = threadIdx.x;
    if (tid == 0) s_nz = g_nzero;
    int tx = tid & 15, ty = tid >> 4;
    int n0 = blockIdx.x * 64, m0 = blockIdx.y * 32;
    int a = blockIdx.z >> 1, half = blockIdx.z & 1;
    int kbeg = half ? 112 : 0;
    int kend = half ? 208 : 112;
    u64 ac1[2][2], ac2[2][2], ac3[2][2];
    #pragma unroll
    for (int i = 0; i < 2; i++) {
        ac1[i][0] = ac1[i][1] = 0ULL;
        ac2[i][0] = ac2[i][1] = 0ULL;
        ac3[i][0] = ac3[i][1] = 0ULL;
    }
    int lm = tid >> 3, lk2 = (tid & 7) << 1;
    int bk = tid >> 4, bn4 = (tid & 15) << 2;
    const float* lsb = ls    + (size_t)a * L * L;
    const float* nsb = noise + (size_t)a * L * L;
    float4 z4 = make_float4(0.f, 0.f, 0.f, 0.f);
    float2 z2 = make_float2(0.f, 0.f);
    int ia = m0 + lm;
    bool iav = ia < L;
    float2 lvP = z2, nvP = z2;
    if (iav) {
        int ja = kbeg + lk2;   // <= 127 < 196
        lvP = *reinterpret_cast<const float2*>(lsb + (size_t)ia * L + ja);
        nvP = *reinterpret_cast<const float2*>(nsb + (size_t)ia * L + ja);
    }
    float4 b1P, b2P, b3P = z4;
    {
        size_t o = (size_t)(a * L + kbeg + bk) * STRH + n0 + bn4;
        b1P = *reinterpret_cast<const float4*>(&g_B1[o]);
        b2P = *reinterpret_cast<const float4*>(&g_B2[o]);
        b3P = *reinterpret_cast<const float4*>(&g_B3[o]);
    }
    int p = 0;
    A1s[lk2 + 0][lm] = lvP.x * nvP.x; A2s[lk2 + 0][lm] = lvP.x;
    A1s[lk2 + 1][lm] = lvP.y * nvP.y; A2s[lk2 + 1][lm] = lvP.y;
    *reinterpret_cast<float4*>(&B1s[bk][bn4]) = b1P;
    *reinterpret_cast<float4*>(&B2s[bk][bn4]) = b2P;
    *reinterpret_cast<float4*>(&B3s[bk][bn4]) = b3P;
    __syncthreads();
    bool fast = (s_nz == 0);
    for (int k0 = kbeg; k0 < kend; k0 += 16) {
        int kn = k0 + 16;
        if (kn < kend) {
            lvP = z2; nvP = z2;
            if (iav) {
                int ja = kn + lk2;
                if (ja + 1 < L) {
                    lvP = *reinterpret_cast<const float2*>(lsb + (size_t)ia * L + ja);
                    nvP = *reinterpret_cast<const float2*>(nsb + (size_t)ia * L + ja);
                } else if (ja < L) {
                    lvP.x = lsb[(size_t)ia * L + ja]; nvP.x = nsb[(size_t)ia * L + ja];
                }
            }
            int jb = kn + bk;
            b1P = z4; b2P = z4; b3P = z4;
            if (jb < L) {
                size_t o = (size_t)(a * L + jb) * STRH + n0 + bn4;
                b1P = *reinterpret_cast<const float4*>(&g_B1[o]);
                b2P = *reinterpret_cast<const float4*>(&g_B2[o]);
                if (!fast) b3P = *reinterpret_cast<const float4*>(&g_B3[o]);
            }
        }
        int pb = p * 16;
        if (fast) {
            #pragma unroll
            for (int kk = 0; kk < 16; kk++) {
                float2 a1 = *reinterpret_cast<float2*>(&A1s[pb + kk][ty << 1]);
                float2 a2 = *reinterpret_cast<float2*>(&A2s[pb + kk][ty << 1]);
                u64 b1a = *reinterpret_cast<u64*>(&B1s[pb + kk][tx << 2]);
                u64 b1b = *reinterpret_cast<u64*>(&B1s[pb + kk][(tx << 2) + 2]);
                u64 b2a = *reinterpret_cast<u64*>(&B2s[pb + kk][tx << 2]);
                u64 b2b = *reinterpret_cast<u64*>(&B2s[pb + kk][(tx << 2) + 2]);
                #pragma unroll
                for (int im = 0; im < 2; im++) {
                    float a1v = im ? a1.y : a1.x;
                    float a2v = im ? a2.y : a2.x;
                    u64 aa1 = pack2(a1v, a1v);
                    u64 aa2 = pack2(a2v, a2v);
                    fma2(ac1[im][0], aa1, b1a); fma2(ac1[im][1], aa1, b1b);
                    fma2(ac2[im][0], aa2, b2a); fma2(ac2[im][1], aa2, b2b);
                }
            }
        } else {
            #pragma unroll
            for (int kk = 0; kk < 16; kk++) {
                float2 a1 = *reinterpret_cast<float2*>(&A1s[pb + kk][ty << 1]);
                float2 a2 = *reinterpret_cast<float2*>(&A2s[pb + kk][ty << 1]);
                u64 b1a = *reinterpret_cast<u64*>(&B1s[pb + kk][tx << 2]);
                u64 b1b = *reinterpret_cast<u64*>(&B1s[pb + kk][(tx << 2) + 2]);
                u64 b2a = *reinterpret_cast<u64*>(&B2s[pb + kk][tx << 2]);
                u64 b2b = *reinterpret_cast<u64*>(&B2s[pb + kk][(tx << 2) + 2]);
                u64 b3a = *reinterpret_cast<u64*>(&B3s[pb + kk][tx << 2]);
                u64 b3b = *reinterpret_cast<u64*>(&B3s[pb + kk][(tx << 2) + 2]);
                #pragma unroll
                for (int im = 0; im < 2; im++) {
                    float a1v = im ? a1.y : a1.x;
                    float a2v = im ? a2.y : a2.x;
                    u64 aa1 = pack2(a1v, a1v);
                    u64 aa2 = pack2(a2v, a2v);
                    fma2(ac1[im][0], aa1, b1a); fma2(ac1[im][1], aa1, b1b);
                    fma2(ac2[im][0], aa2, b2a); fma2(ac2[im][1], aa2, b2b);
                    fma2(ac3[im][0], aa2, b3a); fma2(ac3[im][1], aa2, b3b);
                }
            }
        }
        if (kn < kend) {
            int qb = (1 - p) * 16;
            A1s[qb + lk2 + 0][lm] = lvP.x * nvP.x; A2s[qb + lk2 + 0][lm] = lvP.x;
            A1s[qb + lk2 + 1][lm] = lvP.y * nvP.y; A2s[qb + lk2 + 1][lm] = lvP.y;
            *reinterpret_cast<float4*>(&B1s[qb + bk][bn4]) = b1P;
            *reinterpret_cast<float4*>(&B2s[qb + bk][bn4]) = b2P;
            *reinterpret_cast<float4*>(&B3s[qb + bk][bn4]) = b3P;
            __syncthreads();
            p ^= 1;
        }
    }
    #pragma unroll
    for (int im = 0; im < 2; im++) {
        int i = m0 + (ty << 1) + im;
        if (i >= L) continue;
        int row = a * L + i;
        size_t ob = (size_t)row * STRH + n0 + (tx << 2);
        float2 p1a = unpack2(ac1[im][0]), p1b = unpack2(ac1[im][1]);
        float2 p2a = unpack2(ac2[im][0]), p2b = unpack2(ac2[im][1]);
        float4 numv = make_float4(p1a.x + p2a.x, p1a.y + p2a.y,
                                  p1b.x + p2b.x, p1b.y + p2b.y);
        *reinterpret_cast<float4*>(&g_Sn[half][ob]) = numv;
        if (!fast) {
            float2 p3a = unpack2(ac3[im][0]), p3b = unpack2(ac3[im][1]);
            float4 denv = make_float4(p3a.x, p3a.y, p3b.x, p3b.y);
            *reinterpret_cast<float4*>(&g_Sd[half][ob]) = denv;
        }
    }
}

// ============ Kernel E: combine halves + divide + Y + inverse FFT ============
__global__ void k_E(float* __restrict__ out) {
    __shared__ __align__(16) float S[4352];
    float2* fa = (float2*)S;
    float2* fb = fa + 768;
    float2* tw = fa + 1536;
    int blk = blockIdx.x, a = blk / L, i = blk % L;
    int tid = threadIdx.x;
    for (int t = tid; t < 384; t += 256) {
        float s, c; sincospif((float)t * (1.f / 384.f), &s, &c);
        tw[t] = make_float2(c, s);
    }
    size_t bh = (size_t)blk * STRH;
    bool fast = (g_nzero == 0);
    float rs = fmaxf(g_rsum[blk], 1e-7f);
    for (int c = tid; c <= 384; c += 256) {
        float numv = g_Sn[0][bh + c] + g_Sn[1][bh + c];
        float den = fast ? rs : fmaxf(g_Sd[0][bh + c] + g_Sd[1][bh + c], 1e-7f);
        float s = numv / den;
        float xr = g_Xr[bh + c], xi = g_Xi[bh + c];
        float m2 = xr * xr + xi * xi;
        float yr, yi;
        if (m2 > 0.f) { float r = s / sqrtf(m2); yr = xr * r; yi = xi * r; }
        else          { yr = s; yi = 0.f; }
        fa[c] = make_float2(yr, yi);
    }
    __syncthreads();
    for (int c = 385 + tid; c < 768; c += 256) {
        float2 y = fa[768 - c];
        fa[c] = make_float2(y.x, -y.y);
    }
    __syncthreads();
    float2* res = fft768t(fa, fb, tw, tid, 1.0f);
    float* op = out + ((size_t)(a * 197 + 1 + i)) * D;
    for (int d = tid; d < D; d += 256)
        op[d] = res[d].x * (1.f / 768.f);
}

// ---------------- launch ------------------------------------------------------
extern "C" void kernel_launch(void* const* d_in, const int* in_sizes, int n_in,
                              void* d_out, int out_size) {
    const float* x     = (const float*)d_in[0];
    const float* imgs  = (const float*)d_in[1];
    const float* ls    = (const float*)d_in[2];
    const float* noise = (const float*)d_in[3];
    float* out = (float*)d_out;

    k_A1<<<A1_GRID, 256>>>(imgs, x, out, ls);
    k_A2<<<NLTOT + 56, 256>>>(x);
    k_C<<<NLTOT, 256>>>();
    k_D<<<dim3(7, 7, NB * 2), 256>>>(ls, noise);
    k_E<<<NLTOT, 256>>>(out);
}

// round 8
// speedup vs baseline: 2.9786x; 1.0529x over previous
#include <cuda_runtime.h>
#include <math.h>

#define NB 2
#define L 196
#define D 768
#define LD (L*D)
#define MW 7
#define NLTOT (NB*L)   // 392
#define STRH 448       // padded half-spectrum stride

// ---------------- scratch ---------------------------------------------------
__device__ float    g_V   [NB*LD];
__device__ float    g_Xr  [NLTOT*STRH];
__device__ float    g_Xi  [NLTOT*STRH];
__device__ float    g_sty [NLTOT*STRH];
__device__ float    g_Sn  [4][NLTOT*STRH];   // split-K numerator quarters
__device__ float    g_Sd  [4][NLTOT*STRH];   // split-K denominator quarters (slow path)
__device__ float    g_B1  [NLTOT*STRH];
__device__ float    g_B2  [NLTOT*STRH];
__device__ float    g_B3  [NLTOT*STRH];
__device__ float    g_rsum[NLTOT];
__device__ unsigned g_M   [NB*L*MW];
__device__ int      g_nzero;

// ---------------- f32x2 helpers ---------------------------------------------
typedef unsigned long long u64;
__device__ __forceinline__ void fma2(u64 &acc, u64 a, u64 b) {
    asm("fma.rn.f32x2 %0, %1, %2, %0;" : "+l"(acc) : "l"(a), "l"(b));
}
__device__ __forceinline__ u64 pack2(float x, float y) {
    u64 r; asm("mov.b64 %0, {%1, %2};" : "=l"(r) : "f"(x), "f"(y)); return r;
}
__device__ __forceinline__ float2 unpack2(u64 v) {
    float2 f; asm("mov.b64 {%0, %1}, %2;" : "=f"(f.x), "=f"(f.y) : "l"(v)); return f;
}

__device__ __forceinline__ float blockSum256(float v, float* red) {
    #pragma unroll
    for (int o = 16; o; o >>= 1) v += __shfl_xor_sync(0xffffffffu, v, o);
    if ((threadIdx.x & 31) == 0) red[threadIdx.x >> 5] = v;
    __syncthreads();
    if (threadIdx.x < 32) {
        float x = (threadIdx.x < 8) ? red[threadIdx.x] : 0.f;
        #pragma unroll
        for (int o = 4; o; o >>= 1) x += __shfl_xor_sync(0xffffffffu, x, o);
        if (threadIdx.x == 0) red[0] = x;
    }
    __syncthreads();
    float r = red[0];
    __syncthreads();
    return r;
}

// ---------------- Stockham FFT N=768 = 3*4^4, table twiddles -----------------
// tw[i] = cis(pi*i/384), i in [0,576). sgn = -1 fwd, +1 inv (unscaled).
__device__ __forceinline__ float2* fft768r4(float2* a, float2* b,
                                            const float2* tw, int tid, float sgn) {
    {   // radix-3 stage, l: 1 -> 3
        const float c3 = 0.8660254037844386f * sgn;
        float2 x0 = a[tid], x1 = a[tid + 256], x2 = a[tid + 512];
        float2 s = make_float2(x1.x + x2.x, x1.y + x2.y);
        float2 d = make_float2(x1.x - x2.x, x1.y - x2.y);
        float mr = x0.x - 0.5f * s.x, mi = x0.y - 0.5f * s.y;
        b[3 * tid]     = make_float2(x0.x + s.x, x0.y + s.y);
        b[3 * tid + 1] = make_float2(mr - c3 * d.y, mi + c3 * d.x);
        b[3 * tid + 2] = make_float2(mr + c3 * d.y, mi - c3 * d.x);
    }
    __syncthreads();
    float2* src = b; float2* dst = a;
    #pragma unroll
    for (int st = 0; st < 4; st++) {            // radix-4: l = 3,12,48,192
        const int l = 3 << (2 * st);
        const int step = 64 >> (2 * st);        // 192/l
        if (tid < 192) {
            int j = tid;
            int k = j % l;
            int idx = k * step;
            float2 v0 = src[j], v1 = src[j + 192], v2 = src[j + 384], v3 = src[j + 576];
            float2 w1 = tw[idx], w2 = tw[2 * idx], w3 = tw[3 * idx];
            float s1 = sgn * w1.y, s2 = sgn * w2.y, s3 = sgn * w3.y;
            float2 t1 = make_float2(v1.x * w1.x - v1.y * s1, v1.x * s1 + v1.y * w1.x);
            float2 t2 = make_float2(v2.x * w2.x - v2.y * s2, v2.x * s2 + v2.y * w2.x);
            float2 t3 = make_float2(v3.x * w3.x - v3.y * s3, v3.x * s3 + v3.y * w3.x);
            float2 e0 = make_float2(v0.x + t2.x, v0.y + t2.y);
            float2 e1 = make_float2(v0.x - t2.x, v0.y - t2.y);
            float2 o0 = make_float2(t1.x + t3.x, t1.y + t3.y);
            float2 o1 = make_float2(t1.x - t3.x, t1.y - t3.y);
            float2 io = make_float2(-sgn * o1.y, sgn * o1.x);
            int ob = 4 * j - 3 * k;
            dst[ob]         = make_float2(e0.x + o0.x, e0.y + o0.y);
            dst[ob + l]     = make_float2(e1.x + io.x, e1.y + io.y);
            dst[ob + 2 * l] = make_float2(e0.x - o0.x, e0.y - o0.y);
            dst[ob + 3 * l] = make_float2(e1.x - io.x, e1.y - io.y);
        }
        __syncthreads();
        float2* t = src; src = dst; dst = t;
    }
    return src;
}

// ============ Kernel A1: patch(392) | rowsum(49) | misc(11) ==================
#define A1_PATCH 392
#define A1_RS    49
#define A1_MISC  11
#define A1_GRID  (A1_PATCH + A1_RS + A1_MISC)

__global__ void k_A1(const float* __restrict__ imgs, const float* __restrict__ x,
                     float* __restrict__ out, const float* __restrict__ ls) {
    __shared__ float red[8];
    __shared__ float buf[D];
    int b = blockIdx.x, tid = threadIdx.x;
    if (b < A1_PATCH) {
        int blk = b, a = blk / L, l = blk % L;
        int hh = l / 14, ww = l % 14;
        int p = tid >> 4, q = tid & 15;
        const float* base = imgs + ((size_t)a * 3 * 224 + (size_t)(hh * 16 + p)) * 224
                                 + (ww * 16 + q);
        float v[3];
        #pragma unroll
        for (int c = 0; c < 3; c++) v[c] = base[(size_t)c * 224 * 224];
        float mean = blockSum256(v[0] + v[1] + v[2], red) * (1.f / 768.f);
        float u[3]; float ss = 0.f;
        #pragma unroll
        for (int c = 0; c < 3; c++) { u[c] = v[c] - mean; ss += u[c] * u[c]; }
        float tot = blockSum256(ss, red);
        float inv = 1.f / sqrtf(tot);
        #pragma unroll
        for (int c = 0; c < 3; c++) buf[tid * 3 + c] = u[c] * inv;
        __syncthreads();
        if (tid < 192)
            reinterpret_cast<float4*>(g_V + (size_t)blk * D)[tid] =
                reinterpret_cast<float4*>(buf)[tid];
        return;
    }
    b -= A1_PATCH;
    if (b < A1_RS) {
        int w = tid >> 5, lane = tid & 31;
        int row = b * 8 + w;
        if (row < NLTOT) {
            int a = row / L, i = row % L;
            const float* lp = ls + ((size_t)a * L + i) * L;
            float s = 0.f;
            for (int j = lane; j < L; j += 32) s += lp[j];
            #pragma unroll
            for (int o = 16; o; o >>= 1) s += __shfl_xor_sync(0xffffffffu, s, o);
            if (lane == 0) g_rsum[row] = s;
        }
        return;
    }
    b -= A1_RS;
    {
        int t = b * 256 + tid;
        if (t < NB * L * MW) g_M[t] = 0u;
        if (t < NB * D) {
            int a = t / D, d = t % D;
            out[(size_t)a * 197 * D + d] = x[(size_t)a * 197 * D + d];
        }
        if (t == 0) g_nzero = 0;
    }
}

// ============ Kernel A2: fwd FFT(392) | sim(56) — one wave ===================
__global__ void k_A2(const float* __restrict__ x) {
    __shared__ __align__(16) float S[4400];
    int b = blockIdx.x, tid = threadIdx.x;
    if (b < NLTOT) {
        // ---- forward FFT ----
        float2* fa = (float2*)S;
        float2* fb = fa + 768;
        float2* tw = fa + 1536;
        for (int i = tid; i < 576; i += 256) {
            float s, c; sincospif((float)i * (1.f / 384.f), &s, &c);
            tw[i] = make_float2(c, s);
        }
        int row = b, a = row / L, i = row % L;
        const float* xp = x + ((size_t)(a * 197 + 1 + i)) * D;
        for (int d = tid; d < D; d += 256) fa[d] = make_float2(xp[d], 0.f);
        __syncthreads();
        float2* res = fft768r4(fa, fb, tw, tid, -1.0f);
        size_t bh = (size_t)row * STRH;
        for (int k = tid; k <= 384; k += 256) {
            float2 X = res[k];
            g_Xr[bh + k] = X.x; g_Xi[bh + k] = X.y;
            g_sty[bh + k] = sqrtf(X.x * X.x + X.y * X.y);
        }
        return;
    }
    {
        // ---- sim: 32x32 upper-tri tile, double-buffered ----
        int bb = b - NLTOT;
        int a = bb / 28;
        int t = bb % 28, bi = 0;
        while (t >= 7 - bi) { t -= 7 - bi; bi++; }
        int bj = bi + t;
        int i0 = bi * 32, j0 = bj * 32;
        float (*As)[34] = (float(*)[34])S;
        float (*Bs)[34] = (float(*)[34])(S + 2176);
        int tx = tid & 15, ty = tid >> 4;
        int m = tid >> 3, k4 = (tid & 7) << 2;
        const float* Vb = g_V + (size_t)a * LD;
        const float* Arow = (i0 + m < L) ? Vb + (size_t)(i0 + m) * D : nullptr;
        const float* Brow = (j0 + m < L) ? Vb + (size_t)(j0 + m) * D : nullptr;
        float4 z4 = make_float4(0.f, 0.f, 0.f, 0.f);
        float4 avP = Arow ? *reinterpret_cast<const float4*>(Arow + k4) : z4;
        float4 bvP = Brow ? *reinterpret_cast<const float4*>(Brow + k4) : z4;
        u64 acc[2] = {0ULL, 0ULL};
        int p = 0;
        As[k4 + 0][m] = avP.x; As[k4 + 1][m] = avP.y;
        As[k4 + 2][m] = avP.z; As[k4 + 3][m] = avP.w;
        Bs[k4 + 0][m] = bvP.x; Bs[k4 + 1][m] = bvP.y;
        Bs[k4 + 2][m] = bvP.z; Bs[k4 + 3][m] = bvP.w;
        __syncthreads();
        for (int k0 = 0; k0 < D; k0 += 32) {
            int kn = k0 + 32;
            if (kn < D) {
                avP = Arow ? *reinterpret_cast<const float4*>(Arow + kn + k4) : z4;
                bvP = Brow ? *reinterpret_cast<const float4*>(Brow + kn + k4) : z4;
            }
            int pb = p * 32;
            #pragma unroll
            for (int kk = 0; kk < 32; kk++) {
                float2 a2 = *reinterpret_cast<float2*>(&As[pb + kk][ty << 1]);
                u64 bbv = *reinterpret_cast<u64*>(&Bs[pb + kk][tx << 1]);
                fma2(acc[0], pack2(a2.x, a2.x), bbv);
                fma2(acc[1], pack2(a2.y, a2.y), bbv);
            }
            if (kn < D) {
                int qb = (1 - p) * 32;
                As[qb + k4 + 0][m] = avP.x; As[qb + k4 + 1][m] = avP.y;
                As[qb + k4 + 2][m] = avP.z; As[qb + k4 + 3][m] = avP.w;
                Bs[qb + k4 + 0][m] = bvP.x; Bs[qb + k4 + 1][m] = bvP.y;
                Bs[qb + k4 + 2][m] = bvP.z; Bs[qb + k4 + 3][m] = bvP.w;
                __syncthreads();
                p ^= 1;
            }
        }
        #pragma unroll
        for (int r = 0; r < 2; r++) {
            int i = i0 + (ty << 1) + r;
            if (i >= L) continue;
            float2 c = unpack2(acc[r]);
            int j = j0 + (tx << 1);
            if (j < L && j >= i && c.x > 0.3f)
                atomicOr(&g_M[(a * L + i) * MW + (j >> 5)], 1u << (j & 31));
            j++;
            if (j < L && j >= i && c.y > 0.3f)
                atomicOr(&g_M[(a * L + i) * MW + (j >> 5)], 1u << (j & 31));
        }
    }
}

// ============ Kernel C: per-row prop replay + stats + nzero ==================
__global__ void k_C() {
    __shared__ unsigned m[NB * L * MW];
    __shared__ int sS, sRem, ired[8];
    int blk = blockIdx.x, a = blk / L, i = blk % L;
    int tid = threadIdx.x;
    int local = 0;
    for (int t = tid; t < NB * L * MW; t += 256) {
        unsigned w = g_M[t]; m[t] = w; local += __popc(w);
    }
    #pragma unroll
    for (int o = 16; o; o >>= 1) local += __shfl_xor_sync(0xffffffffu, local, o);
    if ((tid & 31) == 0) ired[tid >> 5] = local;
    __syncthreads();
    if (tid == 0) {
        int s = 0;
        #pragma unroll
        for (int w = 0; w < 8; w++) s += ired[w];
        sS = s;
    }
    __syncthreads();
    for (int ii = 0; ii < i; ii++) {
        if (sS == NB * L) break;
        if (tid == 0) sRem = 0;
        __syncthreads();
        int rem = 0;
        int nj = L - 1 - ii;
        int cnt = NB * nj * MW;
        for (int t = tid; t < cnt; t += 256) {
            int w = t % MW; int r = t / MW;
            int j = ii + 1 + (r % nj); int aa = r / nj;
            unsigned rw  = m[(aa * L + ii) * MW + w];
            unsigned old = m[(aa * L + j) * MW + w];
            unsigned drop = old & rw;
            if (drop) { m[(aa * L + j) * MW + w] = old & ~rw; rem += __popc(drop); }
        }
        #pragma unroll
        for (int o = 16; o; o >>= 1) rem += __shfl_xor_sync(0xffffffffu, rem, o);
        if ((tid & 31) == 0 && rem) atomicAdd(&sRem, rem);
        __syncthreads();
        if (tid == 0) sS -= sRem;
        __syncthreads();
    }
    const unsigned* mw = &m[(a * L + i) * MW];
    int num = 0;
    #pragma unroll
    for (int w = 0; w < MW; w++) num += __popc(mw[w]);
    float numc = (num > 0) ? (float)num : 1e-7f;
    bool has2 = tid < 129;
    int c1 = tid, c2 = tid + 256;
    float S1a = 0.f, S1b = 0.f;
    for (int w = 0; w < MW; w++) {
        unsigned bits = mw[w];
        while (bits) {
            int j = (w << 5) + __ffs((int)bits) - 1; bits &= bits - 1;
            const float* sp = g_sty + (size_t)(a * L + j) * STRH;
            S1a += sp[c1];
            if (has2) S1b += sp[c2];
        }
    }
    float avga = S1a / numc, avgb = S1b / numc;
    float S2a = 0.f, S2b = 0.f;
    for (int w = 0; w < MW; w++) {
        unsigned bits = mw[w];
        while (bits) {
            int j = (w << 5) + __ffs((int)bits) - 1; bits &= bits - 1;
            const float* sp = g_sty + (size_t)(a * L + j) * STRH;
            float xa = sp[c1] - avga; S2a += xa * xa;
            if (has2) { float xb = sp[c2] - avgb; S2b += xb * xb; }
        }
    }
    size_t off = (size_t)blk * STRH;
    float sta = sqrtf(S2a / numc);
    float ma = (S1a > 0.f) ? 1.f : 0.f;
    if (!(S1a > 0.f)) atomicAdd(&g_nzero, 1);
    g_B1[off + c1] = ma * sta; g_B2[off + c1] = ma * avga; g_B3[off + c1] = ma;
    if (has2) {
        float stb = sqrtf(S2b / numc);
        float mb = (S1b > 0.f) ? 1.f : 0.f;
        if (!(S1b > 0.f)) atomicAdd(&g_nzero, 1);
        g_B1[off + c2] = mb * stb; g_B2[off + c2] = mb * avgb; g_B3[off + c2] = mb;
    } else if (tid < 192) {
        g_B1[off + c2] = 0.f; g_B2[off + c2] = 0.f; g_B3[off + c2] = 0.f;
    }
}

// ============ Kernel D: split-K(4) triple GEMM -> g_Sn/g_Sd quarters =========
__global__ void k_D(const float* __restrict__ ls, const float* __restrict__ noise) {
    __shared__ __align__(16) float SD[8320];
    __shared__ int s_nz;
    float (*As)[68]  = (float(*)[68])SD;            // [2*16][68] interleaved a1/a2
    float (*B1s)[64] = (float(*)[64])(SD + 2176);
    float (*B2s)[64] = (float(*)[64])(SD + 4224);
    float (*B3s)[64] = (float(*)[64])(SD + 6272);
    int tid = threadIdx.x;
    if (tid == 0) s_nz = g_nzero;
    int tx = tid & 15, ty = tid >> 4;
    int n0 = blockIdx.x * 64, m0 = blockIdx.y * 32;
    int a = blockIdx.z >> 2, q = blockIdx.z & 3;
    int kbeg = q == 0 ? 0 : 16 + 48 * q;            // 0,64,112,160
    int kend = 64 + 48 * q;                         // 64,112,160,208
    u64 ac1[2][2], ac2[2][2], ac3[2][2];
    #pragma unroll
    for (int i = 0; i < 2; i++) {
        ac1[i][0] = ac1[i][1] = 0ULL;
        ac2[i][0] = ac2[i][1] = 0ULL;
        ac3[i][0] = ac3[i][1] = 0ULL;
    }
    int lm = tid >> 3, lk2 = (tid & 7) << 1;
    int cA = ((lm >> 1) << 2) + (lm & 1);           // interleaved col for a1
    int bk = tid >> 4, bn4 = (tid & 15) << 2;
    const float* lsb = ls    + (size_t)a * L * L;
    const float* nsb = noise + (size_t)a * L * L;
    float4 z4 = make_float4(0.f, 0.f, 0.f, 0.f);
    float2 z2 = make_float2(0.f, 0.f);
    int ia = m0 + lm;
    bool iav = ia < L;
    float2 lvP = z2, nvP = z2;
    if (iav) {                                       // kbeg+lk2 <= 174 < 196
        lvP = *reinterpret_cast<const float2*>(lsb + (size_t)ia * L + kbeg + lk2);
        nvP = *reinterpret_cast<const float2*>(nsb + (size_t)ia * L + kbeg + lk2);
    }
    float4 b1P, b2P, b3P = z4;
    {
        size_t o = (size_t)(a * L + kbeg + bk) * STRH + n0 + bn4;
        b1P = *reinterpret_cast<const float4*>(&g_B1[o]);
        b2P = *reinterpret_cast<const float4*>(&g_B2[o]);
        b3P = *reinterpret_cast<const float4*>(&g_B3[o]);
    }
    int p = 0;
    As[lk2 + 0][cA] = lvP.x * nvP.x; As[lk2 + 0][cA + 2] = lvP.x;
    As[lk2 + 1][cA] = lvP.y * nvP.y; As[lk2 + 1][cA + 2] = lvP.y;
    *reinterpret_cast<float4*>(&B1s[bk][bn4]) = b1P;
    *reinterpret_cast<float4*>(&B2s[bk][bn4]) = b2P;
    *reinterpret_cast<float4*>(&B3s[bk][bn4]) = b3P;
    __syncthreads();
    bool fast = (s_nz == 0);
    for (int k0 = kbeg; k0 < kend; k0 += 16) {
        int kn = k0 + 16;
        if (kn < kend) {
            lvP = z2; nvP = z2;
            if (iav) {
                int ja = kn + lk2;
                if (ja + 1 < L) {
                    lvP = *reinterpret_cast<const float2*>(lsb + (size_t)ia * L + ja);
                    nvP = *reinterpret_cast<const float2*>(nsb + (size_t)ia * L + ja);
                } else if (ja < L) {
                    lvP.x = lsb[(size_t)ia * L + ja]; nvP.x = nsb[(size_t)ia * L + ja];
                }
            }
            int jb = kn + bk;
            b1P = z4; b2P = z4; b3P = z4;
            if (jb < L) {
                size_t o = (size_t)(a * L + jb) * STRH + n0 + bn4;
                b1P = *reinterpret_cast<const float4*>(&g_B1[o]);
                b2P = *reinterpret_cast<const float4*>(&g_B2[o]);
                if (!fast) b3P = *reinterpret_cast<const float4*>(&g_B3[o]);
            }
        }
        int pb = p * 16;
        if (fast) {
            #pragma unroll
            for (int kk = 0; kk < 16; kk++) {
                float4 av = *reinterpret_cast<float4*>(&As[pb + kk][ty << 2]);
                ulonglong2 b1 = *reinterpret_cast<ulonglong2*>(&B1s[pb + kk][tx << 2]);
                ulonglong2 b2 = *reinterpret_cast<ulonglong2*>(&B2s[pb + kk][tx << 2]);
                u64 aa;
                aa = pack2(av.x, av.x); fma2(ac1[0][0], aa, b1.x); fma2(ac1[0][1], aa, b1.y);
                aa = pack2(av.y, av.y); fma2(ac1[1][0], aa, b1.x); fma2(ac1[1][1], aa, b1.y);
                aa = pack2(av.z, av.z); fma2(ac2[0][0], aa, b2.x); fma2(ac2[0][1], aa, b2.y);
                aa = pack2(av.w, av.w); fma2(ac2[1][0], aa, b2.x); fma2(ac2[1][1], aa, b2.y);
            }
        } else {
            #pragma unroll
            for (int kk = 0; kk < 16; kk++) {
                float4 av = *reinterpret_cast<float4*>(&As[pb + kk][ty << 2]);
                ulonglong2 b1 = *reinterpret_cast<ulonglong2*>(&B1s[pb + kk][tx << 2]);
                ulonglong2 b2 = *reinterpret_cast<ulonglong2*>(&B2s[pb + kk][tx << 2]);
                ulonglong2 b3 = *reinterpret_cast<ulonglong2*>(&B3s[pb + kk][tx << 2]);
                u64 aa;
                aa = pack2(av.x, av.x); fma2(ac1[0][0], aa, b1.x); fma2(ac1[0][1], aa, b1.y);
                aa = pack2(av.y, av.y); fma2(ac1[1][0], aa, b1.x); fma2(ac1[1][1], aa, b1.y);
                aa = pack2(av.z, av.z); fma2(ac2[0][0], aa, b2.x); fma2(ac2[0][1], aa, b2.y);
                                        fma2(ac3[0][0], aa, b3.x); fma2(ac3[0][1], aa, b3.y);
                aa = pack2(av.w, av.w); fma2(ac2[1][0], aa, b2.x); fma2(ac2[1][1], aa, b2.y);
                                        fma2(ac3[1][0], aa, b3.x); fma2(ac3[1][1], aa, b3.y);
            }
        }
        if (kn < kend) {
            int qb = (1 - p) * 16;
            As[qb + lk2 + 0][cA] = lvP.x * nvP.x; As[qb + lk2 + 0][cA + 2] = lvP.x;
            As[qb + lk2 + 1][cA] = lvP.y * nvP.y; As[qb + lk2 + 1][cA + 2] = lvP.y;
            *reinterpret_cast<float4*>(&B1s[qb + bk][bn4]) = b1P;
            *reinterpret_cast<float4*>(&B2s[qb + bk][bn4]) = b2P;
            *reinterpret_cast<float4*>(&B3s[qb + bk][bn4]) = b3P;
            __syncthreads();
            p ^= 1;
        }
    }
    #pragma unroll
    for (int im = 0; im < 2; im++) {
        int i = m0 + (ty << 1) + im;
        if (i >= L) continue;
        int row = a * L + i;
        size_t ob = (size_t)row * STRH + n0 + (tx << 2);
        float2 p1a = unpack2(ac1[im][0]), p1b = unpack2(ac1[im][1]);
        float2 p2a = unpack2(ac2[im][0]), p2b = unpack2(ac2[im][1]);
        float4 numv = make_float4(p1a.x + p2a.x, p1a.y + p2a.y,
                                  p1b.x + p2b.x, p1b.y + p2b.y);
        *reinterpret_cast<float4*>(&g_Sn[q][ob]) = numv;
        if (!fast) {
            float2 p3a = unpack2(ac3[im][0]), p3b = unpack2(ac3[im][1]);
            float4 denv = make_float4(p3a.x, p3a.y, p3b.x, p3b.y);
            *reinterpret_cast<float4*>(&g_Sd[q][ob]) = denv;
        }
    }
}

// ============ Kernel E: combine quarters + divide + Y + inverse FFT ==========
__global__ void k_E(float* __restrict__ out) {
    __shared__ __align__(16) float S[4400];
    float2* fa = (float2*)S;
    float2* fb = fa + 768;
    float2* tw = fa + 1536;
    int blk = blockIdx.x, a = blk / L, i = blk % L;
    int tid = threadIdx.x;
    for (int t = tid; t < 576; t += 256) {
        float s, c; sincospif((float)t * (1.f / 384.f), &s, &c);
        tw[t] = make_float2(c, s);
    }
    size_t bh = (size_t)blk * STRH;
    bool fast = (g_nzero == 0);
    float rs = fmaxf(g_rsum[blk], 1e-7f);
    for (int c = tid; c <= 384; c += 256) {
        float numv = g_Sn[0][bh + c] + g_Sn[1][bh + c] + g_Sn[2][bh + c] + g_Sn[3][bh + c];
        float den = fast ? rs
                  : fmaxf(g_Sd[0][bh + c] + g_Sd[1][bh + c] + g_Sd[2][bh + c] + g_Sd[3][bh + c],
                          1e-7f);
        float s = numv / den;
        float xr = g_Xr[bh + c], xi = g_Xi[bh + c];
        float m2 = xr * xr + xi * xi;
        float yr, yi;
        if (m2 > 0.f) { float r = s / sqrtf(m2); yr = xr * r; yi = xi * r; }
        else          { yr = s; yi = 0.f; }
        fa[c] = make_float2(yr, yi);
    }
    __syncthreads();
    for (int c = 385 + tid; c < 768; c += 256) {
        float2 y = fa[768 - c];
        fa[c] = make_float2(y.x, -y.y);
    }
    __syncthreads();
    float2* res = fft768r4(fa, fb, tw, tid, 1.0f);
    float* op = out + ((size_t)(a * 197 + 1 + i)) * D;
    for (int d = tid; d < D; d += 256)
        op[d] = res[d].x * (1.f / 768.f);
}

// ---------------- launch ------------------------------------------------------
extern "C" void kernel_launch(void* const* d_in, const int* in_sizes, int n_in,
                              void* d_out, int out_size) {
    const float* x     = (const float*)d_in[0];
    const float* imgs  = (const float*)d_in[1];
    const float* ls    = (const float*)d_in[2];
    const float* noise = (const float*)d_in[3];
    float* out = (float*)d_out;

    k_A1<<<A1_GRID, 256>>>(imgs, x, out, ls);
    k_A2<<<NLTOT + 56, 256>>>(x);
    k_C<<<NLTOT, 256>>>();
    k_D<<<dim3(7, 7, NB * 4), 256>>>(ls, noise);
    k_E<<<NLTOT, 256>>>(out);
}

// round 9
// speedup vs baseline: 3.0054x; 1.0090x over previous
#include <cuda_runtime.h>
#include <math.h>

#define NB 2
#define L 196
#define D 768
#define LD (L*D)
#define MW 7
#define NLTOT (NB*L)   // 392
#define STRH 448       // padded half-spectrum stride

// ---------------- scratch ---------------------------------------------------
__device__ float    g_V   [NB*LD];
__device__ float    g_Xr  [NLTOT*STRH];
__device__ float    g_Xi  [NLTOT*STRH];
__device__ float    g_sty [NLTOT*STRH];
__device__ float    g_Sn  [4][NLTOT*STRH];
__device__ float    g_Sd  [4][NLTOT*STRH];
__device__ float    g_B1  [NLTOT*STRH];
__device__ float    g_B2  [NLTOT*STRH];
__device__ float    g_B3  [NLTOT*STRH];
__device__ float    g_rsum[NLTOT];
__device__ unsigned g_M   [NB*L*MW];
__device__ int      g_nzero;

// ---------------- f32x2 helpers ---------------------------------------------
typedef unsigned long long u64;
__device__ __forceinline__ void fma2(u64 &acc, u64 a, u64 b) {
    asm("fma.rn.f32x2 %0, %1, %2, %0;" : "+l"(acc) : "l"(a), "l"(b));
}
__device__ __forceinline__ u64 pack2(float x, float y) {
    u64 r; asm("mov.b64 %0, {%1, %2};" : "=l"(r) : "f"(x), "f"(y)); return r;
}
__device__ __forceinline__ float2 unpack2(u64 v) {
    float2 f; asm("mov.b64 {%0, %1}, %2;" : "=f"(f.x), "=f"(f.y) : "l"(v)); return f;
}

__device__ __forceinline__ float blockSum256(float v, float* red) {
    #pragma unroll
    for (int o = 16; o; o >>= 1) v += __shfl_xor_sync(0xffffffffu, v, o);
    if ((threadIdx.x & 31) == 0) red[threadIdx.x >> 5] = v;
    __syncthreads();
    if (threadIdx.x < 32) {
        float x = (threadIdx.x < 8) ? red[threadIdx.x] : 0.f;
        #pragma unroll
        for (int o = 4; o; o >>= 1) x += __shfl_xor_sync(0xffffffffu, x, o);
        if (threadIdx.x == 0) red[0] = x;
    }
    __syncthreads();
    float r = red[0];
    __syncthreads();
    return r;
}

// build tw[0..576): tw[i] = cis(pi*i/384); quarter-rotation symmetry
__device__ __forceinline__ void build_tw(float2* tw, int tid) {
    if (tid < 192) {
        float s, c; sincospif((float)tid * (1.f / 384.f), &s, &c);
        tw[tid]       = make_float2(c, s);
        tw[tid + 192] = make_float2(-s, c);
        tw[tid + 384] = make_float2(-c, -s);
    }
}

// ---------------- Stockham FFT N=768 = 3*4^4, table twiddles -----------------
__device__ __forceinline__ float2* fft768r4(float2* a, float2* b,
                                            const float2* tw, int tid, float sgn) {
    {   // radix-3 stage
        const float c3 = 0.8660254037844386f * sgn;
        float2 x0 = a[tid], x1 = a[tid + 256], x2 = a[tid + 512];
        float2 s = make_float2(x1.x + x2.x, x1.y + x2.y);
        float2 d = make_float2(x1.x - x2.x, x1.y - x2.y);
        float mr = x0.x - 0.5f * s.x, mi = x0.y - 0.5f * s.y;
        b[3 * tid]     = make_float2(x0.x + s.x, x0.y + s.y);
        b[3 * tid + 1] = make_float2(mr - c3 * d.y, mi + c3 * d.x);
        b[3 * tid + 2] = make_float2(mr + c3 * d.y, mi - c3 * d.x);
    }
    __syncthreads();
    float2* src = b; float2* dst = a;
    #pragma unroll
    for (int st = 0; st < 4; st++) {            // radix-4: l = 3,12,48,192
        const int l = 3 << (2 * st);
        const int step = 64 >> (2 * st);
        if (tid < 192) {
            int j = tid;
            int k = j % l;
            int idx = k * step;
            float2 v0 = src[j], v1 = src[j + 192], v2 = src[j + 384], v3 = src[j + 576];
            float2 w1 = tw[idx], w2 = tw[2 * idx], w3 = tw[3 * idx];
            float s1 = sgn * w1.y, s2 = sgn * w2.y, s3 = sgn * w3.y;
            float2 t1 = make_float2(v1.x * w1.x - v1.y * s1, v1.x * s1 + v1.y * w1.x);
            float2 t2 = make_float2(v2.x * w2.x - v2.y * s2, v2.x * s2 + v2.y * w2.x);
            float2 t3 = make_float2(v3.x * w3.x - v3.y * s3, v3.x * s3 + v3.y * w3.x);
            float2 e0 = make_float2(v0.x + t2.x, v0.y + t2.y);
            float2 e1 = make_float2(v0.x - t2.x, v0.y - t2.y);
            float2 o0 = make_float2(t1.x + t3.x, t1.y + t3.y);
            float2 o1 = make_float2(t1.x - t3.x, t1.y - t3.y);
            float2 io = make_float2(-sgn * o1.y, sgn * o1.x);
            int ob = 4 * j - 3 * k;
            dst[ob]         = make_float2(e0.x + o0.x, e0.y + o0.y);
            dst[ob + l]     = make_float2(e1.x + io.x, e1.y + io.y);
            dst[ob + 2 * l] = make_float2(e0.x - o0.x, e0.y - o0.y);
            dst[ob + 3 * l] = make_float2(e1.x - io.x, e1.y - io.y);
        }
        __syncthreads();
        float2* t = src; src = dst; dst = t;
    }
    return src;
}

// ============ Kernel A1: patch(392) | rowsum(49) | misc(11) ==================
#define A1_PATCH 392
#define A1_RS    49
#define A1_MISC  11
#define A1_GRID  (A1_PATCH + A1_RS + A1_MISC)

__global__ void k_A1(const float* __restrict__ imgs, const float* __restrict__ x,
                     float* __restrict__ out, const float* __restrict__ ls) {
    __shared__ float red[8];
    __shared__ float buf[D];
    int b = blockIdx.x, tid = threadIdx.x;
    if (b < A1_PATCH) {
        int blk = b, a = blk / L, l = blk % L;
        int hh = l / 14, ww = l % 14;
        int p = tid >> 4, q = tid & 15;
        const float* base = imgs + ((size_t)a * 3 * 224 + (size_t)(hh * 16 + p)) * 224
                                 + (ww * 16 + q);
        float v[3];
        #pragma unroll
        for (int c = 0; c < 3; c++) v[c] = base[(size_t)c * 224 * 224];
        float mean = blockSum256(v[0] + v[1] + v[2], red) * (1.f / 768.f);
        float u[3]; float ss = 0.f;
        #pragma unroll
        for (int c = 0; c < 3; c++) { u[c] = v[c] - mean; ss += u[c] * u[c]; }
        float tot = blockSum256(ss, red);
        float inv = 1.f / sqrtf(tot);
        #pragma unroll
        for (int c = 0; c < 3; c++) buf[tid * 3 + c] = u[c] * inv;
        __syncthreads();
        if (tid < 192)
            reinterpret_cast<float4*>(g_V + (size_t)blk * D)[tid] =
                reinterpret_cast<float4*>(buf)[tid];
        return;
    }
    b -= A1_PATCH;
    if (b < A1_RS) {
        int w = tid >> 5, lane = tid & 31;
        int row = b * 8 + w;
        if (row < NLTOT) {
            int a = row / L, i = row % L;
            const float* lp = ls + ((size_t)a * L + i) * L;
            float s = 0.f;
            for (int j = lane; j < L; j += 32) s += lp[j];
            #pragma unroll
            for (int o = 16; o; o >>= 1) s += __shfl_xor_sync(0xffffffffu, s, o);
            if (lane == 0) g_rsum[row] = s;
        }
        return;
    }
    b -= A1_RS;
    {
        int t = b * 256 + tid;
        if (t < NB * L * MW) g_M[t] = 0u;
        if (t < NB * D) {
            int a = t / D, d = t % D;
            out[(size_t)a * 197 * D + d] = x[(size_t)a * 197 * D + d];
        }
        if (t == 0) g_nzero = 0;
    }
}

// ============ Kernel A2: fwd FFT(392) | sim(56) — one wave ===================
__global__ void k_A2(const float* __restrict__ x) {
    __shared__ __align__(16) float S[4400];
    int b = blockIdx.x, tid = threadIdx.x;
    if (b < NLTOT) {
        float2* fa = (float2*)S;
        float2* fb = fa + 768;
        float2* tw = fa + 1536;
        build_tw(tw, tid);
        int row = b, a = row / L, i = row % L;
        const float* xp = x + ((size_t)(a * 197 + 1 + i)) * D;
        for (int d = tid; d < D; d += 256) fa[d] = make_float2(xp[d], 0.f);
        __syncthreads();
        float2* res = fft768r4(fa, fb, tw, tid, -1.0f);
        size_t bh = (size_t)row * STRH;
        for (int k = tid; k <= 384; k += 256) {
            float2 X = res[k];
            g_Xr[bh + k] = X.x; g_Xi[bh + k] = X.y;
            g_sty[bh + k] = sqrtf(X.x * X.x + X.y * X.y);
        }
        return;
    }
    {
        // ---- sim: 32x32 upper-tri tile, double-buffered ----
        int bb = b - NLTOT;
        int a = bb / 28;
        int t = bb % 28, bi = 0;
        while (t >= 7 - bi) { t -= 7 - bi; bi++; }
        int bj = bi + t;
        int i0 = bi * 32, j0 = bj * 32;
        float (*As)[34] = (float(*)[34])S;
        float (*Bs)[34] = (float(*)[34])(S + 2176);
        int tx = tid & 15, ty = tid >> 4;
        int m = tid >> 3, k4 = (tid & 7) << 2;
        const float* Vb = g_V + (size_t)a * LD;
        const float* Arow = (i0 + m < L) ? Vb + (size_t)(i0 + m) * D : nullptr;
        const float* Brow = (j0 + m < L) ? Vb + (size_t)(j0 + m) * D : nullptr;
        float4 z4 = make_float4(0.f, 0.f, 0.f, 0.f);
        float4 avP = Arow ? *reinterpret_cast<const float4*>(Arow + k4) : z4;
        float4 bvP = Brow ? *reinterpret_cast<const float4*>(Brow + k4) : z4;
        u64 acc[2] = {0ULL, 0ULL};
        int p = 0;
        As[k4 + 0][m] = avP.x; As[k4 + 1][m] = avP.y;
        As[k4 + 2][m] = avP.z; As[k4 + 3][m] = avP.w;
        Bs[k4 + 0][m] = bvP.x; Bs[k4 + 1][m] = bvP.y;
        Bs[k4 + 2][m] = bvP.z; Bs[k4 + 3][m] = bvP.w;
        __syncthreads();
        for (int k0 = 0; k0 < D; k0 += 32) {
            int kn = k0 + 32;
            if (kn < D) {
                avP = Arow ? *reinterpret_cast<const float4*>(Arow + kn + k4) : z4;
                bvP = Brow ? *reinterpret_cast<const float4*>(Brow + kn + k4) : z4;
            }
            int pb = p * 32;
            #pragma unroll
            for (int kk = 0; kk < 32; kk++) {
                float2 a2 = *reinterpret_cast<float2*>(&As[pb + kk][ty << 1]);
                u64 bbv = *reinterpret_cast<u64*>(&Bs[pb + kk][tx << 1]);
                fma2(acc[0], pack2(a2.x, a2.x), bbv);
                fma2(acc[1], pack2(a2.y, a2.y), bbv);
            }
            if (kn < D) {
                int qb = (1 - p) * 32;
                As[qb + k4 + 0][m] = avP.x; As[qb + k4 + 1][m] = avP.y;
                As[qb + k4 + 2][m] = avP.z; As[qb + k4 + 3][m] = avP.w;
                Bs[qb + k4 + 0][m] = bvP.x; Bs[qb + k4 + 1][m] = bvP.y;
                Bs[qb + k4 + 2][m] = bvP.z; Bs[qb + k4 + 3][m] = bvP.w;
                __syncthreads();
                p ^= 1;
            }
        }
        #pragma unroll
        for (int r = 0; r < 2; r++) {
            int i = i0 + (ty << 1) + r;
            if (i >= L) continue;
            float2 c = unpack2(acc[r]);
            int j = j0 + (tx << 1);
            if (j < L && j >= i && c.x > 0.3f)
                atomicOr(&g_M[(a * L + i) * MW + (j >> 5)], 1u << (j & 31));
            j++;
            if (j < L && j >= i && c.y > 0.3f)
                atomicOr(&g_M[(a * L + i) * MW + (j >> 5)], 1u << (j & 31));
        }
    }
}

// ============ Kernel C: per-row prop replay + stats + nzero ==================
__global__ void k_C() {
    __shared__ unsigned m[NB * L * MW];
    __shared__ int sS, sRem, ired[8];
    int blk = blockIdx.x, a = blk / L, i = blk % L;
    int tid = threadIdx.x;
    int local = 0;
    for (int t = tid; t < NB * L * MW; t += 256) {
        unsigned w = g_M[t]; m[t] = w; local += __popc(w);
    }
    #pragma unroll
    for (int o = 16; o; o >>= 1) local += __shfl_xor_sync(0xffffffffu, local, o);
    if ((tid & 31) == 0) ired[tid >> 5] = local;
    __syncthreads();
    if (tid == 0) {
        int s = 0;
        #pragma unroll
        for (int w = 0; w < 8; w++) s += ired[w];
        sS = s;
    }
    __syncthreads();
    for (int ii = 0; ii < i; ii++) {
        if (sS == NB * L) break;
        if (tid == 0) sRem = 0;
        __syncthreads();
        int rem = 0;
        int nj = L - 1 - ii;
        int cnt = NB * nj * MW;
        for (int t = tid; t < cnt; t += 256) {
            int w = t % MW; int r = t / MW;
            int j = ii + 1 + (r % nj); int aa = r / nj;
            unsigned rw  = m[(aa * L + ii) * MW + w];
            unsigned old = m[(aa * L + j) * MW + w];
            unsigned drop = old & rw;
            if (drop) { m[(aa * L + j) * MW + w] = old & ~rw; rem += __popc(drop); }
        }
        #pragma unroll
        for (int o = 16; o; o >>= 1) rem += __shfl_xor_sync(0xffffffffu, rem, o);
        if ((tid & 31) == 0 && rem) atomicAdd(&sRem, rem);
        __syncthreads();
        if (tid == 0) sS -= sRem;
        __syncthreads();
    }
    const unsigned* mw = &m[(a * L + i) * MW];
    int num = 0;
    #pragma unroll
    for (int w = 0; w < MW; w++) num += __popc(mw[w]);
    float numc = (num > 0) ? (float)num : 1e-7f;
    bool has2 = tid < 129;
    int c1 = tid, c2 = tid + 256;
    float S1a = 0.f, S1b = 0.f;
    for (int w = 0; w < MW; w++) {
        unsigned bits = mw[w];
        while (bits) {
            int j = (w << 5) + __ffs((int)bits) - 1; bits &= bits - 1;
            const float* sp = g_sty + (size_t)(a * L + j) * STRH;
            S1a += sp[c1];
            if (has2) S1b += sp[c2];
        }
    }
    float avga = S1a / numc, avgb = S1b / numc;
    float S2a = 0.f, S2b = 0.f;
    for (int w = 0; w < MW; w++) {
        unsigned bits = mw[w];
        while (bits) {
            int j = (w << 5) + __ffs((int)bits) - 1; bits &= bits - 1;
            const float* sp = g_sty + (size_t)(a * L + j) * STRH;
            float xa = sp[c1] - avga; S2a += xa * xa;
            if (has2) { float xb = sp[c2] - avgb; S2b += xb * xb; }
        }
    }
    size_t off = (size_t)blk * STRH;
    float sta = sqrtf(S2a / numc);
    float ma = (S1a > 0.f) ? 1.f : 0.f;
    if (!(S1a > 0.f)) atomicAdd(&g_nzero, 1);
    g_B1[off + c1] = ma * sta; g_B2[off + c1] = ma * avga; g_B3[off + c1] = ma;
    if (has2) {
        float stb = sqrtf(S2b / numc);
        float mb = (S1b > 0.f) ? 1.f : 0.f;
        if (!(S1b > 0.f)) atomicAdd(&g_nzero, 1);
        g_B1[off + c2] = mb * stb; g_B2[off + c2] = mb * avgb; g_B3[off + c2] = mb;
    } else if (tid < 192) {
        g_B1[off + c2] = 0.f; g_B2[off + c2] = 0.f; g_B3[off + c2] = 0.f;
    }
}

// ============ Kernel Df: FAST split-K(4) dual GEMM (B3 dropped) ==============
__global__ void __launch_bounds__(256, 4)
k_Df(const float* __restrict__ ls, const float* __restrict__ noise) {
    if (g_nzero != 0) return;
    __shared__ __align__(16) float SD[6272];
    float (*As)[68]  = (float(*)[68])SD;            // [2*16][68] interleaved a1/a2
    float (*B1s)[64] = (float(*)[64])(SD + 2176);
    float (*B2s)[64] = (float(*)[64])(SD + 4224);
    int tid = threadIdx.x;
    int tx = tid & 15, ty = tid >> 4;
    int n0 = blockIdx.x * 64, m0 = blockIdx.y * 32;
    int a = blockIdx.z >> 2, q = blockIdx.z & 3;
    int kbeg = q == 0 ? 0 : 16 + 48 * q;
    int kend = 64 + 48 * q;
    u64 ac1[2][2], ac2[2][2];
    #pragma unroll
    for (int i = 0; i < 2; i++) {
        ac1[i][0] = ac1[i][1] = 0ULL;
        ac2[i][0] = ac2[i][1] = 0ULL;
    }
    int lm = tid >> 3, lk2 = (tid & 7) << 1;
    int cA = ((lm >> 1) << 2) + (lm & 1);
    int bk = tid >> 4, bn4 = (tid & 15) << 2;
    const float* lsb = ls    + (size_t)a * L * L;
    const float* nsb = noise + (size_t)a * L * L;
    float2 z2 = make_float2(0.f, 0.f);
    int ia = m0 + lm;
    bool iav = ia < L;
    float2 lvP = z2, nvP = z2;
    if (iav) {
        lvP = *reinterpret_cast<const float2*>(lsb + (size_t)ia * L + kbeg + lk2);
        nvP = *reinterpret_cast<const float2*>(nsb + (size_t)ia * L + kbeg + lk2);
    }
    float4 b1P, b2P;
    {
        size_t o = (size_t)(a * L + kbeg + bk) * STRH + n0 + bn4;
        b1P = *reinterpret_cast<const float4*>(&g_B1[o]);
        b2P = *reinterpret_cast<const float4*>(&g_B2[o]);
    }
    int p = 0;
    As[lk2 + 0][cA] = lvP.x * nvP.x; As[lk2 + 0][cA + 2] = lvP.x;
    As[lk2 + 1][cA] = lvP.y * nvP.y; As[lk2 + 1][cA + 2] = lvP.y;
    *reinterpret_cast<float4*>(&B1s[bk][bn4]) = b1P;
    *reinterpret_cast<float4*>(&B2s[bk][bn4]) = b2P;
    __syncthreads();
    for (int k0 = kbeg; k0 < kend; k0 += 16) {
        int kn = k0 + 16;
        if (kn < kend) {
            lvP = z2; nvP = z2;
            if (iav) {
                int ja = kn + lk2;
                if (ja + 1 < L) {
                    lvP = *reinterpret_cast<const float2*>(lsb + (size_t)ia * L + ja);
                    nvP = *reinterpret_cast<const float2*>(nsb + (size_t)ia * L + ja);
                } else if (ja < L) {
                    lvP.x = lsb[(size_t)ia * L + ja]; nvP.x = nsb[(size_t)ia * L + ja];
                }
            }
            int jb = kn + bk;
            b1P = make_float4(0.f, 0.f, 0.f, 0.f); b2P = b1P;
            if (jb < L) {
                size_t o = (size_t)(a * L + jb) * STRH + n0 + bn4;
                b1P = *reinterpret_cast<const float4*>(&g_B1[o]);
                b2P = *reinterpret_cast<const float4*>(&g_B2[o]);
            }
        }
        int pb = p * 16;
        #pragma unroll
        for (int kk = 0; kk < 16; kk++) {
            float4 av = *reinterpret_cast<float4*>(&As[pb + kk][ty << 2]);
            ulonglong2 b1 = *reinterpret_cast<ulonglong2*>(&B1s[pb + kk][tx << 2]);
            ulonglong2 b2 = *reinterpret_cast<ulonglong2*>(&B2s[pb + kk][tx << 2]);
            u64 aa;
            aa = pack2(av.x, av.x); fma2(ac1[0][0], aa, b1.x); fma2(ac1[0][1], aa, b1.y);
            aa = pack2(av.y, av.y); fma2(ac1[1][0], aa, b1.x); fma2(ac1[1][1], aa, b1.y);
            aa = pack2(av.z, av.z); fma2(ac2[0][0], aa, b2.x); fma2(ac2[0][1], aa, b2.y);
            aa = pack2(av.w, av.w); fma2(ac2[1][0], aa, b2.x); fma2(ac2[1][1], aa, b2.y);
        }
        if (kn < kend) {
            int qb = (1 - p) * 16;
            As[qb + lk2 + 0][cA] = lvP.x * nvP.x; As[qb + lk2 + 0][cA + 2] = lvP.x;
            As[qb + lk2 + 1][cA] = lvP.y * nvP.y; As[qb + lk2 + 1][cA + 2] = lvP.y;
            *reinterpret_cast<float4*>(&B1s[qb + bk][bn4]) = b1P;
            *reinterpret_cast<float4*>(&B2s[qb + bk][bn4]) = b2P;
            __syncthreads();
            p ^= 1;
        }
    }
    #pragma unroll
    for (int im = 0; im < 2; im++) {
        int i = m0 + (ty << 1) + im;
        if (i >= L) continue;
        int row = a * L + i;
        size_t ob = (size_t)row * STRH + n0 + (tx << 2);
        float2 p1a = unpack2(ac1[im][0]), p1b = unpack2(ac1[im][1]);
        float2 p2a = unpack2(ac2[im][0]), p2b = unpack2(ac2[im][1]);
        float4 numv = make_float4(p1a.x + p2a.x, p1a.y + p2a.y,
                                  p1b.x + p2b.x, p1b.y + p2b.y);
        *reinterpret_cast<float4*>(&g_Sn[q][ob]) = numv;
    }
}

// ============ Kernel Ds: SLOW split-K(4) triple GEMM (runs only if nzero) ====
__global__ void k_Ds(const float* __restrict__ ls, const float* __restrict__ noise) {
    if (g_nzero == 0) return;
    __shared__ __align__(16) float SD[8320];
    float (*As)[68]  = (float(*)[68])SD;
    float (*B1s)[64] = (float(*)[64])(SD + 2176);
    float (*B2s)[64] = (float(*)[64])(SD + 4224);
    float (*B3s)[64] = (float(*)[64])(SD + 6272);
    int tid = threadIdx.x;
    int tx = tid & 15, ty = tid >> 4;
    int n0 = blockIdx.x * 64, m0 = blockIdx.y * 32;
    int a = blockIdx.z >> 2, q = blockIdx.z & 3;
    int kbeg = q == 0 ? 0 : 16 + 48 * q;
    int kend = 64 + 48 * q;
    u64 ac1[2][2], ac2[2][2], ac3[2][2];
    #pragma unroll
    for (int i = 0; i < 2; i++) {
        ac1[i][0] = ac1[i][1] = 0ULL;
        ac2[i][0] = ac2[i][1] = 0ULL;
        ac3[i][0] = ac3[i][1] = 0ULL;
    }
    int lm = tid >> 3, lk2 = (tid & 7) << 1;
    int cA = ((lm >> 1) << 2) + (lm & 1);
    int bk = tid >> 4, bn4 = (tid & 15) << 2;
    const float* lsb = ls    + (size_t)a * L * L;
    const float* nsb = noise + (size_t)a * L * L;
    float4 z4 = make_float4(0.f, 0.f, 0.f, 0.f);
    float2 z2 = make_float2(0.f, 0.f);
    int ia = m0 + lm;
    bool iav = ia < L;
    float2 lvP = z2, nvP = z2;
    if (iav) {
        lvP = *reinterpret_cast<const float2*>(lsb + (size_t)ia * L + kbeg + lk2);
        nvP = *reinterpret_cast<const float2*>(nsb + (size_t)ia * L + kbeg + lk2);
    }
    float4 b1P, b2P, b3P;
    {
        size_t o = (size_t)(a * L + kbeg + bk) * STRH + n0 + bn4;
        b1P = *reinterpret_cast<const float4*>(&g_B1[o]);
        b2P = *reinterpret_cast<const float4*>(&g_B2[o]);
        b3P = *reinterpret_cast<const float4*>(&g_B3[o]);
    }
    int p = 0;
    As[lk2 + 0][cA] = lvP.x * nvP.x; As[lk2 + 0][cA + 2] = lvP.x;
    As[lk2 + 1][cA] = lvP.y * nvP.y; As[lk2 + 1][cA + 2] = lvP.y;
    *reinterpret_cast<float4*>(&B1s[bk][bn4]) = b1P;
    *reinterpret_cast<float4*>(&B2s[bk][bn4]) = b2P;
    *reinterpret_cast<float4*>(&B3s[bk][bn4]) = b3P;
    __syncthreads();
    for (int k0 = kbeg; k0 < kend; k0 += 16) {
        int kn = k0 + 16;
        if (kn < kend) {
            lvP = z2; nvP = z2;
            if (iav) {
                int ja = kn + lk2;
                if (ja + 1 < L) {
                    lvP = *reinterpret_cast<const float2*>(lsb + (size_t)ia * L + ja);
                    nvP = *reinterpret_cast<const float2*>(nsb + (size_t)ia * L + ja);
                } else if (ja < L) {
                    lvP.x = lsb[(size_t)ia * L + ja]; nvP.x = nsb[(size_t)ia * L + ja];
                }
            }
            int jb = kn + bk;
            b1P = z4; b2P = z4; b3P = z4;
            if (jb < L) {
                size_t o = (size_t)(a * L + jb) * STRH + n0 + bn4;
                b1P = *reinterpret_cast<const float4*>(&g_B1[o]);
                b2P = *reinterpret_cast<const float4*>(&g_B2[o]);
                b3P = *reinterpret_cast<const float4*>(&g_B3[o]);
            }
        }
        int pb = p * 16;
        #pragma unroll
        for (int kk = 0; kk < 16; kk++) {
            float4 av = *reinterpret_cast<float4*>(&As[pb + kk][ty << 2]);
            ulonglong2 b1 = *reinterpret_cast<ulonglong2*>(&B1s[pb + kk][tx << 2]);
            ulonglong2 b2 = *reinterpret_cast<ulonglong2*>(&B2s[pb + kk][tx << 2]);
            ulonglong2 b3 = *reinterpret_cast<ulonglong2*>(&B3s[pb + kk][tx << 2]);
            u64 aa;
            aa = pack2(av.x, av.x); fma2(ac1[0][0], aa, b1.x); fma2(ac1[0][1], aa, b1.y);
            aa = pack2(av.y, av.y); fma2(ac1[1][0], aa, b1.x); fma2(ac1[1][1], aa, b1.y);
            aa = pack2(av.z, av.z); fma2(ac2[0][0], aa, b2.x); fma2(ac2[0][1], aa, b2.y);
                                    fma2(ac3[0][0], aa, b3.x); fma2(ac3[0][1], aa, b3.y);
            aa = pack2(av.w, av.w); fma2(ac2[1][0], aa, b2.x); fma2(ac2[1][1], aa, b2.y);
                                    fma2(ac3[1][0], aa, b3.x); fma2(ac3[1][1], aa, b3.y);
        }
        if (kn < kend) {
            int qb = (1 - p) * 16;
            As[qb + lk2 + 0][cA] = lvP.x * nvP.x; As[qb + lk2 + 0][cA + 2] = lvP.x;
            As[qb + lk2 + 1][cA] = lvP.y * nvP.y; As[qb + lk2 + 1][cA + 2] = lvP.y;
            *reinterpret_cast<float4*>(&B1s[qb + bk][bn4]) = b1P;
            *reinterpret_cast<float4*>(&B2s[qb + bk][bn4]) = b2P;
            *reinterpret_cast<float4*>(&B3s[qb + bk][bn4]) = b3P;
            __syncthreads();
            p ^= 1;
        }
    }
    #pragma unroll
    for (int im = 0; im < 2; im++) {
        int i = m0 + (ty << 1) + im;
        if (i >= L) continue;
        int row = a * L + i;
        size_t ob = (size_t)row * STRH + n0 + (tx << 2);
        float2 p1a = unpack2(ac1[im][0]), p1b = unpack2(ac1[im][1]);
        float2 p2a = unpack2(ac2[im][0]), p2b = unpack2(ac2[im][1]);
        float4 numv = make_float4(p1a.x + p2a.x, p1a.y + p2a.y,
                                  p1b.x + p2b.x, p1b.y + p2b.y);
        *reinterpret_cast<float4*>(&g_Sn[q][ob]) = numv;
        float2 p3a = unpack2(ac3[im][0]), p3b = unpack2(ac3[im][1]);
        float4 denv = make_float4(p3a.x, p3a.y, p3b.x, p3b.y);
        *reinterpret_cast<float4*>(&g_Sd[q][ob]) = denv;
    }
}

// ============ Kernel E: combine quarters + divide + Y + inverse FFT ==========
__global__ void k_E(float* __restrict__ out) {
    __shared__ __align__(16) float S[4400];
    float2* fa = (float2*)S;
    float2* fb = fa + 768;
    float2* tw = fa + 1536;
    int blk = blockIdx.x, a = blk / L, i = blk % L;
    int tid = threadIdx.x;
    build_tw(tw, tid);
    size_t bh = (size_t)blk * STRH;
    bool fast = (g_nzero == 0);
    float rs = fmaxf(g_rsum[blk], 1e-7f);
    for (int c = tid; c <= 384; c += 256) {
        float numv = g_Sn[0][bh + c] + g_Sn[1][bh + c] + g_Sn[2][bh + c] + g_Sn[3][bh + c];
        float den = fast ? rs
                  : fmaxf(g_Sd[0][bh + c] + g_Sd[1][bh + c] + g_Sd[2][bh + c] + g_Sd[3][bh + c],
                          1e-7f);
        float s = numv / den;
        float xr = g_Xr[bh + c], xi = g_Xi[bh + c];
        float m2 = xr * xr + xi * xi;
        float yr, yi;
        if (m2 > 0.f) { float r = s / sqrtf(m2); yr = xr * r; yi = xi * r; }
        else          { yr = s; yi = 0.f; }
        fa[c] = make_float2(yr, yi);
    }
    __syncthreads();
    for (int c = 385 + tid; c < 768; c += 256) {
        float2 y = fa[768 - c];
        fa[c] = make_float2(y.x, -y.y);
    }
    __syncthreads();
    float2* res = fft768r4(fa, fb, tw, tid, 1.0f);
    float* op = out + ((size_t)(a * 197 + 1 + i)) * D;
    if (tid < 192) {
        int d = tid << 2;
        float4 o = make_float4(res[d].x     * (1.f / 768.f),
                               res[d + 1].x * (1.f / 768.f),
                               res[d + 2].x * (1.f / 768.f),
                               res[d + 3].x * (1.f / 768.f));
        *reinterpret_cast<float4*>(op + d) = o;
    }
}

// ---------------- launch ------------------------------------------------------
extern "C" void kernel_launch(void* const* d_in, const int* in_sizes, int n_in,
                              void* d_out, int out_size) {
    const float* x     = (const float*)d_in[0];
    const float* imgs  = (const float*)d_in[1];
    const float* ls    = (const float*)d_in[2];
    const float* noise = (const float*)d_in[3];
    float* out = (float*)d_out;

    k_A1<<<A1_GRID, 256>>>(imgs, x, out, ls);
    k_A2<<<NLTOT + 56, 256>>>(x);
    k_C<<<NLTOT, 256>>>();
    k_Df<<<dim3(7, 7, NB * 4), 256>>>(ls, noise);
    k_Ds<<<dim3(7, 7, NB * 4), 256>>>(ls, noise);
    k_E<<<NLTOT, 256>>>(out);
}

// round 10
// speedup vs baseline: 3.0831x; 1.0259x over previous
#include <cuda_runtime.h>
#include <math.h>

#define NB 2
#define L 196
#define D 768
#define LD (L*D)
#define MW 7
#define NLTOT (NB*L)   // 392
#define STRH 448       // padded half-spectrum stride
#define SPK 7          // split-K slices

// ---------------- scratch ---------------------------------------------------
__device__ float    g_V   [NB*LD];
__device__ float    g_Xr  [NLTOT*STRH];
__device__ float    g_Xi  [NLTOT*STRH];
__device__ float    g_sty [NLTOT*STRH];
__device__ float    g_Sn  [SPK][NLTOT*STRH];
__device__ float    g_Sd  [SPK][NLTOT*STRH];
__device__ float    g_B1  [NLTOT*STRH];
__device__ float    g_B2  [NLTOT*STRH];
__device__ float    g_B3  [NLTOT*STRH];
__device__ float    g_rsum[NLTOT];
__device__ unsigned g_M   [NB*L*MW];
__device__ int      g_nzero;

// ---------------- f32x2 helpers ---------------------------------------------
typedef unsigned long long u64;
__device__ __forceinline__ void fma2(u64 &acc, u64 a, u64 b) {
    asm("fma.rn.f32x2 %0, %1, %2, %0;" : "+l"(acc) : "l"(a), "l"(b));
}
__device__ __forceinline__ u64 pack2(float x, float y) {
    u64 r; asm("mov.b64 %0, {%1, %2};" : "=l"(r) : "f"(x), "f"(y)); return r;
}
__device__ __forceinline__ float2 unpack2(u64 v) {
    float2 f; asm("mov.b64 {%0, %1}, %2;" : "=f"(f.x), "=f"(f.y) : "l"(v)); return f;
}

__device__ __forceinline__ float blockSum256(float v, float* red) {
    #pragma unroll
    for (int o = 16; o; o >>= 1) v += __shfl_xor_sync(0xffffffffu, v, o);
    if ((threadIdx.x & 31) == 0) red[threadIdx.x >> 5] = v;
    __syncthreads();
    if (threadIdx.x < 32) {
        float x = (threadIdx.x < 8) ? red[threadIdx.x] : 0.f;
        #pragma unroll
        for (int o = 4; o; o >>= 1) x += __shfl_xor_sync(0xffffffffu, x, o);
        if (threadIdx.x == 0) red[0] = x;
    }
    __syncthreads();
    float r = red[0];
    __syncthreads();
    return r;
}

// build tw[0..576): tw[i] = cis(pi*i/384); quarter-rotation symmetry
__device__ __forceinline__ void build_tw(float2* tw, int tid) {
    if (tid < 192) {
        float s, c; sincospif((float)tid * (1.f / 384.f), &s, &c);
        tw[tid]       = make_float2(c, s);
        tw[tid + 192] = make_float2(-s, c);
        tw[tid + 384] = make_float2(-c, -s);
    }
}

// ---------------- Stockham FFT N=768 = 3*4^4, table twiddles -----------------
__device__ __forceinline__ float2* fft768r4(float2* a, float2* b,
                                            const float2* tw, int tid, float sgn) {
    {   // radix-3 stage
        const float c3 = 0.8660254037844386f * sgn;
        float2 x0 = a[tid], x1 = a[tid + 256], x2 = a[tid + 512];
        float2 s = make_float2(x1.x + x2.x, x1.y + x2.y);
        float2 d = make_float2(x1.x - x2.x, x1.y - x2.y);
        float mr = x0.x - 0.5f * s.x, mi = x0.y - 0.5f * s.y;
        b[3 * tid]     = make_float2(x0.x + s.x, x0.y + s.y);
        b[3 * tid + 1] = make_float2(mr - c3 * d.y, mi + c3 * d.x);
        b[3 * tid + 2] = make_float2(mr + c3 * d.y, mi - c3 * d.x);
    }
    __syncthreads();
    float2* src = b; float2* dst = a;
    #pragma unroll
    for (int st = 0; st < 4; st++) {            // radix-4: l = 3,12,48,192
        const int l = 3 << (2 * st);
        const int step = 64 >> (2 * st);
        if (tid < 192) {
            int j = tid;
            int k = j % l;
            int idx = k * step;
            float2 v0 = src[j], v1 = src[j + 192], v2 = src[j + 384], v3 = src[j + 576];
            float2 w1 = tw[idx], w2 = tw[2 * idx], w3 = tw[3 * idx];
            float s1 = sgn * w1.y, s2 = sgn * w2.y, s3 = sgn * w3.y;
            float2 t1 = make_float2(v1.x * w1.x - v1.y * s1, v1.x * s1 + v1.y * w1.x);
            float2 t2 = make_float2(v2.x * w2.x - v2.y * s2, v2.x * s2 + v2.y * w2.x);
            float2 t3 = make_float2(v3.x * w3.x - v3.y * s3, v3.x * s3 + v3.y * w3.x);
            float2 e0 = make_float2(v0.x + t2.x, v0.y + t2.y);
            float2 e1 = make_float2(v0.x - t2.x, v0.y - t2.y);
            float2 o0 = make_float2(t1.x + t3.x, t1.y + t3.y);
            float2 o1 = make_float2(t1.x - t3.x, t1.y - t3.y);
            float2 io = make_float2(-sgn * o1.y, sgn * o1.x);
            int ob = 4 * j - 3 * k;
            dst[ob]         = make_float2(e0.x + o0.x, e0.y + o0.y);
            dst[ob + l]     = make_float2(e1.x + io.x, e1.y + io.y);
            dst[ob + 2 * l] = make_float2(e0.x - o0.x, e0.y - o0.y);
            dst[ob + 3 * l] = make_float2(e1.x - io.x, e1.y - io.y);
        }
        __syncthreads();
        float2* t = src; src = dst; dst = t;
    }
    return src;
}

// ============ Kernel A1: patch(392) | rowsum(49) | misc(11) ==================
#define A1_PATCH 392
#define A1_RS    49
#define A1_MISC  11
#define A1_GRID  (A1_PATCH + A1_RS + A1_MISC)

__global__ void k_A1(const float* __restrict__ imgs, const float* __restrict__ x,
                     float* __restrict__ out, const float* __restrict__ ls) {
    __shared__ float red[8];
    __shared__ float buf[D];
    int b = blockIdx.x, tid = threadIdx.x;
    if (b < A1_PATCH) {
        int blk = b, a = blk / L, l = blk % L;
        int hh = l / 14, ww = l % 14;
        int p = tid >> 4, q = tid & 15;
        const float* base = imgs + ((size_t)a * 3 * 224 + (size_t)(hh * 16 + p)) * 224
                                 + (ww * 16 + q);
        float v[3];
        #pragma unroll
        for (int c = 0; c < 3; c++) v[c] = base[(size_t)c * 224 * 224];
        float mean = blockSum256(v[0] + v[1] + v[2], red) * (1.f / 768.f);
        float u[3]; float ss = 0.f;
        #pragma unroll
        for (int c = 0; c < 3; c++) { u[c] = v[c] - mean; ss += u[c] * u[c]; }
        float tot = blockSum256(ss, red);
        float inv = 1.f / sqrtf(tot);
        #pragma unroll
        for (int c = 0; c < 3; c++) buf[tid * 3 + c] = u[c] * inv;
        __syncthreads();
        if (tid < 192)
            reinterpret_cast<float4*>(g_V + (size_t)blk * D)[tid] =
                reinterpret_cast<float4*>(buf)[tid];
        return;
    }
    b -= A1_PATCH;
    if (b < A1_RS) {
        int w = tid >> 5, lane = tid & 31;
        int row = b * 8 + w;
        if (row < NLTOT) {
            int a = row / L, i = row % L;
            const float* lp = ls + ((size_t)a * L + i) * L;
            float s = 0.f;
            for (int j = lane; j < L; j += 32) s += lp[j];
            #pragma unroll
            for (int o = 16; o; o >>= 1) s += __shfl_xor_sync(0xffffffffu, s, o);
            if (lane == 0) g_rsum[row] = s;
        }
        return;
    }
    b -= A1_RS;
    {
        int t = b * 256 + tid;
        if (t < NB * L * MW) g_M[t] = 0u;
        if (t < NB * D) {
            int a = t / D, d = t % D;
            out[(size_t)a * 197 * D + d] = x[(size_t)a * 197 * D + d];
        }
        if (t == 0) g_nzero = 0;
    }
}

// ============ Kernel A2: fwd FFT(392) | sim(56) — one wave ===================
__global__ void k_A2(const float* __restrict__ x) {
    __shared__ __align__(16) float S[4400];
    int b = blockIdx.x, tid = threadIdx.x;
    if (b < NLTOT) {
        float2* fa = (float2*)S;
        float2* fb = fa + 768;
        float2* tw = fa + 1536;
        build_tw(tw, tid);
        int row = b, a = row / L, i = row % L;
        const float* xp = x + ((size_t)(a * 197 + 1 + i)) * D;
        for (int d = tid; d < D; d += 256) fa[d] = make_float2(xp[d], 0.f);
        __syncthreads();
        float2* res = fft768r4(fa, fb, tw, tid, -1.0f);
        size_t bh = (size_t)row * STRH;
        for (int k = tid; k <= 384; k += 256) {
            float2 X = res[k];
            g_Xr[bh + k] = X.x; g_Xi[bh + k] = X.y;
            g_sty[bh + k] = sqrtf(X.x * X.x + X.y * X.y);
        }
        return;
    }
    {
        // ---- sim: 32x32 upper-tri tile, double-buffered ----
        int bb = b - NLTOT;
        int a = bb / 28;
        int t = bb % 28, bi = 0;
        while (t >= 7 - bi) { t -= 7 - bi; bi++; }
        int bj = bi + t;
        int i0 = bi * 32, j0 = bj * 32;
        float (*As)[34] = (float(*)[34])S;
        float (*Bs)[34] = (float(*)[34])(S + 2176);
        int tx = tid & 15, ty = tid >> 4;
        int m = tid >> 3, k4 = (tid & 7) << 2;
        const float* Vb = g_V + (size_t)a * LD;
        const float* Arow = (i0 + m < L) ? Vb + (size_t)(i0 + m) * D : nullptr;
        const float* Brow = (j0 + m < L) ? Vb + (size_t)(j0 + m) * D : nullptr;
        float4 z4 = make_float4(0.f, 0.f, 0.f, 0.f);
        float4 avP = Arow ? *reinterpret_cast<const float4*>(Arow + k4) : z4;
        float4 bvP = Brow ? *reinterpret_cast<const float4*>(Brow + k4) : z4;
        u64 acc[2] = {0ULL, 0ULL};
        int p = 0;
        As[k4 + 0][m] = avP.x; As[k4 + 1][m] = avP.y;
        As[k4 + 2][m] = avP.z; As[k4 + 3][m] = avP.w;
        Bs[k4 + 0][m] = bvP.x; Bs[k4 + 1][m] = bvP.y;
        Bs[k4 + 2][m] = bvP.z; Bs[k4 + 3][m] = bvP.w;
        __syncthreads();
        for (int k0 = 0; k0 < D; k0 += 32) {
            int kn = k0 + 32;
            if (kn < D) {
                avP = Arow ? *reinterpret_cast<const float4*>(Arow + kn + k4) : z4;
                bvP = Brow ? *reinterpret_cast<const float4*>(Brow + kn + k4) : z4;
            }
            int pb = p * 32;
            #pragma unroll
            for (int kk = 0; kk < 32; kk++) {
                float2 a2 = *reinterpret_cast<float2*>(&As[pb + kk][ty << 1]);
                u64 bbv = *reinterpret_cast<u64*>(&Bs[pb + kk][tx << 1]);
                fma2(acc[0], pack2(a2.x, a2.x), bbv);
                fma2(acc[1], pack2(a2.y, a2.y), bbv);
            }
            if (kn < D) {
                int qb = (1 - p) * 32;
                As[qb + k4 + 0][m] = avP.x; As[qb + k4 + 1][m] = avP.y;
                As[qb + k4 + 2][m] = avP.z; As[qb + k4 + 3][m] = avP.w;
                Bs[qb + k4 + 0][m] = bvP.x; Bs[qb + k4 + 1][m] = bvP.y;
                Bs[qb + k4 + 2][m] = bvP.z; Bs[qb + k4 + 3][m] = bvP.w;
                __syncthreads();
                p ^= 1;
            }
        }
        #pragma unroll
        for (int r = 0; r < 2; r++) {
            int i = i0 + (ty << 1) + r;
            if (i >= L) continue;
            float2 c = unpack2(acc[r]);
            int j = j0 + (tx << 1);
            if (j < L && j >= i && c.x > 0.3f)
                atomicOr(&g_M[(a * L + i) * MW + (j >> 5)], 1u << (j & 31));
            j++;
            if (j < L && j >= i && c.y > 0.3f)
                atomicOr(&g_M[(a * L + i) * MW + (j >> 5)], 1u << (j & 31));
        }
    }
}

// ============ Kernel C: per-row prop replay + stats + nzero ==================
__global__ void k_C() {
    __shared__ unsigned m[NB * L * MW];
    __shared__ int sS, sRem, ired[8];
    int blk = blockIdx.x, a = blk / L, i = blk % L;
    int tid = threadIdx.x;
    int local = 0;
    for (int t = tid; t < NB * L * MW; t += 256) {
        unsigned w = g_M[t]; m[t] = w; local += __popc(w);
    }
    #pragma unroll
    for (int o = 16; o; o >>= 1) local += __shfl_xor_sync(0xffffffffu, local, o);
    if ((tid & 31) == 0) ired[tid >> 5] = local;
    __syncthreads();
    if (tid == 0) {
        int s = 0;
        #pragma unroll
        for (int w = 0; w < 8; w++) s += ired[w];
        sS = s;
    }
    __syncthreads();
    for (int ii = 0; ii < i; ii++) {
        if (sS == NB * L) break;
        if (tid == 0) sRem = 0;
        __syncthreads();
        int rem = 0;
        int nj = L - 1 - ii;
        int cnt = NB * nj * MW;
        for (int t = tid; t < cnt; t += 256) {
            int w = t % MW; int r = t / MW;
            int j = ii + 1 + (r % nj); int aa = r / nj;
            unsigned rw  = m[(aa * L + ii) * MW + w];
            unsigned old = m[(aa * L + j) * MW + w];
            unsigned drop = old & rw;
            if (drop) { m[(aa * L + j) * MW + w] = old & ~rw; rem += __popc(drop); }
        }
        #pragma unroll
        for (int o = 16; o; o >>= 1) rem += __shfl_xor_sync(0xffffffffu, rem, o);
        if ((tid & 31) == 0 && rem) atomicAdd(&sRem, rem);
        __syncthreads();
        if (tid == 0) sS -= sRem;
        __syncthreads();
    }
    const unsigned* mw = &m[(a * L + i) * MW];
    int num = 0;
    #pragma unroll
    for (int w = 0; w < MW; w++) num += __popc(mw[w]);
    float numc = (num > 0) ? (float)num : 1e-7f;
    bool has2 = tid < 129;
    int c1 = tid, c2 = tid + 256;
    float S1a = 0.f, S1b = 0.f;
    for (int w = 0; w < MW; w++) {
        unsigned bits = mw[w];
        while (bits) {
            int j = (w << 5) + __ffs((int)bits) - 1; bits &= bits - 1;
            const float* sp = g_sty + (size_t)(a * L + j) * STRH;
            S1a += sp[c1];
            if (has2) S1b += sp[c2];
        }
    }
    float avga = S1a / numc, avgb = S1b / numc;
    float S2a = 0.f, S2b = 0.f;
    for (int w = 0; w < MW; w++) {
        unsigned bits = mw[w];
        while (bits) {
            int j = (w << 5) + __ffs((int)bits) - 1; bits &= bits - 1;
            const float* sp = g_sty + (size_t)(a * L + j) * STRH;
            float xa = sp[c1] - avga; S2a += xa * xa;
            if (has2) { float xb = sp[c2] - avgb; S2b += xb * xb; }
        }
    }
    size_t off = (size_t)blk * STRH;
    float sta = sqrtf(S2a / numc);
    float ma = (S1a > 0.f) ? 1.f : 0.f;
    if (!(S1a > 0.f)) atomicAdd(&g_nzero, 1);
    g_B1[off + c1] = ma * sta; g_B2[off + c1] = ma * avga; g_B3[off + c1] = ma;
    if (has2) {
        float stb = sqrtf(S2b / numc);
        float mb = (S1b > 0.f) ? 1.f : 0.f;
        if (!(S1b > 0.f)) atomicAdd(&g_nzero, 1);
        g_B1[off + c2] = mb * stb; g_B2[off + c2] = mb * avgb; g_B3[off + c2] = mb;
    } else if (tid < 192) {
        g_B1[off + c2] = 0.f; g_B2[off + c2] = 0.f; g_B3[off + c2] = 0.f;
    }
}

// ============ Kernel Df: FAST split-K(7) dual GEMM, 64x64 tile, 4Mx4N ========
// slice q: k in [kbeg, kend), kbeg = q?16+32(q-1):0, kend = 16+32q (clamped work via guards)
#define ARS 68   // smem row stride (17*16B aligned)
__global__ void __launch_bounds__(256, 3)
k_Df(const float* __restrict__ ls, const float* __restrict__ noise) {
    if (g_nzero != 0) return;
    __shared__ __align__(16) float SD[4 * 32 * ARS];   // A1|A2|B1|B2, dbl-buffered
    float* A1s = SD;
    float* A2s = SD + 32 * ARS;
    float* B1s = SD + 64 * ARS;
    float* B2s = SD + 96 * ARS;
    int tid = threadIdx.x;
    int tx = tid & 15, ty = tid >> 4;
    int n0 = blockIdx.x * 64, m0 = blockIdx.y * 64;
    int a = blockIdx.z / SPK, q = blockIdx.z % SPK;
    int kbeg = (q == 0) ? 0 : 16 + 32 * (q - 1);
    int kend = 16 + 32 * q;
    u64 ac1[4][2], ac2[4][2];
    #pragma unroll
    for (int i = 0; i < 4; i++) {
        ac1[i][0] = ac1[i][1] = 0ULL;
        ac2[i][0] = ac2[i][1] = 0ULL;
    }
    int lm = tid >> 2, lk = (tid & 3) << 2;     // A loader: row lm, k-chunk lk
    int bk = tid >> 4, bn4 = (tid & 15) << 2;   // B loader
    const float* lsb = ls    + (size_t)a * L * L;
    const float* nsb = noise + (size_t)a * L * L;
    float4 z4 = make_float4(0.f, 0.f, 0.f, 0.f);
    int ia = m0 + lm;
    bool iav = ia < L;
    float4 lvP = z4, nvP = z4;
    {
        int ja = kbeg + lk;
        if (iav && ja < L) {
            lvP = *reinterpret_cast<const float4*>(lsb + (size_t)ia * L + ja);
            nvP = *reinterpret_cast<const float4*>(nsb + (size_t)ia * L + ja);
        }
    }
    float4 b1P = z4, b2P = z4;
    {
        int jb = kbeg + bk;
        if (jb < L) {
            size_t o = (size_t)(a * L + jb) * STRH + n0 + bn4;
            b1P = *reinterpret_cast<const float4*>(&g_B1[o]);
            b2P = *reinterpret_cast<const float4*>(&g_B2[o]);
        }
    }
    int p = 0;
    {
        const float* lv = reinterpret_cast<const float*>(&lvP);
        const float* nv = reinterpret_cast<const float*>(&nvP);
        #pragma unroll
        for (int t = 0; t < 4; t++) {
            A1s[(lk + t) * ARS + lm] = lv[t] * nv[t];
            A2s[(lk + t) * ARS + lm] = lv[t];
        }
        *reinterpret_cast<float4*>(&B1s[bk * ARS + bn4]) = b1P;
        *reinterpret_cast<float4*>(&B2s[bk * ARS + bn4]) = b2P;
    }
    __syncthreads();
    for (int k0 = kbeg; k0 < kend; k0 += 16) {
        int kn = k0 + 16;
        if (kn < kend) {
            lvP = z4; nvP = z4;
            int ja = kn + lk;
            if (iav && ja < L) {
                lvP = *reinterpret_cast<const float4*>(lsb + (size_t)ia * L + ja);
                nvP = *reinterpret_cast<const float4*>(nsb + (size_t)ia * L + ja);
            }
            int jb = kn + bk;
            b1P = z4; b2P = z4;
            if (jb < L) {
                size_t o = (size_t)(a * L + jb) * STRH + n0 + bn4;
                b1P = *reinterpret_cast<const float4*>(&g_B1[o]);
                b2P = *reinterpret_cast<const float4*>(&g_B2[o]);
            }
        }
        int pb = p * 16;
        #pragma unroll
        for (int kk = 0; kk < 16; kk++) {
            float4 a1 = *reinterpret_cast<float4*>(&A1s[(pb + kk) * ARS + (ty << 2)]);
            float4 a2 = *reinterpret_cast<float4*>(&A2s[(pb + kk) * ARS + (ty << 2)]);
            ulonglong2 b1 = *reinterpret_cast<ulonglong2*>(&B1s[(pb + kk) * ARS + (tx << 2)]);
            ulonglong2 b2 = *reinterpret_cast<ulonglong2*>(&B2s[(pb + kk) * ARS + (tx << 2)]);
            u64 aa;
            aa = pack2(a1.x, a1.x); fma2(ac1[0][0], aa, b1.x); fma2(ac1[0][1], aa, b1.y);
            aa = pack2(a1.y, a1.y); fma2(ac1[1][0], aa, b1.x); fma2(ac1[1][1], aa, b1.y);
            aa = pack2(a1.z, a1.z); fma2(ac1[2][0], aa, b1.x); fma2(ac1[2][1], aa, b1.y);
            aa = pack2(a1.w, a1.w); fma2(ac1[3][0], aa, b1.x); fma2(ac1[3][1], aa, b1.y);
            aa = pack2(a2.x, a2.x); fma2(ac2[0][0], aa, b2.x); fma2(ac2[0][1], aa, b2.y);
            aa = pack2(a2.y, a2.y); fma2(ac2[1][0], aa, b2.x); fma2(ac2[1][1], aa, b2.y);
            aa = pack2(a2.z, a2.z); fma2(ac2[2][0], aa, b2.x); fma2(ac2[2][1], aa, b2.y);
            aa = pack2(a2.w, a2.w); fma2(ac2[3][0], aa, b2.x); fma2(ac2[3][1], aa, b2.y);
        }
        if (kn < kend) {
            int qb = (1 - p) * 16;
            const float* lv = reinterpret_cast<const float*>(&lvP);
            const float* nv = reinterpret_cast<const float*>(&nvP);
            #pragma unroll
            for (int t = 0; t < 4; t++) {
                A1s[(qb + lk + t) * ARS + lm] = lv[t] * nv[t];
                A2s[(qb + lk + t) * ARS + lm] = lv[t];
            }
            *reinterpret_cast<float4*>(&B1s[(qb + bk) * ARS + bn4]) = b1P;
            *reinterpret_cast<float4*>(&B2s[(qb + bk) * ARS + bn4]) = b2P;
            __syncthreads();
            p ^= 1;
        }
    }
    #pragma unroll
    for (int im = 0; im < 4; im++) {
        int i = m0 + (ty << 2) + im;
        if (i >= L) continue;
        int row = a * L + i;
        size_t ob = (size_t)row * STRH + n0 + (tx << 2);
        float2 p1a = unpack2(ac1[im][0]), p1b = unpack2(ac1[im][1]);
        float2 p2a = unpack2(ac2[im][0]), p2b = unpack2(ac2[im][1]);
        float4 numv = make_float4(p1a.x + p2a.x, p1a.y + p2a.y,
                                  p1b.x + p2b.x, p1b.y + p2b.y);
        *reinterpret_cast<float4*>(&g_Sn[q][ob]) = numv;
    }
}

// ============ Kernel Ds: SLOW split-K(7) triple GEMM (runs only if nzero) ====
__global__ void k_Ds(const float* __restrict__ ls, const float* __restrict__ noise) {
    if (g_nzero == 0) return;
    __shared__ __align__(16) float SD[5 * 32 * ARS];
    float* A1s = SD;
    float* A2s = SD + 32 * ARS;
    float* B1s = SD + 64 * ARS;
    float* B2s = SD + 96 * ARS;
    float* B3s = SD + 128 * ARS;
    int tid = threadIdx.x;
    int tx = tid & 15, ty = tid >> 4;
    int n0 = blockIdx.x * 64, m0 = blockIdx.y * 64;
    int a = blockIdx.z / SPK, q = blockIdx.z % SPK;
    int kbeg = (q == 0) ? 0 : 16 + 32 * (q - 1);
    int kend = 16 + 32 * q;
    u64 ac1[4][2], ac2[4][2], ac3[4][2];
    #pragma unroll
    for (int i = 0; i < 4; i++) {
        ac1[i][0] = ac1[i][1] = 0ULL;
        ac2[i][0] = ac2[i][1] = 0ULL;
        ac3[i][0] = ac3[i][1] = 0ULL;
    }
    int lm = tid >> 2, lk = (tid & 3) << 2;
    int bk = tid >> 4, bn4 = (tid & 15) << 2;
    const float* lsb = ls    + (size_t)a * L * L;
    const float* nsb = noise + (size_t)a * L * L;
    float4 z4 = make_float4(0.f, 0.f, 0.f, 0.f);
    int ia = m0 + lm;
    bool iav = ia < L;
    float4 lvP = z4, nvP = z4;
    {
        int ja = kbeg + lk;
        if (iav && ja < L) {
            lvP = *reinterpret_cast<const float4*>(lsb + (size_t)ia * L + ja);
            nvP = *reinterpret_cast<const float4*>(nsb + (size_t)ia * L + ja);
        }
    }
    float4 b1P = z4, b2P = z4, b3P = z4;
    {
        int jb = kbeg + bk;
        if (jb < L) {
            size_t o = (size_t)(a * L + jb) * STRH + n0 + bn4;
            b1P = *reinterpret_cast<const float4*>(&g_B1[o]);
            b2P = *reinterpret_cast<const float4*>(&g_B2[o]);
            b3P = *reinterpret_cast<const float4*>(&g_B3[o]);
        }
    }
    int p = 0;
    {
        const float* lv = reinterpret_cast<const float*>(&lvP);
        const float* nv = reinterpret_cast<const float*>(&nvP);
        #pragma unroll
        for (int t = 0; t < 4; t++) {
            A1s[(lk + t) * ARS + lm] = lv[t] * nv[t];
            A2s[(lk + t) * ARS + lm] = lv[t];
        }
        *reinterpret_cast<float4*>(&B1s[bk * ARS + bn4]) = b1P;
        *reinterpret_cast<float4*>(&B2s[bk * ARS + bn4]) = b2P;
        *reinterpret_cast<float4*>(&B3s[bk * ARS + bn4]) = b3P;
    }
    __syncthreads();
    for (int k0 = kbeg; k0 < kend; k0 += 16) {
        int kn = k0 + 16;
        if (kn < kend) {
            lvP = z4; nvP = z4;
            int ja = kn + lk;
            if (iav && ja < L) {
                lvP = *reinterpret_cast<const float4*>(lsb + (size_t)ia * L + ja);
                nvP = *reinterpret_cast<const float4*>(nsb + (size_t)ia * L + ja);
            }
            int jb = kn + bk;
            b1P = z4; b2P = z4; b3P = z4;
            if (jb < L) {
                size_t o = (size_t)(a * L + jb) * STRH + n0 + bn4;
                b1P = *reinterpret_cast<const float4*>(&g_B1[o]);
                b2P = *reinterpret_cast<const float4*>(&g_B2[o]);
                b3P = *reinterpret_cast<const float4*>(&g_B3[o]);
            }
        }
        int pb = p * 16;
        #pragma unroll
        for (int kk = 0; kk < 16; kk++) {
            float4 a1 = *reinterpret_cast<float4*>(&A1s[(pb + kk) * ARS + (ty << 2)]);
            float4 a2 = *reinterpret_cast<float4*>(&A2s[(pb + kk) * ARS + (ty << 2)]);
            ulonglong2 b1 = *reinterpret_cast<ulonglong2*>(&B1s[(pb + kk) * ARS + (tx << 2)]);
            ulonglong2 b2 = *reinterpret_cast<ulonglong2*>(&B2s[(pb + kk) * ARS + (tx << 2)]);
            ulonglong2 b3 = *reinterpret_cast<ulonglong2*>(&B3s[(pb + kk) * ARS + (tx << 2)]);
            u64 aa;
            aa = pack2(a1.x, a1.x); fma2(ac1[0][0], aa, b1.x); fma2(ac1[0][1], aa, b1.y);
            aa = pack2(a1.y, a1.y); fma2(ac1[1][0], aa, b1.x); fma2(ac1[1][1], aa, b1.y);
            aa = pack2(a1.z, a1.z); fma2(ac1[2][0], aa, b1.x); fma2(ac1[2][1], aa, b1.y);
            aa = pack2(a1.w, a1.w); fma2(ac1[3][0], aa, b1.x); fma2(ac1[3][1], aa, b1.y);
            aa = pack2(a2.x, a2.x); fma2(ac2[0][0], aa, b2.x); fma2(ac2[0][1], aa, b2.y);
                                    fma2(ac3[0][0], aa, b3.x); fma2(ac3[0][1], aa, b3.y);
            aa = pack2(a2.y, a2.y); fma2(ac2[1][0], aa, b2.x); fma2(ac2[1][1], aa, b2.y);
                                    fma2(ac3[1][0], aa, b3.x); fma2(ac3[1][1], aa, b3.y);
            aa = pack2(a2.z, a2.z); fma2(ac2[2][0], aa, b2.x); fma2(ac2[2][1], aa, b2.y);
                                    fma2(ac3[2][0], aa, b3.x); fma2(ac3[2][1], aa, b3.y);
            aa = pack2(a2.w, a2.w); fma2(ac2[3][0], aa, b2.x); fma2(ac2[3][1], aa, b2.y);
                                    fma2(ac3[3][0], aa, b3.x); fma2(ac3[3][1], aa, b3.y);
        }
        if (kn < kend) {
            int qb = (1 - p) * 16;
            const float* lv = reinterpret_cast<const float*>(&lvP);
            const float* nv = reinterpret_cast<const float*>(&nvP);
            #pragma unroll
            for (int t = 0; t < 4; t++) {
                A1s[(qb + lk + t) * ARS + lm] = lv[t] * nv[t];
                A2s[(qb + lk + t) * ARS + lm] = lv[t];
            }
            *reinterpret_cast<float4*>(&B1s[(qb + bk) * ARS + bn4]) = b1P;
            *reinterpret_cast<float4*>(&B2s[(qb + bk) * ARS + bn4]) = b2P;
            *reinterpret_cast<float4*>(&B3s[(qb + bk) * ARS + bn4]) = b3P;
            __syncthreads();
            p ^= 1;
        }
    }
    #pragma unroll
    for (int im = 0; im < 4; im++) {
        int i = m0 + (ty << 2) + im;
        if (i >= L) continue;
        int row = a * L + i;
        size_t ob = (size_t)row * STRH + n0 + (tx << 2);
        float2 p1a = unpack2(ac1[im][0]), p1b = unpack2(ac1[im][1]);
        float2 p2a = unpack2(ac2[im][0]), p2b = unpack2(ac2[im][1]);
        float4 numv = make_float4(p1a.x + p2a.x, p1a.y + p2a.y,
                                  p1b.x + p2b.x, p1b.y + p2b.y);
        *reinterpret_cast<float4*>(&g_Sn[q][ob]) = numv;
        float2 p3a = unpack2(ac3[im][0]), p3b = unpack2(ac3[im][1]);
        float4 denv = make_float4(p3a.x, p3a.y, p3b.x, p3b.y);
        *reinterpret_cast<float4*>(&g_Sd[q][ob]) = denv;
    }
}

// ============ Kernel E: combine slices + divide + Y + inverse FFT ============
__global__ void k_E(float* __restrict__ out) {
    __shared__ __align__(16) float S[4400];
    float2* fa = (float2*)S;
    float2* fb = fa + 768;
    float2* tw = fa + 1536;
    int blk = blockIdx.x, a = blk / L, i = blk % L;
    int tid = threadIdx.x;
    build_tw(tw, tid);
    size_t bh = (size_t)blk * STRH;
    bool fast = (g_nzero == 0);
    float rs = fmaxf(g_rsum[blk], 1e-7f);
    for (int c = tid; c <= 384; c += 256) {
        float numv = 0.f;
        #pragma unroll
        for (int s = 0; s < SPK; s++) numv += g_Sn[s][bh + c];
        float den;
        if (fast) den = rs;
        else {
            float dd = 0.f;
            #pragma unroll
            for (int s = 0; s < SPK; s++) dd += g_Sd[s][bh + c];
            den = fmaxf(dd, 1e-7f);
        }
        float sv = numv / den;
        float xr = g_Xr[bh + c], xi = g_Xi[bh + c];
        float m2 = xr * xr + xi * xi;
        float yr, yi;
        if (m2 > 0.f) { float r = sv / sqrtf(m2); yr = xr * r; yi = xi * r; }
        else          { yr = sv; yi = 0.f; }
        fa[c] = make_float2(yr, yi);
    }
    __syncthreads();
    for (int c = 385 + tid; c < 768; c += 256) {
        float2 y = fa[768 - c];
        fa[c] = make_float2(y.x, -y.y);
    }
    __syncthreads();
    float2* res = fft768r4(fa, fb, tw, tid, 1.0f);
    float* op = out + ((size_t)(a * 197 + 1 + i)) * D;
    if (tid < 192) {
        int d = tid << 2;
        float4 o = make_float4(res[d].x     * (1.f / 768.f),
                               res[d + 1].x * (1.f / 768.f),
                               res[d + 2].x * (1.f / 768.f),
                               res[d + 3].x * (1.f / 768.f));
        *reinterpret_cast<float4*>(op + d) = o;
    }
}

// ---------------- launch ------------------------------------------------------
extern "C" void kernel_launch(void* const* d_in, const int* in_sizes, int n_in,
                              void* d_out, int out_size) {
    const float* x     = (const float*)d_in[0];
    const float* imgs  = (const float*)d_in[1];
    const float* ls    = (const float*)d_in[2];
    const float* noise = (const float*)d_in[3];
    float* out = (float*)d_out;

    k_A1<<<A1_GRID, 256>>>(imgs, x, out, ls);
    k_A2<<<NLTOT + 56, 256>>>(x);
    k_C<<<NLTOT, 256>>>();
    k_Df<<<dim3(7, 4, NB * SPK), 256>>>(ls, noise);
    k_Ds<<<dim3(7, 4, NB * SPK), 256>>>(ls, noise);
    k_E<<<NLTOT, 256>>>(out);
}